// round 1
// baseline (speedup 1.0000x reference)
#include <cuda_runtime.h>
#include <math.h>

#define BB 32
#define KK 8192
#define DC 256
#define DQ 256
#define HID 256
#define SK 50
#define IB 512
#define EH 512

// ---- output layout (f32, tuple concatenated) ----
// z[32,50,512], selection[32,50,8192], kl_loss[1], hard[32,50,8192],
// selected_score[32,50], selected_raw_score[32,50]
#define OFF_Z    0ull
#define OFF_SEL  819200ull
#define OFF_KL   13926400ull
#define OFF_HARD 13926401ull
#define OFF_SSC  27033601ull
#define OFF_SRS  27035201ull

// ---- scratch (no allocations allowed) ----
__device__ float g_logits[BB * KK];
__device__ float g_sel[BB * KK];
__device__ float g_qW1[BB * HID];
__device__ float g_qWe1[BB * EH];
__device__ int   g_topk[BB * SK];
__device__ float g_klrows[BB * SK];

// ===================== zero output =====================
__global__ void zero_kernel(float* __restrict__ out, size_t n) {
    size_t n4 = n >> 2;
    float4* o4 = reinterpret_cast<float4*>(out);
    size_t i = (size_t)blockIdx.x * blockDim.x + threadIdx.x;
    size_t stride = (size_t)gridDim.x * blockDim.x;
    float4 z = make_float4(0.f, 0.f, 0.f, 0.f);
    for (; i < n4; i += stride) o4[i] = z;
    if (blockIdx.x == 0 && threadIdx.x == 0) {
        for (size_t t = n4 << 2; t < n; t++) out[t] = 0.f;
    }
}

// ===================== query projections =====================
// g_qW1[b,j]  = sum_d q[b,d] * W1[256+d, j]   (j<256)
// g_qWe1[b,j] = sum_d q[b,d] * We1[256+d, j]  (j<512)
__global__ void qproj_kernel(const float* __restrict__ q,
                             const float* __restrict__ W1,
                             const float* __restrict__ We1) {
    int b = blockIdx.x, tid = threadIdx.x;
    __shared__ float qs[DQ];
    if (tid < DQ) qs[tid] = q[b * DQ + tid];
    __syncthreads();
    if (tid < HID) {
        float s = 0.f;
        #pragma unroll 8
        for (int d = 0; d < DQ; d++) s += qs[d] * W1[(size_t)(DC + d) * HID + tid];
        g_qW1[b * HID + tid] = s;
    }
    {
        float s = 0.f;
        #pragma unroll 8
        for (int d = 0; d < DQ; d++) s += qs[d] * We1[(size_t)(DC + d) * EH + tid];
        g_qWe1[b * EH + tid] = s;
    }
}

// ===================== scorer logits =====================
// logits[b,k] = relu(cand[b,k,:]@W1a + qW1[b,:] + b1) @ W2 + b2
// tile: 64 candidates x 256 hidden per block; thread owns hidden col = tid
__global__ void __launch_bounds__(256, 2)
logits_kernel(const float* __restrict__ cand,
              const float* __restrict__ W1,
              const float* __restrict__ b1,
              const float* __restrict__ W2,
              const float* __restrict__ b2,
              const float* __restrict__ gum) {
    const int tid = threadIdx.x;
    const int b = blockIdx.y;
    const int k0 = blockIdx.x * 64;

    __shared__ float candT[32][68];   // [d][k], stride 68 floats (16B-aligned rows)
    __shared__ float w1s[32][256];    // [d][j]
    __shared__ float part[64][8];

    float acc[64];
    #pragma unroll
    for (int k = 0; k < 64; k++) acc[k] = 0.f;

    for (int d0 = 0; d0 < DC; d0 += 32) {
        // load 64x32 cand tile (transposed into smem)
        #pragma unroll
        for (int r = 0; r < 8; r++) {
            int i = tid + r * 256;
            int k = i >> 5, d = i & 31;
            candT[d][k] = cand[((size_t)b * KK + k0 + k) * DC + d0 + d];
        }
        // load 32x256 W1 tile
        #pragma unroll
        for (int r = 0; r < 32; r++) {
            int i = tid + r * 256;
            int d = i >> 8, c = i & 255;
            w1s[d][c] = W1[(size_t)(d0 + d) * HID + c];
        }
        __syncthreads();
        #pragma unroll
        for (int d = 0; d < 32; d++) {
            float w = w1s[d][tid];
            const float4* cp = reinterpret_cast<const float4*>(&candT[d][0]);
            #pragma unroll
            for (int k4 = 0; k4 < 16; k4++) {
                float4 c = cp[k4];
                acc[k4 * 4 + 0] += c.x * w;
                acc[k4 * 4 + 1] += c.y * w;
                acc[k4 * 4 + 2] += c.z * w;
                acc[k4 * 4 + 3] += c.w * w;
            }
        }
        __syncthreads();
    }

    // epilogue: relu + dot with W2, reduce over 256 threads per k
    const float qb = g_qW1[b * HID + tid] + b1[tid];
    const float w2 = W2[tid];
    const int lane = tid & 31, wid = tid >> 5;
    #pragma unroll 4
    for (int k = 0; k < 64; k++) {
        float h = acc[k] + qb;
        h = h > 0.f ? h : 0.f;
        float p = h * w2;
        #pragma unroll
        for (int off = 16; off; off >>= 1) p += __shfl_down_sync(0xffffffffu, p, off);
        if (lane == 0) part[k][wid] = p;
    }
    __syncthreads();
    if (tid < 64) {
        float s = 0.f;
        #pragma unroll
        for (int w = 0; w < 8; w++) s += part[tid][w];
        s += b2[0];
        int gk = k0 + tid;
        size_t idx = (size_t)b * KK + gk;
        g_logits[idx] = s;
        g_sel[idx] = s + gum[idx];
    }
}

// ===================== top-k (sequential argmax, 50 rounds) =====================
__global__ void topk_kernel(const float* __restrict__ cand_score,
                            float* __restrict__ out) {
    const int b = blockIdx.x;
    const int tid = threadIdx.x;             // 1024 threads
    __shared__ float vals[KK];
    __shared__ float rv[1024];
    __shared__ int   ri[1024];

    for (int i = tid; i < KK; i += 1024) vals[i] = g_sel[(size_t)b * KK + i];
    __syncthreads();

    for (int s = 0; s < SK; s++) {
        float bv = -INFINITY; int bi = KK;
        for (int i = tid; i < KK; i += 1024) {
            float v = vals[i];
            if (v > bv) { bv = v; bi = i; }   // increasing i -> keeps lowest index on tie
        }
        rv[tid] = bv; ri[tid] = bi;
        __syncthreads();
        for (int off = 512; off; off >>= 1) {
            if (tid < off) {
                float ov = rv[tid + off]; int oi = ri[tid + off];
                if (ov > rv[tid] || (ov == rv[tid] && oi < ri[tid])) { rv[tid] = ov; ri[tid] = oi; }
            }
            __syncthreads();
        }
        if (tid == 0) {
            int idx = ri[0];
            int row = b * SK + s;
            g_topk[row] = idx;
            out[OFF_SSC + row] = g_logits[(size_t)b * KK + idx];
            out[OFF_SRS + row] = cand_score[(size_t)b * KK + idx];
            out[OFF_SEL + (size_t)row * KK + idx] = 1.0f;
            out[OFF_HARD + (size_t)row * KK + idx] = 1.0f;
            vals[idx] = -INFINITY;
        }
        __syncthreads();
    }
}

// ===================== encoder / IB head =====================
// per block: one b, 10 selected rows. 512 threads (thread = hidden/output col)
#define RPB 10
__global__ void __launch_bounds__(512)
encoder_kernel(const float* __restrict__ cand,
               const float* __restrict__ We1,
               const float* __restrict__ be1,
               const float* __restrict__ We2,
               const float* __restrict__ be2,
               const float* __restrict__ eps,
               float* __restrict__ out) {
    const int tid = threadIdx.x;
    const int b = blockIdx.y;
    const int s0 = blockIdx.x * RPB;

    __shared__ float sel_s[RPB][DC];
    __shared__ float he_s[RPB][EH];
    __shared__ int   idxs[RPB];
    __shared__ float redp[16];

    if (tid < RPB) idxs[tid] = g_topk[b * SK + s0 + tid];
    __syncthreads();
    for (int e = tid; e < RPB * DC; e += 512) {
        int r = e >> 8, d = e & 255;
        sel_s[r][d] = cand[((size_t)b * KK + idxs[r]) * DC + d];
    }
    __syncthreads();

    // he = relu(sel @ We1a + qWe1 + be1)
    {
        float acc[RPB];
        #pragma unroll
        for (int r = 0; r < RPB; r++) acc[r] = 0.f;
        for (int d = 0; d < DC; d++) {
            float w = We1[(size_t)d * EH + tid];
            #pragma unroll
            for (int r = 0; r < RPB; r++) acc[r] += sel_s[r][d] * w;
        }
        float bias = g_qWe1[b * EH + tid] + be1[tid];
        #pragma unroll
        for (int r = 0; r < RPB; r++) {
            float h = acc[r] + bias;
            he_s[r][tid] = h > 0.f ? h : 0.f;
        }
    }
    __syncthreads();

    // params = he @ We2 + be2 ; thread computes mu_tid and log_sigma_tid
    float acc0[RPB], acc1[RPB];
    #pragma unroll
    for (int r = 0; r < RPB; r++) { acc0[r] = 0.f; acc1[r] = 0.f; }
    for (int h = 0; h < EH; h++) {
        float w0 = We2[(size_t)h * (2 * IB) + tid];
        float w1 = We2[(size_t)h * (2 * IB) + IB + tid];
        #pragma unroll
        for (int r = 0; r < RPB; r++) {
            float hv = he_s[r][h];
            acc0[r] += hv * w0;
            acc1[r] += hv * w1;
        }
    }
    const float bmu = be2[tid];
    const float bls = be2[IB + tid];
    const int lane = tid & 31, wid = tid >> 5;

    for (int r = 0; r < RPB; r++) {
        int row = b * SK + s0 + r;
        float mu = acc0[r] + bmu;
        float lsr = acc1[r] + bls;
        float lsc = fminf(fmaxf(lsr, -10.f), 10.f);
        float sd = expf(lsc);
        out[OFF_Z + (size_t)row * IB + tid] = mu + sd * eps[(size_t)row * IB + tid];
        float t = mu * mu + sd * sd - 1.0f - 2.0f * lsr;
        #pragma unroll
        for (int off = 16; off; off >>= 1) t += __shfl_down_sync(0xffffffffu, t, off);
        if (lane == 0) redp[wid] = t;
        __syncthreads();
        if (tid == 0) {
            float ssum = 0.f;
            #pragma unroll
            for (int w = 0; w < 16; w++) ssum += redp[w];
            g_klrows[row] = 0.5f * ssum;
        }
        __syncthreads();
    }
}

// ===================== kl finalize =====================
__global__ void klfinal_kernel(float* __restrict__ out) {
    const int tid = threadIdx.x;   // 256
    __shared__ float redp[8];
    float s = 0.f;
    for (int i = tid; i < BB * SK; i += 256) s += g_klrows[i];
    #pragma unroll
    for (int off = 16; off; off >>= 1) s += __shfl_down_sync(0xffffffffu, s, off);
    if ((tid & 31) == 0) redp[tid >> 5] = s;
    __syncthreads();
    if (tid == 0) {
        float t = 0.f;
        #pragma unroll
        for (int w = 0; w < 8; w++) t += redp[w];
        out[OFF_KL] = (t / (float)(BB * SK)) * 0.001f;
    }
}

// ===================== launch =====================
extern "C" void kernel_launch(void* const* d_in, const int* in_sizes, int n_in,
                              void* d_out, int out_size) {
    const float* query = (const float*)d_in[0];
    const float* cand  = (const float*)d_in[1];
    const float* score = (const float*)d_in[2];
    const float* gum   = (const float*)d_in[3];
    const float* eps   = (const float*)d_in[4];
    const float* W1    = (const float*)d_in[5];
    const float* b1    = (const float*)d_in[6];
    const float* W2    = (const float*)d_in[7];
    const float* b2    = (const float*)d_in[8];
    const float* We1   = (const float*)d_in[9];
    const float* be1   = (const float*)d_in[10];
    const float* We2   = (const float*)d_in[11];
    const float* be2   = (const float*)d_in[12];
    float* out = (float*)d_out;

    zero_kernel<<<4096, 256>>>(out, (size_t)out_size);
    qproj_kernel<<<BB, 512>>>(query, W1, We1);
    logits_kernel<<<dim3(KK / 64, BB), 256>>>(cand, W1, b1, W2, b2, gum);
    topk_kernel<<<BB, 1024>>>(score, out);
    encoder_kernel<<<dim3(SK / RPB, BB), 512>>>(cand, We1, be1, We2, be2, eps, out);
    klfinal_kernel<<<1, 256>>>(out);
}

// round 3
// speedup vs baseline: 1.6948x; 1.6948x over previous
#include <cuda_runtime.h>
#include <math.h>
#include <stdint.h>

#define BB 32
#define KK 8192
#define DC 256
#define DQ 256
#define HID 256
#define SK 50
#define IB 512
#define EH 512

// ---- output layout (f32, tuple concatenated) ----
#define OFF_Z    0ull
#define OFF_SEL  819200ull
#define OFF_KL   13926400ull
#define OFF_HARD 13926401ull
#define OFF_SSC  27033601ull
#define OFF_SRS  27035201ull

// ---- scratch ----
__device__ float g_logits[BB * KK];
__device__ float g_sel[BB * KK];
__device__ float g_qW1[BB * HID];
__device__ float g_qWe1[BB * EH];
__device__ int   g_topk[BB * SK];
__device__ float g_klrows[BB * SK];
__device__ __align__(16) float g_W1T_hi[HID * DC];  // [n][k] = W1[k][n] tf32-hi
__device__ __align__(16) float g_W1T_lo[HID * DC];  // tf32-lo residual

// ===================== helpers =====================
__device__ __forceinline__ float tf32_rna(float x) {
    uint32_t u;
    asm("cvt.rna.tf32.f32 %0, %1;" : "=r"(u) : "f"(x));
    return __uint_as_float(u);
}

__device__ __forceinline__ void mma8(float* c, const uint4& a, uint32_t b0, uint32_t b1) {
    asm volatile(
        "mma.sync.aligned.m16n8k8.row.col.f32.tf32.tf32.f32 "
        "{%0,%1,%2,%3},{%4,%5,%6,%7},{%8,%9},{%0,%1,%2,%3};"
        : "+f"(c[0]), "+f"(c[1]), "+f"(c[2]), "+f"(c[3])
        : "r"(a.x), "r"(a.y), "r"(a.z), "r"(a.w), "r"(b0), "r"(b1));
}

// ===================== zero output =====================
__global__ void zero_kernel(float* __restrict__ out, size_t n) {
    size_t n4 = n >> 2;
    float4* o4 = reinterpret_cast<float4*>(out);
    size_t i = (size_t)blockIdx.x * blockDim.x + threadIdx.x;
    size_t stride = (size_t)gridDim.x * blockDim.x;
    float4 z = make_float4(0.f, 0.f, 0.f, 0.f);
    for (; i < n4; i += stride) o4[i] = z;
    if (blockIdx.x == 0 && threadIdx.x == 0) {
        for (size_t t = n4 << 2; t < n; t++) out[t] = 0.f;
    }
}

// ===================== W1 transpose + tf32 split =====================
__global__ void w1t_kernel(const float* __restrict__ W1) {
    int idx = blockIdx.x * 256 + threadIdx.x;   // 65536 total
    int k = idx >> 8, n = idx & 255;
    float x = W1[(size_t)k * HID + n];
    float h = tf32_rna(x);
    float l = tf32_rna(x - h);
    g_W1T_hi[n * DC + k] = h;
    g_W1T_lo[n * DC + k] = l;
}

// ===================== query projections =====================
__global__ void qproj_kernel(const float* __restrict__ q,
                             const float* __restrict__ W1,
                             const float* __restrict__ We1) {
    int b = blockIdx.x, tid = threadIdx.x;
    __shared__ float qs[DQ];
    if (tid < DQ) qs[tid] = q[b * DQ + tid];
    __syncthreads();
    if (tid < HID) {
        float s = 0.f;
        #pragma unroll 8
        for (int d = 0; d < DQ; d++) s += qs[d] * W1[(size_t)(DC + d) * HID + tid];
        g_qW1[b * HID + tid] = s;
    }
    {
        float s = 0.f;
        #pragma unroll 8
        for (int d = 0; d < DQ; d++) s += qs[d] * We1[(size_t)(DC + d) * EH + tid];
        g_qWe1[b * EH + tid] = s;
    }
}

// ===================== scorer logits via mma.sync tf32 3-pass =====================
// CTA tile: M=128 cand x N=256 hidden, K=256 in 8 chunks of 32; double-buffered.
// Stage layout (floats): A_hi[4096] A_lo[4096] B_hi[256*36] B_lo[256*36]
#define SA_HI 0
#define SA_LO 4096
#define SB_HI 8192
#define SB_LO 17408
#define STAGE_F 26624
#define SM_DYN (2 * STAGE_F * 4)

struct Pref { float4 a[2]; float4 bh[4]; };

__device__ __forceinline__ void load_pref(Pref& p, const float* __restrict__ cand,
                                          int b, int k0, int d0, int tid) {
    #pragma unroll
    for (int t = 0; t < 2; t++) {
        int idx = tid + t * 512;
        int m = idx >> 3, k4 = idx & 7;
        p.a[t] = *reinterpret_cast<const float4*>(
            &cand[((size_t)b * KK + k0 + m) * DC + d0 + k4 * 4]);
    }
    #pragma unroll
    for (int t = 0; t < 4; t++) {
        int idx = tid + t * 512;
        int n = idx >> 3, k4 = idx & 7;
        p.bh[t] = *reinterpret_cast<const float4*>(&g_W1T_hi[n * DC + d0 + k4 * 4]);
    }
}

__device__ __forceinline__ void store_stage(float* __restrict__ st, const Pref& p,
                                            int d0, int tid) {
    #pragma unroll
    for (int t = 0; t < 2; t++) {
        int idx = tid + t * 512;
        int m = idx >> 3, k4 = idx & 7;
        float4 v = p.a[t];
        float4 h, l;
        h.x = tf32_rna(v.x); l.x = tf32_rna(v.x - h.x);
        h.y = tf32_rna(v.y); l.y = tf32_rna(v.y - h.y);
        h.z = tf32_rna(v.z); l.z = tf32_rna(v.z - h.z);
        h.w = tf32_rna(v.w); l.w = tf32_rna(v.w - h.w);
        int r = ((m >> 3) & 1) + 2 * (k4 & 1);
        int base = ((m >> 4) * 4 + (k4 >> 1)) * 128 + (m & 7) * 16 + r;
        st[SA_HI + base + 0]  = h.x; st[SA_HI + base + 4]  = h.y;
        st[SA_HI + base + 8]  = h.z; st[SA_HI + base + 12] = h.w;
        st[SA_LO + base + 0]  = l.x; st[SA_LO + base + 4]  = l.y;
        st[SA_LO + base + 8]  = l.z; st[SA_LO + base + 12] = l.w;
    }
    #pragma unroll
    for (int t = 0; t < 4; t++) {
        int idx = tid + t * 512;
        int n = idx >> 3, k4 = idx & 7;
        *reinterpret_cast<float4*>(&st[SB_HI + n * 36 + k4 * 4]) = p.bh[t];
        float4 vl = *reinterpret_cast<const float4*>(&g_W1T_lo[n * DC + d0 + k4 * 4]);
        *reinterpret_cast<float4*>(&st[SB_LO + n * 36 + k4 * 4]) = vl;
    }
}

__device__ __forceinline__ void compute_stage(const float* __restrict__ st,
                                              float acc[2][8][4],
                                              int wm, int wn, int lane) {
    #pragma unroll
    for (int tk = 0; tk < 4; tk++) {
        uint4 ah[2], al[2];
        #pragma unroll
        for (int mt = 0; mt < 2; mt++) {
            int off = ((wm * 2 + mt) * 4 + tk) * 128 + lane * 4;
            ah[mt] = *reinterpret_cast<const uint4*>(&st[SA_HI + off]);
            al[mt] = *reinterpret_cast<const uint4*>(&st[SA_LO + off]);
        }
        #pragma unroll
        for (int nt = 0; nt < 8; nt++) {
            int nrow = (wn * 8 + nt) * 8 + (lane >> 2);
            int kc = tk * 8 + (lane & 3);
            uint32_t bh0 = __float_as_uint(st[SB_HI + nrow * 36 + kc]);
            uint32_t bh1 = __float_as_uint(st[SB_HI + nrow * 36 + kc + 4]);
            uint32_t bl0 = __float_as_uint(st[SB_LO + nrow * 36 + kc]);
            uint32_t bl1 = __float_as_uint(st[SB_LO + nrow * 36 + kc + 4]);
            #pragma unroll
            for (int mt = 0; mt < 2; mt++) {
                mma8(acc[mt][nt], ah[mt], bh0, bh1);
                mma8(acc[mt][nt], al[mt], bh0, bh1);
                mma8(acc[mt][nt], ah[mt], bl0, bl1);
            }
        }
    }
}

__global__ void __launch_bounds__(512, 1)
logits_mma_kernel(const float* __restrict__ cand,
                  const float* __restrict__ b1,
                  const float* __restrict__ W2,
                  const float* __restrict__ b2,
                  const float* __restrict__ gum) {
    extern __shared__ float dsm[];
    __shared__ float qb_s[HID];
    __shared__ float w2_s[HID];
    __shared__ float part[128][4];

    const int tid = threadIdx.x;
    const int b = blockIdx.y;
    const int k0 = blockIdx.x * 128;
    const int w = tid >> 5, lane = tid & 31;
    const int wm = w & 3, wn = w >> 2;

    if (tid < HID) {
        qb_s[tid] = g_qW1[b * HID + tid] + b1[tid];
        w2_s[tid] = W2[tid];
    }

    float acc[2][8][4];
    #pragma unroll
    for (int mt = 0; mt < 2; mt++)
        #pragma unroll
        for (int nt = 0; nt < 8; nt++)
            #pragma unroll
            for (int r = 0; r < 4; r++) acc[mt][nt][r] = 0.f;

    Pref p;
    load_pref(p, cand, b, k0, 0, tid);
    store_stage(dsm, p, 0, tid);
    __syncthreads();

    for (int c = 0; c < 8; c++) {
        if (c < 7) load_pref(p, cand, b, k0, (c + 1) * 32, tid);
        compute_stage(dsm + (c & 1) * STAGE_F, acc, wm, wn, lane);
        if (c < 7) store_stage(dsm + ((c + 1) & 1) * STAGE_F, p, (c + 1) * 32, tid);
        __syncthreads();
    }

    // epilogue: relu(D + qb) * w2, reduce over n
    float rs[2][2] = {{0.f, 0.f}, {0.f, 0.f}};
    #pragma unroll
    for (int mt = 0; mt < 2; mt++)
        #pragma unroll
        for (int nt = 0; nt < 8; nt++)
            #pragma unroll
            for (int ci = 0; ci < 4; ci++) {
                int col = wn * 64 + nt * 8 + (lane & 3) * 2 + (ci & 1);
                float v = acc[mt][nt][ci] + qb_s[col];
                rs[mt][ci >> 1] += fmaxf(v, 0.f) * w2_s[col];
            }
    #pragma unroll
    for (int mt = 0; mt < 2; mt++)
        #pragma unroll
        for (int rh = 0; rh < 2; rh++) {
            float s = rs[mt][rh];
            s += __shfl_xor_sync(0xffffffffu, s, 1);
            s += __shfl_xor_sync(0xffffffffu, s, 2);
            if ((lane & 3) == 0)
                part[wm * 32 + mt * 16 + rh * 8 + (lane >> 2)][wn] = s;
        }
    __syncthreads();
    if (tid < 128) {
        float lg = part[tid][0] + part[tid][1] + part[tid][2] + part[tid][3] + b2[0];
        size_t gi = (size_t)b * KK + k0 + tid;
        g_logits[gi] = lg;
        g_sel[gi] = lg + gum[gi];
    }
}

// ===================== top-k (register-resident argmax, 50 rounds) =====================
__global__ void __launch_bounds__(1024)
topk_kernel(const float* __restrict__ cand_score, float* __restrict__ out) {
    const int b = blockIdx.x;
    const int tid = threadIdx.x;
    const int lane = tid & 31, w = tid >> 5;
    const int base = tid * 8;
    float v[8];
    #pragma unroll
    for (int r = 0; r < 8; r++) v[r] = g_sel[(size_t)b * KK + base + r];

    __shared__ float wv[32];
    __shared__ int   wi[32];
    __shared__ int   bcast;

    for (int s = 0; s < SK; s++) {
        float bv = v[0]; int bi = base;
        #pragma unroll
        for (int r = 1; r < 8; r++) if (v[r] > bv) { bv = v[r]; bi = base + r; }
        #pragma unroll
        for (int off = 16; off; off >>= 1) {
            float ov = __shfl_down_sync(0xffffffffu, bv, off);
            int   oi = __shfl_down_sync(0xffffffffu, bi, off);
            if (ov > bv || (ov == bv && oi < bi)) { bv = ov; bi = oi; }
        }
        if (lane == 0) { wv[w] = bv; wi[w] = bi; }
        __syncthreads();
        if (w == 0) {
            float rv = wv[lane]; int ri = wi[lane];
            #pragma unroll
            for (int off = 16; off; off >>= 1) {
                float ov = __shfl_down_sync(0xffffffffu, rv, off);
                int   oi = __shfl_down_sync(0xffffffffu, ri, off);
                if (ov > rv || (ov == rv && oi < ri)) { rv = ov; ri = oi; }
            }
            if (lane == 0) {
                int idx = ri;
                bcast = idx;
                int row = b * SK + s;
                g_topk[row] = idx;
                out[OFF_SSC + row] = g_logits[(size_t)b * KK + idx];
                out[OFF_SRS + row] = cand_score[(size_t)b * KK + idx];
                out[OFF_SEL + (size_t)row * KK + idx] = 1.0f;
                out[OFF_HARD + (size_t)row * KK + idx] = 1.0f;
            }
        }
        __syncthreads();
        int ib = bcast;
        if ((ib >> 3) == tid) v[ib & 7] = -INFINITY;
    }
}

// ===================== encoder / IB head =====================
#define RPB 10
__global__ void __launch_bounds__(512)
encoder_kernel(const float* __restrict__ cand,
               const float* __restrict__ We1,
               const float* __restrict__ be1,
               const float* __restrict__ We2,
               const float* __restrict__ be2,
               const float* __restrict__ eps,
               float* __restrict__ out) {
    const int tid = threadIdx.x;
    const int b = blockIdx.y;
    const int s0 = blockIdx.x * RPB;

    __shared__ float sel_s[RPB][DC];
    __shared__ float he_s[RPB][EH];
    __shared__ int   idxs[RPB];
    __shared__ float redp[16];

    if (tid < RPB) idxs[tid] = g_topk[b * SK + s0 + tid];
    __syncthreads();
    for (int e = tid; e < RPB * DC; e += 512) {
        int r = e >> 8, d = e & 255;
        sel_s[r][d] = cand[((size_t)b * KK + idxs[r]) * DC + d];
    }
    __syncthreads();

    {
        float acc[RPB];
        #pragma unroll
        for (int r = 0; r < RPB; r++) acc[r] = 0.f;
        for (int d = 0; d < DC; d++) {
            float wv = We1[(size_t)d * EH + tid];
            #pragma unroll
            for (int r = 0; r < RPB; r++) acc[r] += sel_s[r][d] * wv;
        }
        float bias = g_qWe1[b * EH + tid] + be1[tid];
        #pragma unroll
        for (int r = 0; r < RPB; r++) {
            float h = acc[r] + bias;
            he_s[r][tid] = h > 0.f ? h : 0.f;
        }
    }
    __syncthreads();

    float acc0[RPB], acc1[RPB];
    #pragma unroll
    for (int r = 0; r < RPB; r++) { acc0[r] = 0.f; acc1[r] = 0.f; }
    for (int h = 0; h < EH; h++) {
        float w0 = We2[(size_t)h * (2 * IB) + tid];
        float w1 = We2[(size_t)h * (2 * IB) + IB + tid];
        #pragma unroll
        for (int r = 0; r < RPB; r++) {
            float hv = he_s[r][h];
            acc0[r] += hv * w0;
            acc1[r] += hv * w1;
        }
    }
    const float bmu = be2[tid];
    const float bls = be2[IB + tid];
    const int lane = tid & 31, wid = tid >> 5;

    for (int r = 0; r < RPB; r++) {
        int row = b * SK + s0 + r;
        float mu = acc0[r] + bmu;
        float lsr = acc1[r] + bls;
        float lsc = fminf(fmaxf(lsr, -10.f), 10.f);
        float sd = expf(lsc);
        out[OFF_Z + (size_t)row * IB + tid] = mu + sd * eps[(size_t)row * IB + tid];
        float t = mu * mu + sd * sd - 1.0f - 2.0f * lsr;
        #pragma unroll
        for (int off = 16; off; off >>= 1) t += __shfl_down_sync(0xffffffffu, t, off);
        if (lane == 0) redp[wid] = t;
        __syncthreads();
        if (tid == 0) {
            float ssum = 0.f;
            #pragma unroll
            for (int ww = 0; ww < 16; ww++) ssum += redp[ww];
            g_klrows[row] = 0.5f * ssum;
        }
        __syncthreads();
    }
}

// ===================== kl finalize =====================
__global__ void klfinal_kernel(float* __restrict__ out) {
    const int tid = threadIdx.x;
    __shared__ float redp[8];
    float s = 0.f;
    for (int i = tid; i < BB * SK; i += 256) s += g_klrows[i];
    #pragma unroll
    for (int off = 16; off; off >>= 1) s += __shfl_down_sync(0xffffffffu, s, off);
    if ((tid & 31) == 0) redp[tid >> 5] = s;
    __syncthreads();
    if (tid == 0) {
        float t = 0.f;
        #pragma unroll
        for (int w = 0; w < 8; w++) t += redp[w];
        out[OFF_KL] = (t / (float)(BB * SK)) * 0.001f;
    }
}

// ===================== launch =====================
extern "C" void kernel_launch(void* const* d_in, const int* in_sizes, int n_in,
                              void* d_out, int out_size) {
    const float* query = (const float*)d_in[0];
    const float* cand  = (const float*)d_in[1];
    const float* score = (const float*)d_in[2];
    const float* gum   = (const float*)d_in[3];
    const float* eps   = (const float*)d_in[4];
    const float* W1    = (const float*)d_in[5];
    const float* b1    = (const float*)d_in[6];
    const float* W2    = (const float*)d_in[7];
    const float* b2    = (const float*)d_in[8];
    const float* We1   = (const float*)d_in[9];
    const float* be1   = (const float*)d_in[10];
    const float* We2   = (const float*)d_in[11];
    const float* be2   = (const float*)d_in[12];
    float* out = (float*)d_out;

    static int smem_set = 0;
    if (!smem_set) {
        cudaFuncSetAttribute(logits_mma_kernel,
                             cudaFuncAttributeMaxDynamicSharedMemorySize, SM_DYN);
        smem_set = 1;
    }

    zero_kernel<<<4096, 256>>>(out, (size_t)out_size);
    w1t_kernel<<<256, 256>>>(W1);
    qproj_kernel<<<BB, 512>>>(query, W1, We1);
    logits_mma_kernel<<<dim3(KK / 128, BB), 512, SM_DYN>>>(cand, b1, W2, b2, gum);
    topk_kernel<<<BB, 1024>>>(score, out);
    encoder_kernel<<<dim3(SK / RPB, BB), 512>>>(cand, We1, be1, We2, be2, eps, out);
    klfinal_kernel<<<1, 256>>>(out);
}

// round 4
// speedup vs baseline: 2.8393x; 1.6754x over previous
#include <cuda_runtime.h>
#include <cuda_bf16.h>
#include <math.h>
#include <stdint.h>

#define BB 32
#define KK 8192
#define DC 256
#define DQ 256
#define HID 256
#define SK 50
#define IB 512
#define EH 512

// ---- output layout (f32, tuple concatenated) ----
#define OFF_Z    0ull
#define OFF_SEL  819200ull
#define OFF_KL   13926400ull
#define OFF_HARD 13926401ull
#define OFF_SSC  27033601ull
#define OFF_SRS  27035201ull

// ---- scratch ----
__device__ float g_logits[BB * KK];
__device__ float g_sel[BB * KK];
__device__ float g_qW1[BB * HID];
__device__ float g_qWe1[BB * EH];
__device__ int   g_topk[BB * SK];
__device__ float g_klrows[BB * SK];
// W1^T hi/lo bf16 in fragment-permuted layout: 8 chunks x 1024 uint4 (16KB each)
__device__ __align__(16) uint4 g_BpH[8 * 1024];
__device__ __align__(16) uint4 g_BpL[8 * 1024];

// ===================== helpers =====================
__device__ __forceinline__ uint32_t bf16x2(float lo, float hi) {
    __nv_bfloat162 v = __floats2bfloat162_rn(lo, hi);
    return *reinterpret_cast<uint32_t*>(&v);
}
__device__ __forceinline__ void mma16(float* c, const uint4& a, uint32_t b0, uint32_t b1) {
    asm volatile(
        "mma.sync.aligned.m16n8k16.row.col.f32.bf16.bf16.f32 "
        "{%0,%1,%2,%3},{%4,%5,%6,%7},{%8,%9},{%0,%1,%2,%3};"
        : "+f"(c[0]), "+f"(c[1]), "+f"(c[2]), "+f"(c[3])
        : "r"(a.x), "r"(a.y), "r"(a.z), "r"(a.w), "r"(b0), "r"(b1));
}

// ===================== zero output =====================
__global__ void zero_kernel(float* __restrict__ out, size_t n) {
    size_t n4 = n >> 2;
    float4* o4 = reinterpret_cast<float4*>(out);
    size_t i = (size_t)blockIdx.x * blockDim.x + threadIdx.x;
    size_t stride = (size_t)gridDim.x * blockDim.x;
    float4 z = make_float4(0.f, 0.f, 0.f, 0.f);
    for (; i < n4; i += stride) o4[i] = z;
    if (blockIdx.x == 0 && threadIdx.x == 0) {
        for (size_t t = n4 << 2; t < n; t++) out[t] = 0.f;
    }
}

// ===================== W1 -> permuted bf16 hi/lo fragments =====================
// Fragment layout per k-chunk c (32 k's): [ntile(32)][ktile(2)][lane(32)] uint2:
//   pos0:(n=ntile*8+lane/4, k=ktile*16+(lane%4)*2) pos1:k+1 pos2:k+8 pos3:k+9
__global__ void w1t_kernel(const float* __restrict__ W1) {
    int idx = blockIdx.x * 256 + threadIdx.x;   // 65536
    int k = idx >> 8, n = idx & 255;
    float x = W1[(size_t)k * HID + n];
    __nv_bfloat16 h = __float2bfloat16(x);
    __nv_bfloat16 l = __float2bfloat16(x - __bfloat162float(h));
    int c = k >> 5, kp = k & 31;
    int ntile = n >> 3, g = n & 7;
    int ktile = kp >> 4;
    int lane = g * 4 + ((kp & 7) >> 1);
    int pos = (kp & 1) + 2 * ((kp & 15) >> 3);
    size_t off = (size_t)c * 8192 + (size_t)(((ntile * 2 + ktile) * 32 + lane) * 4 + pos);
    reinterpret_cast<__nv_bfloat16*>(g_BpH)[off] = h;
    reinterpret_cast<__nv_bfloat16*>(g_BpL)[off] = l;
}

// ===================== query projections =====================
__global__ void qproj_kernel(const float* __restrict__ q,
                             const float* __restrict__ W1,
                             const float* __restrict__ We1) {
    int b = blockIdx.x, tid = threadIdx.x;
    __shared__ float qs[DQ];
    if (tid < DQ) qs[tid] = q[b * DQ + tid];
    __syncthreads();
    if (tid < HID) {
        float s = 0.f;
        #pragma unroll 8
        for (int d = 0; d < DQ; d++) s += qs[d] * W1[(size_t)(DC + d) * HID + tid];
        g_qW1[b * HID + tid] = s;
    }
    {
        float s = 0.f;
        #pragma unroll 8
        for (int d = 0; d < DQ; d++) s += qs[d] * We1[(size_t)(DC + d) * EH + tid];
        g_qWe1[b * EH + tid] = s;
    }
}

// ===================== scorer logits via mma.sync bf16 3-pass =====================
// CTA tile: M=128 x N=256, K=256 in 8 chunks of 32; double-buffered smem.
// Stage (bytes): A_hi[8192] A_lo[8192] B_hi[16384] B_lo[16384] = 48KB
#define SAH 0
#define SAL 8192
#define SBH 16384
#define SBL 32768
#define STAGE_B 49152
#define SM_DYN (2 * STAGE_B)

struct Pref { float4 a[2]; uint4 bh[2]; uint4 bl[2]; };

__device__ __forceinline__ void load_pref(Pref& p, const float* __restrict__ cand,
                                          int b, int k0, int c, int tid) {
    #pragma unroll
    for (int t = 0; t < 2; t++) {
        int idx = tid + t * 512;
        int m = idx >> 3, k4 = idx & 7;
        p.a[t] = *reinterpret_cast<const float4*>(
            &cand[((size_t)b * KK + k0 + m) * DC + c * 32 + k4 * 4]);
        p.bh[t] = g_BpH[c * 1024 + idx];
        p.bl[t] = g_BpL[c * 1024 + idx];
    }
}

__device__ __forceinline__ void store_stage(char* __restrict__ st, const Pref& p, int tid) {
    #pragma unroll
    for (int t = 0; t < 2; t++) {
        int idx = tid + t * 512;
        int m = idx >> 3, k4 = idx & 7;
        float4 v = p.a[t];
        float hx = __bfloat162float(__float2bfloat16(v.x));
        float hy = __bfloat162float(__float2bfloat16(v.y));
        float hz = __bfloat162float(__float2bfloat16(v.z));
        float hw = __bfloat162float(__float2bfloat16(v.w));
        uint32_t h01 = bf16x2(v.x, v.y), h23 = bf16x2(v.z, v.w);
        uint32_t l01 = bf16x2(v.x - hx, v.y - hy), l23 = bf16x2(v.z - hz, v.w - hw);
        int mtile = m >> 4, r = m & 15;
        int ktile = k4 >> 2;
        int lane0 = (r & 7) * 4 + (k4 & 1) * 2;
        int boff = 2 * ((r >> 3) & 1) + 4 * ((k4 >> 1) & 1);   // bf16 units
        int base = ((mtile * 2 + ktile) * 32) * 16 + boff * 2; // bytes
        *reinterpret_cast<uint32_t*>(st + SAH + base + lane0 * 16)       = h01;
        *reinterpret_cast<uint32_t*>(st + SAH + base + (lane0 + 1) * 16) = h23;
        *reinterpret_cast<uint32_t*>(st + SAL + base + lane0 * 16)       = l01;
        *reinterpret_cast<uint32_t*>(st + SAL + base + (lane0 + 1) * 16) = l23;
        reinterpret_cast<uint4*>(st + SBH)[idx] = p.bh[t];
        reinterpret_cast<uint4*>(st + SBL)[idx] = p.bl[t];
    }
}

__device__ __forceinline__ void compute_stage(const char* __restrict__ st,
                                              float acc[2][8][4],
                                              int wm, int wn, int lane) {
    #pragma unroll
    for (int kt = 0; kt < 2; kt++) {
        uint4 ah[2], al[2];
        #pragma unroll
        for (int mt = 0; mt < 2; mt++) {
            int off = (((wm * 2 + mt) * 2 + kt) * 32 + lane) * 16;
            ah[mt] = *reinterpret_cast<const uint4*>(st + SAH + off);
            al[mt] = *reinterpret_cast<const uint4*>(st + SAL + off);
        }
        #pragma unroll
        for (int nt = 0; nt < 8; nt++) {
            int ntile = wn * 8 + nt;
            int boff = ((ntile * 2 + kt) * 32 + lane) * 8;
            uint2 bh = *reinterpret_cast<const uint2*>(st + SBH + boff);
            uint2 bl = *reinterpret_cast<const uint2*>(st + SBL + boff);
            #pragma unroll
            for (int mt = 0; mt < 2; mt++) {
                mma16(acc[mt][nt], ah[mt], bh.x, bh.y);
                mma16(acc[mt][nt], al[mt], bh.x, bh.y);
                mma16(acc[mt][nt], ah[mt], bl.x, bl.y);
            }
        }
    }
}

__global__ void __launch_bounds__(512, 1)
logits_mma_kernel(const float* __restrict__ cand,
                  const float* __restrict__ b1,
                  const float* __restrict__ W2,
                  const float* __restrict__ b2,
                  const float* __restrict__ gum) {
    extern __shared__ char dsm[];
    __shared__ float qb_s[HID];
    __shared__ float w2_s[HID];
    __shared__ float part[128][4];

    const int tid = threadIdx.x;
    const int b = blockIdx.y;
    const int k0 = blockIdx.x * 128;
    const int w = tid >> 5, lane = tid & 31;
    const int wm = w & 3, wn = w >> 2;

    if (tid < HID) {
        qb_s[tid] = g_qW1[b * HID + tid] + b1[tid];
        w2_s[tid] = W2[tid];
    }

    float acc[2][8][4];
    #pragma unroll
    for (int mt = 0; mt < 2; mt++)
        #pragma unroll
        for (int nt = 0; nt < 8; nt++)
            #pragma unroll
            for (int r = 0; r < 4; r++) acc[mt][nt][r] = 0.f;

    Pref p;
    load_pref(p, cand, b, k0, 0, tid);
    store_stage(dsm, p, tid);
    __syncthreads();

    for (int c = 0; c < 8; c++) {
        if (c < 7) load_pref(p, cand, b, k0, c + 1, tid);
        compute_stage(dsm + (c & 1) * STAGE_B, acc, wm, wn, lane);
        if (c < 7) store_stage(dsm + ((c + 1) & 1) * STAGE_B, p, tid);
        __syncthreads();
    }

    // epilogue: relu(D + qb) * w2, reduce over n
    float rs[2][2] = {{0.f, 0.f}, {0.f, 0.f}};
    #pragma unroll
    for (int mt = 0; mt < 2; mt++)
        #pragma unroll
        for (int nt = 0; nt < 8; nt++)
            #pragma unroll
            for (int ci = 0; ci < 4; ci++) {
                int col = wn * 64 + nt * 8 + (lane & 3) * 2 + (ci & 1);
                float v = acc[mt][nt][ci] + qb_s[col];
                rs[mt][ci >> 1] += fmaxf(v, 0.f) * w2_s[col];
            }
    #pragma unroll
    for (int mt = 0; mt < 2; mt++)
        #pragma unroll
        for (int rh = 0; rh < 2; rh++) {
            float s = rs[mt][rh];
            s += __shfl_xor_sync(0xffffffffu, s, 1);
            s += __shfl_xor_sync(0xffffffffu, s, 2);
            if ((lane & 3) == 0)
                part[wm * 32 + mt * 16 + rh * 8 + (lane >> 2)][wn] = s;
        }
    __syncthreads();
    if (tid < 128) {
        float lg = part[tid][0] + part[tid][1] + part[tid][2] + part[tid][3] + b2[0];
        size_t gi = (size_t)b * KK + k0 + tid;
        g_logits[gi] = lg;
        g_sel[gi] = lg + gum[gi];
    }
}

// ===================== top-k (register-resident argmax, 50 rounds) =====================
__global__ void __launch_bounds__(1024)
topk_kernel(const float* __restrict__ cand_score, float* __restrict__ out) {
    const int b = blockIdx.x;
    const int tid = threadIdx.x;
    const int lane = tid & 31, w = tid >> 5;
    const int base = tid * 8;
    float v[8];
    #pragma unroll
    for (int r = 0; r < 8; r++) v[r] = g_sel[(size_t)b * KK + base + r];

    __shared__ float wv[32];
    __shared__ int   wi[32];
    __shared__ int   bcast;

    for (int s = 0; s < SK; s++) {
        float bv = v[0]; int bi = base;
        #pragma unroll
        for (int r = 1; r < 8; r++) if (v[r] > bv) { bv = v[r]; bi = base + r; }
        #pragma unroll
        for (int off = 16; off; off >>= 1) {
            float ov = __shfl_down_sync(0xffffffffu, bv, off);
            int   oi = __shfl_down_sync(0xffffffffu, bi, off);
            if (ov > bv || (ov == bv && oi < bi)) { bv = ov; bi = oi; }
        }
        if (lane == 0) { wv[w] = bv; wi[w] = bi; }
        __syncthreads();
        if (w == 0) {
            float rv = wv[lane]; int ri = wi[lane];
            #pragma unroll
            for (int off = 16; off; off >>= 1) {
                float ov = __shfl_down_sync(0xffffffffu, rv, off);
                int   oi = __shfl_down_sync(0xffffffffu, ri, off);
                if (ov > rv || (ov == rv && oi < ri)) { rv = ov; ri = oi; }
            }
            if (lane == 0) {
                int idx = ri;
                bcast = idx;
                int row = b * SK + s;
                g_topk[row] = idx;
                out[OFF_SSC + row] = g_logits[(size_t)b * KK + idx];
                out[OFF_SRS + row] = cand_score[(size_t)b * KK + idx];
                out[OFF_SEL + (size_t)row * KK + idx] = 1.0f;
                out[OFF_HARD + (size_t)row * KK + idx] = 1.0f;
            }
        }
        __syncthreads();
        int ib = bcast;
        if ((ib >> 3) == tid) v[ib & 7] = -INFINITY;
    }
}

// ===================== encoder / IB head =====================
#define RPB 10
__global__ void __launch_bounds__(512)
encoder_kernel(const float* __restrict__ cand,
               const float* __restrict__ We1,
               const float* __restrict__ be1,
               const float* __restrict__ We2,
               const float* __restrict__ be2,
               const float* __restrict__ eps,
               float* __restrict__ out) {
    const int tid = threadIdx.x;
    const int b = blockIdx.y;
    const int s0 = blockIdx.x * RPB;

    __shared__ float sel_s[RPB][DC];
    __shared__ float he_s[RPB][EH];
    __shared__ int   idxs[RPB];
    __shared__ float redp[16];

    if (tid < RPB) idxs[tid] = g_topk[b * SK + s0 + tid];
    __syncthreads();
    for (int e = tid; e < RPB * DC; e += 512) {
        int r = e >> 8, d = e & 255;
        sel_s[r][d] = cand[((size_t)b * KK + idxs[r]) * DC + d];
    }
    __syncthreads();

    {
        float acc[RPB];
        #pragma unroll
        for (int r = 0; r < RPB; r++) acc[r] = 0.f;
        for (int d = 0; d < DC; d++) {
            float wv = We1[(size_t)d * EH + tid];
            #pragma unroll
            for (int r = 0; r < RPB; r++) acc[r] += sel_s[r][d] * wv;
        }
        float bias = g_qWe1[b * EH + tid] + be1[tid];
        #pragma unroll
        for (int r = 0; r < RPB; r++) {
            float h = acc[r] + bias;
            he_s[r][tid] = h > 0.f ? h : 0.f;
        }
    }
    __syncthreads();

    float acc0[RPB], acc1[RPB];
    #pragma unroll
    for (int r = 0; r < RPB; r++) { acc0[r] = 0.f; acc1[r] = 0.f; }
    for (int h = 0; h < EH; h++) {
        float w0 = We2[(size_t)h * (2 * IB) + tid];
        float w1 = We2[(size_t)h * (2 * IB) + IB + tid];
        #pragma unroll
        for (int r = 0; r < RPB; r++) {
            float hv = he_s[r][h];
            acc0[r] += hv * w0;
            acc1[r] += hv * w1;
        }
    }
    const float bmu = be2[tid];
    const float bls = be2[IB + tid];
    const int lane = tid & 31, wid = tid >> 5;

    for (int r = 0; r < RPB; r++) {
        int row = b * SK + s0 + r;
        float mu = acc0[r] + bmu;
        float lsr = acc1[r] + bls;
        float lsc = fminf(fmaxf(lsr, -10.f), 10.f);
        float sd = expf(lsc);
        out[OFF_Z + (size_t)row * IB + tid] = mu + sd * eps[(size_t)row * IB + tid];
        float t = mu * mu + sd * sd - 1.0f - 2.0f * lsr;
        #pragma unroll
        for (int off = 16; off; off >>= 1) t += __shfl_down_sync(0xffffffffu, t, off);
        if (lane == 0) redp[wid] = t;
        __syncthreads();
        if (tid == 0) {
            float ssum = 0.f;
            #pragma unroll
            for (int ww = 0; ww < 16; ww++) ssum += redp[ww];
            g_klrows[row] = 0.5f * ssum;
        }
        __syncthreads();
    }
}

// ===================== kl finalize =====================
__global__ void klfinal_kernel(float* __restrict__ out) {
    const int tid = threadIdx.x;
    __shared__ float redp[8];
    float s = 0.f;
    for (int i = tid; i < BB * SK; i += 256) s += g_klrows[i];
    #pragma unroll
    for (int off = 16; off; off >>= 1) s += __shfl_down_sync(0xffffffffu, s, off);
    if ((tid & 31) == 0) redp[tid >> 5] = s;
    __syncthreads();
    if (tid == 0) {
        float t = 0.f;
        #pragma unroll
        for (int w = 0; w < 8; w++) t += redp[w];
        out[OFF_KL] = (t / (float)(BB * SK)) * 0.001f;
    }
}

// ===================== launch =====================
extern "C" void kernel_launch(void* const* d_in, const int* in_sizes, int n_in,
                              void* d_out, int out_size) {
    const float* query = (const float*)d_in[0];
    const float* cand  = (const float*)d_in[1];
    const float* score = (const float*)d_in[2];
    const float* gum   = (const float*)d_in[3];
    const float* eps   = (const float*)d_in[4];
    const float* W1    = (const float*)d_in[5];
    const float* b1    = (const float*)d_in[6];
    const float* W2    = (const float*)d_in[7];
    const float* b2    = (const float*)d_in[8];
    const float* We1   = (const float*)d_in[9];
    const float* be1   = (const float*)d_in[10];
    const float* We2   = (const float*)d_in[11];
    const float* be2   = (const float*)d_in[12];
    float* out = (float*)d_out;

    static int smem_set = 0;
    if (!smem_set) {
        cudaFuncSetAttribute(logits_mma_kernel,
                             cudaFuncAttributeMaxDynamicSharedMemorySize, SM_DYN);
        smem_set = 1;
    }

    zero_kernel<<<4096, 256>>>(out, (size_t)out_size);
    w1t_kernel<<<256, 256>>>(W1);
    qproj_kernel<<<BB, 512>>>(query, W1, We1);
    logits_mma_kernel<<<dim3(KK / 128, BB), 512, SM_DYN>>>(cand, b1, W2, b2, gum);
    topk_kernel<<<BB, 1024>>>(score, out);
    encoder_kernel<<<dim3(SK / RPB, BB), 512>>>(cand, We1, be1, We2, be2, eps, out);
    klfinal_kernel<<<1, 256>>>(out);
}

// round 5
// speedup vs baseline: 3.4489x; 1.2147x over previous
#include <cuda_runtime.h>
#include <cuda_fp16.h>
#include <math.h>
#include <stdint.h>

#define BB 32
#define KK 8192
#define DC 256
#define DQ 256
#define HID 256
#define SK 50
#define IB 512
#define EH 512

// ---- output layout (f32, tuple concatenated) ----
#define OFF_Z    0ull
#define OFF_SEL  819200ull
#define OFF_KL   13926400ull
#define OFF_HARD 13926401ull
#define OFF_SSC  27033601ull
#define OFF_SRS  27035201ull

// ---- scratch ----
__device__ float g_logits[BB * KK];
__device__ float g_sel[BB * KK];
__device__ float g_qW1[BB * HID];
__device__ float g_qWe1[BB * EH];
__device__ int   g_topk[BB * SK];
__device__ float g_klblk[BB * 5];
// W1^T fp16 in fragment-permuted layout: 8 chunks x 1024 uint4 (16KB/chunk)
__device__ __align__(16) uint4 g_Bp[8 * 1024];

// ===================== helpers =====================
__device__ __forceinline__ uint32_t h2u(__half2 h) {
    return *reinterpret_cast<uint32_t*>(&h);
}
__device__ __forceinline__ void mma16(float* c, const uint4& a, uint32_t b0, uint32_t b1) {
    asm volatile(
        "mma.sync.aligned.m16n8k16.row.col.f32.f16.f16.f32 "
        "{%0,%1,%2,%3},{%4,%5,%6,%7},{%8,%9},{%0,%1,%2,%3};"
        : "+f"(c[0]), "+f"(c[1]), "+f"(c[2]), "+f"(c[3])
        : "r"(a.x), "r"(a.y), "r"(a.z), "r"(a.w), "r"(b0), "r"(b1));
}

// ===================== zero output =====================
__global__ void zero_kernel(float* __restrict__ out, size_t n) {
    size_t n4 = n >> 2;
    float4* o4 = reinterpret_cast<float4*>(out);
    size_t i = (size_t)blockIdx.x * blockDim.x + threadIdx.x;
    size_t stride = (size_t)gridDim.x * blockDim.x;
    float4 z = make_float4(0.f, 0.f, 0.f, 0.f);
    for (; i < n4; i += stride) o4[i] = z;
    if (blockIdx.x == 0 && threadIdx.x == 0) {
        for (size_t t = n4 << 2; t < n; t++) out[t] = 0.f;
    }
}

// ===================== W1 -> permuted fp16 fragments =====================
// Per k-chunk c (32 k's): [ntile(32)][ktile(2)][lane(32)] x 8B (uint2 per lane):
//   pos0:(n=ntile*8+lane/4, k=ktile*16+(lane%4)*2) pos1:k+1 pos2:k+8 pos3:k+9
__global__ void w1t_kernel(const float* __restrict__ W1) {
    int idx = blockIdx.x * 256 + threadIdx.x;   // 65536
    int k = idx >> 8, n = idx & 255;
    float x = W1[(size_t)k * HID + n];
    __half h = __float2half_rn(x);
    int c = k >> 5, kp = k & 31;
    int ntile = n >> 3, g = n & 7;
    int ktile = kp >> 4;
    int lane = g * 4 + ((kp & 7) >> 1);
    int pos = (kp & 1) + 2 * ((kp & 15) >> 3);
    size_t off = (size_t)c * 8192 + (size_t)(((ntile * 2 + ktile) * 32 + lane) * 4 + pos);
    reinterpret_cast<__half*>(g_Bp)[off] = h;
}

// ===================== query projections =====================
// grid (3, 32): bx=0 -> qW1[256], bx=1,2 -> qWe1 halves. 256 threads.
__global__ void qproj_kernel(const float* __restrict__ q,
                             const float* __restrict__ W1,
                             const float* __restrict__ We1) {
    int bx = blockIdx.x, b = blockIdx.y, tid = threadIdx.x;
    __shared__ float qs[DQ];
    qs[tid] = q[b * DQ + tid];
    __syncthreads();
    float s = 0.f;
    if (bx == 0) {
        #pragma unroll 8
        for (int d = 0; d < DQ; d++) s += qs[d] * W1[(size_t)(DC + d) * HID + tid];
        g_qW1[b * HID + tid] = s;
    } else {
        int c0 = (bx - 1) * 256 + tid;
        #pragma unroll 8
        for (int d = 0; d < DQ; d++) s += qs[d] * We1[(size_t)(DC + d) * EH + c0];
        g_qWe1[b * EH + c0] = s;
    }
}

// ===================== scorer logits: fp16 2-pass A-split mma =====================
// CTA tile: M=64 x N=256, 256 threads (8 warps, 2x4), 2 CTAs/SM.
// K=256 in 8 chunks of 32; double-buffered smem stage = Ah 4KB | Al 4KB | B 16KB.
#define SAH 0
#define SAL 4096
#define SB  8192
#define STAGE_B 24576
#define SM_DYN (2 * STAGE_B)

struct Pref { float4 a[2]; uint4 b[4]; };

__device__ __forceinline__ void load_pref(Pref& p, const float* __restrict__ cand,
                                          int b, int k0, int c, int tid) {
    #pragma unroll
    for (int t = 0; t < 2; t++) {
        int idx = tid + t * 256;
        int m = idx >> 3, k4 = idx & 7;
        p.a[t] = *reinterpret_cast<const float4*>(
            &cand[((size_t)b * KK + k0 + m) * DC + c * 32 + k4 * 4]);
    }
    #pragma unroll
    for (int t = 0; t < 4; t++)
        p.b[t] = g_Bp[c * 1024 + tid + t * 256];
}

__device__ __forceinline__ void store_stage(char* __restrict__ st, const Pref& p, int tid) {
    #pragma unroll
    for (int t = 0; t < 2; t++) {
        int idx = tid + t * 256;
        int m = idx >> 3, k4 = idx & 7;
        float4 v = p.a[t];
        __half hx = __float2half_rn(v.x), hy = __float2half_rn(v.y);
        __half hz = __float2half_rn(v.z), hw = __float2half_rn(v.w);
        uint32_t h01 = h2u(__halves2half2(hx, hy));
        uint32_t h23 = h2u(__halves2half2(hz, hw));
        uint32_t l01 = h2u(__halves2half2(__float2half_rn(v.x - __half2float(hx)),
                                          __float2half_rn(v.y - __half2float(hy))));
        uint32_t l23 = h2u(__halves2half2(__float2half_rn(v.z - __half2float(hz)),
                                          __float2half_rn(v.w - __half2float(hw))));
        int mtile = m >> 4, r = m & 15;
        int ktile = k4 >> 2;
        int lane0 = (r & 7) * 4 + (k4 & 1) * 2;
        int boff = 2 * ((r >> 3) & 1) + 4 * ((k4 >> 1) & 1);   // fp16 units
        int base = ((mtile * 2 + ktile) * 32) * 16 + boff * 2; // bytes
        *reinterpret_cast<uint32_t*>(st + SAH + base + lane0 * 16)       = h01;
        *reinterpret_cast<uint32_t*>(st + SAH + base + (lane0 + 1) * 16) = h23;
        *reinterpret_cast<uint32_t*>(st + SAL + base + lane0 * 16)       = l01;
        *reinterpret_cast<uint32_t*>(st + SAL + base + (lane0 + 1) * 16) = l23;
    }
    #pragma unroll
    for (int t = 0; t < 4; t++)
        reinterpret_cast<uint4*>(st + SB)[tid + t * 256] = p.b[t];
}

__device__ __forceinline__ void compute_stage(const char* __restrict__ st,
                                              float acc[2][8][4],
                                              int wm, int wn, int lane) {
    #pragma unroll
    for (int kt = 0; kt < 2; kt++) {
        uint4 ah[2], al[2];
        #pragma unroll
        for (int mt = 0; mt < 2; mt++) {
            int off = (((wm * 2 + mt) * 2 + kt) * 32 + lane) * 16;
            ah[mt] = *reinterpret_cast<const uint4*>(st + SAH + off);
            al[mt] = *reinterpret_cast<const uint4*>(st + SAL + off);
        }
        #pragma unroll
        for (int nt = 0; nt < 8; nt++) {
            int ntile = wn * 8 + nt;
            int boff = ((ntile * 2 + kt) * 32 + lane) * 8;
            uint2 bb = *reinterpret_cast<const uint2*>(st + SB + boff);
            #pragma unroll
            for (int mt = 0; mt < 2; mt++) {
                mma16(acc[mt][nt], ah[mt], bb.x, bb.y);
                mma16(acc[mt][nt], al[mt], bb.x, bb.y);
            }
        }
    }
}

__global__ void __launch_bounds__(256, 2)
logits_mma_kernel(const float* __restrict__ cand,
                  const float* __restrict__ b1,
                  const float* __restrict__ W2,
                  const float* __restrict__ b2,
                  const float* __restrict__ gum) {
    extern __shared__ char dsm[];
    __shared__ float qb_s[HID];
    __shared__ float w2_s[HID];
    __shared__ float part[64][4];

    const int tid = threadIdx.x;
    const int b = blockIdx.y;
    const int k0 = blockIdx.x * 64;
    const int w = tid >> 5, lane = tid & 31;
    const int wm = w & 1, wn = w >> 1;

    qb_s[tid] = g_qW1[b * HID + tid] + b1[tid];
    w2_s[tid] = W2[tid];

    float acc[2][8][4];
    #pragma unroll
    for (int mt = 0; mt < 2; mt++)
        #pragma unroll
        for (int nt = 0; nt < 8; nt++)
            #pragma unroll
            for (int r = 0; r < 4; r++) acc[mt][nt][r] = 0.f;

    Pref p;
    load_pref(p, cand, b, k0, 0, tid);
    store_stage(dsm, p, tid);
    __syncthreads();

    for (int c = 0; c < 8; c++) {
        if (c < 7) load_pref(p, cand, b, k0, c + 1, tid);
        compute_stage(dsm + (c & 1) * STAGE_B, acc, wm, wn, lane);
        if (c < 7) store_stage(dsm + ((c + 1) & 1) * STAGE_B, p, tid);
        __syncthreads();
    }

    // epilogue: relu(D + qb) * w2, reduce over n
    float rs[2][2] = {{0.f, 0.f}, {0.f, 0.f}};
    #pragma unroll
    for (int mt = 0; mt < 2; mt++)
        #pragma unroll
        for (int nt = 0; nt < 8; nt++)
            #pragma unroll
            for (int ci = 0; ci < 4; ci++) {
                int col = wn * 64 + nt * 8 + (lane & 3) * 2 + (ci & 1);
                float v = acc[mt][nt][ci] + qb_s[col];
                rs[mt][ci >> 1] += fmaxf(v, 0.f) * w2_s[col];
            }
    #pragma unroll
    for (int mt = 0; mt < 2; mt++)
        #pragma unroll
        for (int rh = 0; rh < 2; rh++) {
            float s = rs[mt][rh];
            s += __shfl_xor_sync(0xffffffffu, s, 1);
            s += __shfl_xor_sync(0xffffffffu, s, 2);
            if ((lane & 3) == 0)
                part[wm * 32 + mt * 16 + rh * 8 + (lane >> 2)][wn] = s;
        }
    __syncthreads();
    if (tid < 64) {
        float lg = part[tid][0] + part[tid][1] + part[tid][2] + part[tid][3] + b2[0];
        size_t gi = (size_t)b * KK + k0 + tid;
        g_logits[gi] = lg;
        g_sel[gi] = lg + gum[gi];
    }
}

// ===================== top-k (register-resident argmax, 50 rounds) =====================
__global__ void __launch_bounds__(1024)
topk_kernel(const float* __restrict__ cand_score, float* __restrict__ out) {
    const int b = blockIdx.x;
    const int tid = threadIdx.x;
    const int lane = tid & 31, w = tid >> 5;
    const int base = tid * 8;
    float v[8];
    #pragma unroll
    for (int r = 0; r < 8; r++) v[r] = g_sel[(size_t)b * KK + base + r];

    __shared__ float wv[32];
    __shared__ int   wi[32];
    __shared__ int   bcast;

    for (int s = 0; s < SK; s++) {
        float bv = v[0]; int bi = base;
        #pragma unroll
        for (int r = 1; r < 8; r++) if (v[r] > bv) { bv = v[r]; bi = base + r; }
        #pragma unroll
        for (int off = 16; off; off >>= 1) {
            float ov = __shfl_down_sync(0xffffffffu, bv, off);
            int   oi = __shfl_down_sync(0xffffffffu, bi, off);
            if (ov > bv || (ov == bv && oi < bi)) { bv = ov; bi = oi; }
        }
        if (lane == 0) { wv[w] = bv; wi[w] = bi; }
        __syncthreads();
        if (w == 0) {
            float rv = wv[lane]; int ri = wi[lane];
            #pragma unroll
            for (int off = 16; off; off >>= 1) {
                float ov = __shfl_down_sync(0xffffffffu, rv, off);
                int   oi = __shfl_down_sync(0xffffffffu, ri, off);
                if (ov > rv || (ov == rv && oi < ri)) { rv = ov; ri = oi; }
            }
            if (lane == 0) {
                int idx = ri;
                bcast = idx;
                int row = b * SK + s;
                g_topk[row] = idx;
                out[OFF_SSC + row] = g_logits[(size_t)b * KK + idx];
                out[OFF_SRS + row] = cand_score[(size_t)b * KK + idx];
                out[OFF_SEL + (size_t)row * KK + idx] = 1.0f;
                out[OFF_HARD + (size_t)row * KK + idx] = 1.0f;
            }
        }
        __syncthreads();
        int ib = bcast;
        if ((ib >> 3) == tid) v[ib & 7] = -INFINITY;
    }
}

// ===================== encoder / IB head (1024 threads, col-split) =====================
#define RPB 10
#define ESM_F (RPB * DC + 3 * RPB * EH)   // sel 2560 + he 5120 + sd 5120 + lsr 5120
__global__ void __launch_bounds__(1024)
encoder_kernel(const float* __restrict__ cand,
               const float* __restrict__ We1,
               const float* __restrict__ be1,
               const float* __restrict__ We2,
               const float* __restrict__ be2,
               const float* __restrict__ eps,
               float* __restrict__ out) {
    extern __shared__ float esm[];
    float* sel_s = esm;                       // [10][256]
    float* he_s  = esm + RPB * DC;            // [10][512]
    float* sd_s  = he_s + RPB * EH;           // [10][512]
    float* lsr_s = sd_s + RPB * EH;           // [10][512]
    __shared__ int   idxs[RPB];
    __shared__ float redp[32];

    const int tid = threadIdx.x;
    const int b = blockIdx.y;
    const int s0 = blockIdx.x * RPB;
    const int half = tid >> 9, col = tid & 511;

    if (tid < RPB) idxs[tid] = g_topk[b * SK + s0 + tid];
    __syncthreads();
    for (int e = tid; e < RPB * DC; e += 1024) {
        int r = e >> 8, d = e & 255;
        sel_s[r * DC + d] = cand[((size_t)b * KK + idxs[r]) * DC + d];
    }
    __syncthreads();

    // We1: half splits d-range; combine in he_s
    {
        float acc[RPB];
        #pragma unroll
        for (int r = 0; r < RPB; r++) acc[r] = 0.f;
        int d0 = half * 128;
        for (int d = d0; d < d0 + 128; d++) {
            float wv = We1[(size_t)d * EH + col];
            #pragma unroll
            for (int r = 0; r < RPB; r++) acc[r] += sel_s[r * DC + d] * wv;
        }
        if (half == 0) {
            #pragma unroll
            for (int r = 0; r < RPB; r++) he_s[r * EH + col] = acc[r];
        }
        __syncthreads();
        if (half == 1) {
            float bias = g_qWe1[b * EH + col] + be1[col];
            #pragma unroll
            for (int r = 0; r < RPB; r++) {
                float h = he_s[r * EH + col] + acc[r] + bias;
                he_s[r * EH + col] = h > 0.f ? h : 0.f;
            }
        }
        __syncthreads();
    }

    // We2: half 0 -> mu columns, half 1 -> log_sigma columns
    float a2[RPB];
    #pragma unroll
    for (int r = 0; r < RPB; r++) a2[r] = 0.f;
    const float* wp = We2 + half * IB + col;
    for (int h = 0; h < EH; h++) {
        float wv = wp[(size_t)h * (2 * IB)];
        #pragma unroll
        for (int r = 0; r < RPB; r++) a2[r] += he_s[r * EH + h] * wv;
    }
    if (half == 1) {
        float bls = be2[IB + col];
        #pragma unroll
        for (int r = 0; r < RPB; r++) {
            float lsr = a2[r] + bls;
            float lsc = fminf(fmaxf(lsr, -10.f), 10.f);
            sd_s[r * EH + col] = expf(lsc);
            lsr_s[r * EH + col] = lsr;
        }
    }
    __syncthreads();

    float tkl = 0.f;
    if (half == 0) {
        float bmu = be2[col];
        #pragma unroll
        for (int r = 0; r < RPB; r++) {
            int row = b * SK + s0 + r;
            float mu = a2[r] + bmu;
            float sd = sd_s[r * EH + col];
            float lsr = lsr_s[r * EH + col];
            out[OFF_Z + (size_t)row * IB + col] = mu + sd * eps[(size_t)row * IB + col];
            tkl += mu * mu + sd * sd - 1.0f - 2.0f * lsr;
        }
    }
    #pragma unroll
    for (int off = 16; off; off >>= 1) tkl += __shfl_down_sync(0xffffffffu, tkl, off);
    if ((tid & 31) == 0) redp[tid >> 5] = tkl;
    __syncthreads();
    if (tid == 0) {
        float s = 0.f;
        #pragma unroll
        for (int ww = 0; ww < 32; ww++) s += redp[ww];
        g_klblk[b * 5 + blockIdx.x] = 0.5f * s;
    }
}

// ===================== kl finalize =====================
__global__ void klfinal_kernel(float* __restrict__ out) {
    const int tid = threadIdx.x;   // 256
    __shared__ float redp[8];
    float s = 0.f;
    for (int i = tid; i < BB * 5; i += 256) s += g_klblk[i];
    #pragma unroll
    for (int off = 16; off; off >>= 1) s += __shfl_down_sync(0xffffffffu, s, off);
    if ((tid & 31) == 0) redp[tid >> 5] = s;
    __syncthreads();
    if (tid == 0) {
        float t = 0.f;
        #pragma unroll
        for (int w = 0; w < 8; w++) t += redp[w];
        out[OFF_KL] = (t / (float)(BB * SK)) * 0.001f;
    }
}

// ===================== launch =====================
extern "C" void kernel_launch(void* const* d_in, const int* in_sizes, int n_in,
                              void* d_out, int out_size) {
    const float* query = (const float*)d_in[0];
    const float* cand  = (const float*)d_in[1];
    const float* score = (const float*)d_in[2];
    const float* gum   = (const float*)d_in[3];
    const float* eps   = (const float*)d_in[4];
    const float* W1    = (const float*)d_in[5];
    const float* b1    = (const float*)d_in[6];
    const float* W2    = (const float*)d_in[7];
    const float* b2    = (const float*)d_in[8];
    const float* We1   = (const float*)d_in[9];
    const float* be1   = (const float*)d_in[10];
    const float* We2   = (const float*)d_in[11];
    const float* be2   = (const float*)d_in[12];
    float* out = (float*)d_out;

    static int attr_set = 0;
    if (!attr_set) {
        cudaFuncSetAttribute(logits_mma_kernel,
                             cudaFuncAttributeMaxDynamicSharedMemorySize, SM_DYN);
        cudaFuncSetAttribute(encoder_kernel,
                             cudaFuncAttributeMaxDynamicSharedMemorySize, ESM_F * 4);
        attr_set = 1;
    }

    zero_kernel<<<4096, 256>>>(out, (size_t)out_size);
    w1t_kernel<<<256, 256>>>(W1);
    qproj_kernel<<<dim3(3, BB), 256>>>(query, W1, We1);
    logits_mma_kernel<<<dim3(KK / 64, BB), 256, SM_DYN>>>(cand, b1, W2, b2, gum);
    topk_kernel<<<BB, 1024>>>(score, out);
    encoder_kernel<<<dim3(SK / RPB, BB), 1024, ESM_F * 4>>>(cand, We1, be1, We2, be2, eps, out);
    klfinal_kernel<<<1, 256>>>(out);
}

// round 6
// speedup vs baseline: 4.5554x; 1.3208x over previous
#include <cuda_runtime.h>
#include <cuda_fp16.h>
#include <math.h>
#include <stdint.h>

#define BB 32
#define KK 8192
#define DC 256
#define DQ 256
#define HID 256
#define SK 50
#define IB 512
#define EH 512

// ---- output layout (f32, tuple concatenated) ----
#define OFF_Z    0ull
#define OFF_SEL  819200ull
#define OFF_KL   13926400ull
#define OFF_HARD 13926401ull
#define OFF_SSC  27033601ull
#define OFF_SRS  27035201ull

// ---- scratch ----
__device__ float g_logits[BB * KK];
__device__ float g_sel[BB * KK];
__device__ float g_qW1[BB * HID];
__device__ float g_qWe1[BB * EH];
__device__ int   g_topk[BB * SK];
__device__ float g_klblk[BB * 10];
// W1^T fp16 fragment-permuted: 8 chunks(32k) x 1024 uint4
__device__ __align__(16) uint4 g_Bp[8 * 1024];

// ===================== helpers =====================
__device__ __forceinline__ uint32_t h2u(__half2 h) {
    return *reinterpret_cast<uint32_t*>(&h);
}
__device__ __forceinline__ uint32_t smem_u32(const void* p) {
    uint32_t a;
    asm("{ .reg .u64 t; cvta.to.shared.u64 t, %1; cvt.u32.u64 %0, t; }" : "=r"(a) : "l"(p));
    return a;
}
__device__ __forceinline__ void mma16(float* c, const uint4& a, uint32_t b0, uint32_t b1) {
    asm volatile(
        "mma.sync.aligned.m16n8k16.row.col.f32.f16.f16.f32 "
        "{%0,%1,%2,%3},{%4,%5,%6,%7},{%8,%9},{%0,%1,%2,%3};"
        : "+f"(c[0]), "+f"(c[1]), "+f"(c[2]), "+f"(c[3])
        : "r"(a.x), "r"(a.y), "r"(a.z), "r"(a.w), "r"(b0), "r"(b1));
}
__device__ __forceinline__ void cp16(uint32_t dst, const void* src) {
    asm volatile("cp.async.cg.shared.global [%0], [%1], 16;" :: "r"(dst), "l"(src));
}
#define CP_COMMIT() asm volatile("cp.async.commit_group;" ::: "memory")
#define CP_WAIT0()  asm volatile("cp.async.wait_group 0;" ::: "memory")

// ===================== prep: zero out + W1 permute + qproj =====================
#define NZB 2048
__global__ void __launch_bounds__(256)
prep_kernel(float* __restrict__ out, size_t n,
            const float* __restrict__ W1,
            const float* __restrict__ q,
            const float* __restrict__ We1) {
    int blk = blockIdx.x, tid = threadIdx.x;
    if (blk < NZB) {
        size_t n4 = n >> 2;
        float4* o4 = reinterpret_cast<float4*>(out);
        size_t i = (size_t)blk * 256 + tid;
        size_t stride = (size_t)NZB * 256;
        float4 z = make_float4(0.f, 0.f, 0.f, 0.f);
        for (; i < n4; i += stride) o4[i] = z;
        if (blk == 0 && tid == 0)
            for (size_t t = n4 << 2; t < n; t++) out[t] = 0.f;
        return;
    }
    blk -= NZB;
    if (blk < 256) {   // W1 -> permuted fp16 fragments
        int idx = blk * 256 + tid;
        int k = idx >> 8, n2 = idx & 255;
        float x = W1[(size_t)k * HID + n2];
        __half h = __float2half_rn(x);
        int c = k >> 5, kp = k & 31;
        int ntile = n2 >> 3, g = n2 & 7;
        int ktile = kp >> 4;
        int lane = g * 4 + ((kp & 7) >> 1);
        int pos = (kp & 1) + 2 * ((kp & 15) >> 3);
        size_t off = (size_t)c * 8192 +
                     (size_t)(((ntile * 2 + ktile) * 32 + lane) * 4 + pos);
        reinterpret_cast<__half*>(g_Bp)[off] = h;
        return;
    }
    blk -= 256;        // qproj: 96 blocks = 3 per batch
    int sub = blk % 3, b = blk / 3;
    __shared__ float qs[DQ];
    qs[tid] = q[b * DQ + tid];
    __syncthreads();
    float s = 0.f;
    if (sub == 0) {
        #pragma unroll 8
        for (int d = 0; d < DQ; d++) s += qs[d] * W1[(size_t)(DC + d) * HID + tid];
        g_qW1[b * HID + tid] = s;
    } else {
        int c0 = (sub - 1) * 256 + tid;
        #pragma unroll 8
        for (int d = 0; d < DQ; d++) s += qs[d] * We1[(size_t)(DC + d) * EH + c0];
        g_qWe1[b * EH + c0] = s;
    }
}

// ===================== scorer logits: fp16 2-pass, cp.async B =====================
// CTA tile M=64 x N=256, 256 threads, 2 CTAs/SM. K=256 in 4 chunks of 64.
// Stage: Ah 8KB | Al 8KB | B 32KB = 48KB, double buffered.
#define SAH 0
#define SAL 8192
#define SB  16384
#define STAGE_B 49152
#define SM_DYN (2 * STAGE_B)

struct PrefA { float4 a[4]; };

__device__ __forceinline__ void load_prefA(PrefA& p, const float* __restrict__ cand,
                                           int b, int k0, int c, int tid) {
    #pragma unroll
    for (int t = 0; t < 4; t++) {
        int idx = tid + t * 256;
        int m = idx >> 4, k4 = idx & 15;
        p.a[t] = *reinterpret_cast<const float4*>(
            &cand[((size_t)b * KK + k0 + m) * DC + c * 64 + k4 * 4]);
    }
}

__device__ __forceinline__ void cp_asyncB(uint32_t stb, int c, int tid) {
    #pragma unroll
    for (int t = 0; t < 8; t++) {
        int idx = tid + t * 256;
        int sub = idx >> 10, j = idx & 1023;
        cp16(stb + SB + sub * 16384 + j * 16, &g_Bp[(c * 2 + sub) * 1024 + j]);
    }
}

__device__ __forceinline__ void store_stageA(char* __restrict__ st, const PrefA& p, int tid) {
    #pragma unroll
    for (int t = 0; t < 4; t++) {
        int idx = tid + t * 256;
        int m = idx >> 4, k4 = idx & 15;
        int sub = k4 >> 3, k4in = k4 & 7;
        float4 v = p.a[t];
        __half hx = __float2half_rn(v.x), hy = __float2half_rn(v.y);
        __half hz = __float2half_rn(v.z), hw = __float2half_rn(v.w);
        uint32_t h01 = h2u(__halves2half2(hx, hy));
        uint32_t h23 = h2u(__halves2half2(hz, hw));
        uint32_t l01 = h2u(__halves2half2(__float2half_rn(v.x - __half2float(hx)),
                                          __float2half_rn(v.y - __half2float(hy))));
        uint32_t l23 = h2u(__halves2half2(__float2half_rn(v.z - __half2float(hz)),
                                          __float2half_rn(v.w - __half2float(hw))));
        int mtile = m >> 4, r = m & 15;
        int ktile = k4in >> 2;
        int lane0 = (r & 7) * 4 + (k4in & 1) * 2;
        int boff = 2 * ((r >> 3) & 1) + 4 * ((k4in >> 1) & 1);
        int base = sub * 4096 + ((mtile * 2 + ktile) * 32) * 16 + boff * 2;
        *reinterpret_cast<uint32_t*>(st + SAH + base + lane0 * 16)       = h01;
        *reinterpret_cast<uint32_t*>(st + SAH + base + (lane0 + 1) * 16) = h23;
        *reinterpret_cast<uint32_t*>(st + SAL + base + lane0 * 16)       = l01;
        *reinterpret_cast<uint32_t*>(st + SAL + base + (lane0 + 1) * 16) = l23;
    }
}

__device__ __forceinline__ void compute_stage(const char* __restrict__ st,
                                              float acc[2][8][4],
                                              int wm, int wn, int lane) {
    #pragma unroll
    for (int sub = 0; sub < 2; sub++) {
        #pragma unroll
        for (int kt = 0; kt < 2; kt++) {
            uint4 ah[2], al[2];
            #pragma unroll
            for (int mt = 0; mt < 2; mt++) {
                int off = sub * 4096 + (((wm * 2 + mt) * 2 + kt) * 32 + lane) * 16;
                ah[mt] = *reinterpret_cast<const uint4*>(st + SAH + off);
                al[mt] = *reinterpret_cast<const uint4*>(st + SAL + off);
            }
            #pragma unroll
            for (int nt = 0; nt < 8; nt++) {
                int ntile = wn * 8 + nt;
                int boff = sub * 16384 + ((ntile * 2 + kt) * 32 + lane) * 8;
                uint2 bb = *reinterpret_cast<const uint2*>(st + SB + boff);
                #pragma unroll
                for (int mt = 0; mt < 2; mt++) {
                    mma16(acc[mt][nt], ah[mt], bb.x, bb.y);
                    mma16(acc[mt][nt], al[mt], bb.x, bb.y);
                }
            }
        }
    }
}

__global__ void __launch_bounds__(256, 2)
logits_mma_kernel(const float* __restrict__ cand,
                  const float* __restrict__ b1,
                  const float* __restrict__ W2,
                  const float* __restrict__ b2,
                  const float* __restrict__ gum) {
    extern __shared__ char dsm[];
    __shared__ float qb_s[HID];
    __shared__ float w2_s[HID];
    __shared__ float part[64][4];

    const int tid = threadIdx.x;
    const int b = blockIdx.y;
    const int k0 = blockIdx.x * 64;
    const int w = tid >> 5, lane = tid & 31;
    const int wm = w & 1, wn = w >> 1;
    const uint32_t sb = smem_u32(dsm);

    qb_s[tid] = g_qW1[b * HID + tid] + b1[tid];
    w2_s[tid] = W2[tid];

    float acc[2][8][4];
    #pragma unroll
    for (int mt = 0; mt < 2; mt++)
        #pragma unroll
        for (int nt = 0; nt < 8; nt++)
            #pragma unroll
            for (int r = 0; r < 4; r++) acc[mt][nt][r] = 0.f;

    PrefA p;
    load_prefA(p, cand, b, k0, 0, tid);
    cp_asyncB(sb, 0, tid);
    CP_COMMIT();
    store_stageA(dsm, p, tid);
    CP_WAIT0();
    __syncthreads();

    #pragma unroll
    for (int c = 0; c < 4; c++) {
        if (c < 3) {
            load_prefA(p, cand, b, k0, c + 1, tid);
            cp_asyncB(sb + ((c + 1) & 1) * STAGE_B, c + 1, tid);
            CP_COMMIT();
        }
        compute_stage(dsm + (c & 1) * STAGE_B, acc, wm, wn, lane);
        if (c < 3) store_stageA(dsm + ((c + 1) & 1) * STAGE_B, p, tid);
        CP_WAIT0();
        __syncthreads();
    }

    // epilogue: relu(D + qb) * w2, reduce over n
    float rs[2][2] = {{0.f, 0.f}, {0.f, 0.f}};
    #pragma unroll
    for (int mt = 0; mt < 2; mt++)
        #pragma unroll
        for (int nt = 0; nt < 8; nt++)
            #pragma unroll
            for (int ci = 0; ci < 4; ci++) {
                int col = wn * 64 + nt * 8 + (lane & 3) * 2 + (ci & 1);
                float v = acc[mt][nt][ci] + qb_s[col];
                rs[mt][ci >> 1] += fmaxf(v, 0.f) * w2_s[col];
            }
    #pragma unroll
    for (int mt = 0; mt < 2; mt++)
        #pragma unroll
        for (int rh = 0; rh < 2; rh++) {
            float s = rs[mt][rh];
            s += __shfl_xor_sync(0xffffffffu, s, 1);
            s += __shfl_xor_sync(0xffffffffu, s, 2);
            if ((lane & 3) == 0)
                part[wm * 32 + mt * 16 + rh * 8 + (lane >> 2)][wn] = s;
        }
    __syncthreads();
    if (tid < 64) {
        float lg = part[tid][0] + part[tid][1] + part[tid][2] + part[tid][3] + b2[0];
        size_t gi = (size_t)b * KK + k0 + tid;
        g_logits[gi] = lg;
        g_sel[gi] = lg + gum[gi];
    }
}

// ===================== top-k via 4-level radix select =====================
__global__ void __launch_bounds__(1024)
topk_kernel(const float* __restrict__ cand_score, float* __restrict__ out) {
    const int b = blockIdx.x;
    const int tid = threadIdx.x;
    const int base = tid * 8;

    __shared__ uint32_t hist8[8][256];
    __shared__ uint32_t shist[256];
    __shared__ uint32_t s_prefix, s_above;
    __shared__ uint32_t cntG, cntE;
    __shared__ uint32_t gk[64];
    __shared__ int      gi[64];
    __shared__ int      ei[256];

    // monotonic keys
    uint32_t k[8];
    #pragma unroll
    for (int r = 0; r < 8; r++) {
        uint32_t u = __float_as_uint(g_sel[(size_t)b * KK + base + r]);
        k[r] = (u & 0x80000000u) ? ~u : (u | 0x80000000u);
    }
    if (tid == 0) { s_prefix = 0; s_above = 0; cntG = 0; cntE = 0; }

    #pragma unroll
    for (int round = 0; round < 4; round++) {
        const int shift = 24 - round * 8;
        // zero hists
        if (round == 0) {
            #pragma unroll
            for (int t = 0; t < 2; t++) hist8[(tid + t * 1024) >> 8][(tid + t * 1024) & 255] = 0;
        } else if (tid < 256) shist[tid] = 0;
        __syncthreads();
        uint32_t pfx = s_prefix;
        // accumulate
        if (round == 0) {
            uint32_t* hh = hist8[(tid >> 5) & 7];
            #pragma unroll
            for (int r = 0; r < 8; r++) atomicAdd(&hh[k[r] >> 24], 1u);
        } else {
            const int ps = shift + 8;
            #pragma unroll
            for (int r = 0; r < 8; r++)
                if ((k[r] >> ps) == (pfx >> ps))
                    atomicAdd(&shist[(k[r] >> shift) & 255u], 1u);
        }
        __syncthreads();
        if (round == 0 && tid < 256) {
            uint32_t s = 0;
            #pragma unroll
            for (int g = 0; g < 8; g++) s += hist8[g][tid];
            shist[tid] = s;
        }
        if (round == 0) __syncthreads();
        // scan by warp 0: descending cumulative, find bin of (50 - s_above)-th
        if (tid < 32) {
            uint32_t loc[8], tot = 0;
            #pragma unroll
            for (int j = 0; j < 8; j++) { loc[j] = shist[tid * 8 + j]; tot += loc[j]; }
            // exclusive suffix over lanes (sum of totals of lanes > tid)
            uint32_t suf = tot;
            #pragma unroll
            for (int off = 1; off < 32; off <<= 1) {
                uint32_t v = __shfl_down_sync(0xffffffffu, suf, off);
                if (tid + off < 32) suf += v;
            }
            uint32_t exclHi = suf - tot;
            uint32_t target = 50u - s_above;
            bool has = (exclHi < target) && (exclHi + tot >= target);
            if (has) {
                uint32_t c = exclHi;
                #pragma unroll
                for (int j = 7; j >= 0; j--) {
                    uint32_t nc = c + loc[j];
                    if (nc >= target) {
                        s_prefix = pfx | ((uint32_t)(tid * 8 + j) << shift);
                        s_above += c;   // strictly greater at this level
                        break;
                    }
                    c = nc;
                }
            }
        }
        __syncthreads();
    }

    const uint32_t T50 = s_prefix;
    const uint32_t C1 = s_above;        // keys > T50 (< 50)
    const int E = 50 - (int)C1;

    #pragma unroll
    for (int r = 0; r < 8; r++) {
        if (k[r] > T50) {
            uint32_t pos = atomicAdd(&cntG, 1u);
            gk[pos] = k[r]; gi[pos] = base + r;
        } else if (k[r] == T50) {
            uint32_t pos = atomicAdd(&cntE, 1u);
            if (pos < 256) ei[pos] = base + r;
        }
    }
    __syncthreads();

    // rank & write
    if (tid < (int)C1) {
        uint32_t mk = gk[tid]; int mi = gi[tid];
        int rank = 0;
        for (int j = 0; j < (int)C1; j++)
            if (gk[j] > mk || (gk[j] == mk && gi[j] < mi)) rank++;
        int row = b * SK + rank;
        g_topk[row] = mi;
        out[OFF_SSC + row] = g_logits[(size_t)b * KK + mi];
        out[OFF_SRS + row] = cand_score[(size_t)b * KK + mi];
        out[OFF_SEL + (size_t)row * KK + mi] = 1.0f;
        out[OFF_HARD + (size_t)row * KK + mi] = 1.0f;
    }
    int nE = (int)cntE; if (nE > 256) nE = 256;
    if (tid < nE) {
        int mi = ei[tid];
        int rank = 0;
        for (int j = 0; j < nE; j++) if (ei[j] < mi) rank++;
        if (rank < E) {
            int row = b * SK + (int)C1 + rank;
            g_topk[row] = mi;
            out[OFF_SSC + row] = g_logits[(size_t)b * KK + mi];
            out[OFF_SRS + row] = cand_score[(size_t)b * KK + mi];
            out[OFF_SEL + (size_t)row * KK + mi] = 1.0f;
            out[OFF_HARD + (size_t)row * KK + mi] = 1.0f;
        }
    }
}

// ===================== encoder / IB head (RPB=5, transposed smem) =====================
#define RPB 5
#define PAD 8
// dynamic floats: selT 256*8 | heT 512*8 | sd 5*512 | lsr 5*512
#define E_SEL 0
#define E_HE  (256 * PAD)
#define E_SD  (E_HE + 512 * PAD)
#define E_LSR (E_SD + RPB * EH)
#define ESM_F (E_LSR + RPB * EH)

__global__ void __launch_bounds__(1024)
encoder_kernel(const float* __restrict__ cand,
               const float* __restrict__ We1,
               const float* __restrict__ be1,
               const float* __restrict__ We2,
               const float* __restrict__ be2,
               const float* __restrict__ eps,
               float* __restrict__ out) {
    extern __shared__ float esm[];
    float* selT = esm + E_SEL;
    float* heT  = esm + E_HE;
    float* sd_s = esm + E_SD;
    float* lsr_s = esm + E_LSR;
    __shared__ int   idxs[RPB];
    __shared__ float redp[32];

    const int tid = threadIdx.x;
    const int b = blockIdx.y;
    const int s0 = blockIdx.x * RPB;
    const int half = tid >> 9, col = tid & 511;

    if (tid < RPB) idxs[tid] = g_topk[b * SK + s0 + tid];
    __syncthreads();
    for (int e = tid; e < RPB * DC; e += 1024) {
        int r = e >> 8, d = e & 255;
        selT[d * PAD + r] = cand[((size_t)b * KK + idxs[r]) * DC + d];
    }
    __syncthreads();

    // We1 (d-range split by half)
    {
        float acc[RPB];
        #pragma unroll
        for (int r = 0; r < RPB; r++) acc[r] = 0.f;
        int d0 = half * 128;
        for (int d = d0; d < d0 + 128; d++) {
            float wv = We1[(size_t)d * EH + col];
            float4 s4 = *reinterpret_cast<const float4*>(&selT[d * PAD]);
            float s5 = selT[d * PAD + 4];
            acc[0] += s4.x * wv; acc[1] += s4.y * wv;
            acc[2] += s4.z * wv; acc[3] += s4.w * wv;
            acc[4] += s5 * wv;
        }
        if (half == 0) {
            #pragma unroll
            for (int r = 0; r < RPB; r++) heT[col * PAD + r] = acc[r];
        }
        __syncthreads();
        if (half == 1) {
            float bias = g_qWe1[b * EH + col] + be1[col];
            #pragma unroll
            for (int r = 0; r < RPB; r++) {
                float h = heT[col * PAD + r] + acc[r] + bias;
                heT[col * PAD + r] = h > 0.f ? h : 0.f;
            }
        }
        __syncthreads();
    }

    // We2: half 0 -> mu cols, half 1 -> log_sigma cols
    float a2[RPB];
    #pragma unroll
    for (int r = 0; r < RPB; r++) a2[r] = 0.f;
    const float* wp = We2 + half * IB + col;
    for (int h = 0; h < EH; h++) {
        float wv = wp[(size_t)h * (2 * IB)];
        float4 h4 = *reinterpret_cast<const float4*>(&heT[h * PAD]);
        float h5 = heT[h * PAD + 4];
        a2[0] += h4.x * wv; a2[1] += h4.y * wv;
        a2[2] += h4.z * wv; a2[3] += h4.w * wv;
        a2[4] += h5 * wv;
    }
    if (half == 1) {
        float bls = be2[IB + col];
        #pragma unroll
        for (int r = 0; r < RPB; r++) {
            float lsr = a2[r] + bls;
            float lsc = fminf(fmaxf(lsr, -10.f), 10.f);
            sd_s[r * EH + col] = expf(lsc);
            lsr_s[r * EH + col] = lsr;
        }
    }
    __syncthreads();

    float tkl = 0.f;
    if (half == 0) {
        float bmu = be2[col];
        #pragma unroll
        for (int r = 0; r < RPB; r++) {
            int row = b * SK + s0 + r;
            float mu = a2[r] + bmu;
            float sd = sd_s[r * EH + col];
            float lsr = lsr_s[r * EH + col];
            out[OFF_Z + (size_t)row * IB + col] = mu + sd * eps[(size_t)row * IB + col];
            tkl += mu * mu + sd * sd - 1.0f - 2.0f * lsr;
        }
    }
    #pragma unroll
    for (int off = 16; off; off >>= 1) tkl += __shfl_down_sync(0xffffffffu, tkl, off);
    if ((tid & 31) == 0) redp[tid >> 5] = tkl;
    __syncthreads();
    if (tid == 0) {
        float s = 0.f;
        #pragma unroll
        for (int ww = 0; ww < 32; ww++) s += redp[ww];
        g_klblk[b * 10 + blockIdx.x] = 0.5f * s;
    }
}

// ===================== kl finalize =====================
__global__ void klfinal_kernel(float* __restrict__ out) {
    const int tid = threadIdx.x;   // 320
    __shared__ float redp[10];
    float s = (tid < BB * 10) ? g_klblk[tid] : 0.f;
    #pragma unroll
    for (int off = 16; off; off >>= 1) s += __shfl_down_sync(0xffffffffu, s, off);
    if ((tid & 31) == 0) redp[tid >> 5] = s;
    __syncthreads();
    if (tid == 0) {
        float t = 0.f;
        #pragma unroll
        for (int w = 0; w < 10; w++) t += redp[w];
        out[OFF_KL] = (t / (float)(BB * SK)) * 0.001f;
    }
}

// ===================== launch =====================
extern "C" void kernel_launch(void* const* d_in, const int* in_sizes, int n_in,
                              void* d_out, int out_size) {
    const float* query = (const float*)d_in[0];
    const float* cand  = (const float*)d_in[1];
    const float* score = (const float*)d_in[2];
    const float* gum   = (const float*)d_in[3];
    const float* eps   = (const float*)d_in[4];
    const float* W1    = (const float*)d_in[5];
    const float* b1    = (const float*)d_in[6];
    const float* W2    = (const float*)d_in[7];
    const float* b2    = (const float*)d_in[8];
    const float* We1   = (const float*)d_in[9];
    const float* be1   = (const float*)d_in[10];
    const float* We2   = (const float*)d_in[11];
    const float* be2   = (const float*)d_in[12];
    float* out = (float*)d_out;

    static int attr_set = 0;
    if (!attr_set) {
        cudaFuncSetAttribute(logits_mma_kernel,
                             cudaFuncAttributeMaxDynamicSharedMemorySize, SM_DYN);
        cudaFuncSetAttribute(encoder_kernel,
                             cudaFuncAttributeMaxDynamicSharedMemorySize, ESM_F * 4);
        attr_set = 1;
    }

    prep_kernel<<<NZB + 256 + 96, 256>>>(out, (size_t)out_size, W1, query, We1);
    logits_mma_kernel<<<dim3(KK / 64, BB), 256, SM_DYN>>>(cand, b1, W2, b2, gum);
    topk_kernel<<<BB, 1024>>>(score, out);
    encoder_kernel<<<dim3(SK / RPB, BB), 1024, ESM_F * 4>>>(cand, We1, be1, We2, be2, eps, out);
    klfinal_kernel<<<1, 320>>>(out);
}

// round 7
// speedup vs baseline: 5.5091x; 1.2094x over previous
#include <cuda_runtime.h>
#include <cuda_fp16.h>
#include <math.h>
#include <stdint.h>

#define BB 32
#define KK 8192
#define DC 256
#define DQ 256
#define HID 256
#define SK 50
#define IB 512
#define EH 512

// ---- output layout (f32, tuple concatenated) ----
#define OFF_Z    0ull
#define OFF_SEL  819200ull
#define OFF_KL   13926400ull
#define OFF_HARD 13926401ull
#define OFF_SSC  27033601ull
#define OFF_SRS  27035201ull

// ---- scratch ----
__device__ float g_logits[BB * KK];
__device__ float g_sel[BB * KK];
__device__ float g_qW1[BB * HID];
__device__ float g_qWe1[BB * EH];
__device__ int   g_topk[BB * SK];
__device__ float g_klblk[BB];
// W1^T fp16 fragment-permuted (for logits): 8 chunks(32k) x 1024 uint4
__device__ __align__(16) uint4 g_Bp[8 * 1024];
// We1^T fp16 fragment-permuted: 8 k-chunks x 64 ntiles x 2 x 32 x 4 halves
__device__ __align__(16) __half g_We1p[131072];
// We2^T fp16 fragment-permuted + mu/ls column interleave: 16 k-chunks x 128 ntiles
__device__ __align__(16) __half g_We2p[524288];

// ===================== helpers =====================
__device__ __forceinline__ uint32_t h2u(__half2 h) {
    return *reinterpret_cast<uint32_t*>(&h);
}
__device__ __forceinline__ uint32_t smem_u32(const void* p) {
    uint32_t a;
    asm("{ .reg .u64 t; cvta.to.shared.u64 t, %1; cvt.u32.u64 %0, t; }" : "=r"(a) : "l"(p));
    return a;
}
__device__ __forceinline__ void mma16(float* c, const uint4& a, uint32_t b0, uint32_t b1) {
    asm volatile(
        "mma.sync.aligned.m16n8k16.row.col.f32.f16.f16.f32 "
        "{%0,%1,%2,%3},{%4,%5,%6,%7},{%8,%9},{%0,%1,%2,%3};"
        : "+f"(c[0]), "+f"(c[1]), "+f"(c[2]), "+f"(c[3])
        : "r"(a.x), "r"(a.y), "r"(a.z), "r"(a.w), "r"(b0), "r"(b1));
}
__device__ __forceinline__ void cp16(uint32_t dst, const void* src) {
    asm volatile("cp.async.cg.shared.global [%0], [%1], 16;" :: "r"(dst), "l"(src));
}
#define CP_COMMIT() asm volatile("cp.async.commit_group;" ::: "memory")
#define CP_WAIT0()  asm volatile("cp.async.wait_group 0;" ::: "memory")
#define CP_WAIT1()  asm volatile("cp.async.wait_group 1;" ::: "memory")

// A-fragment load from row-major fp16 smem (stride in halves)
__device__ __forceinline__ uint4 ldsA(const __half* A, int stride, int rb, int kb, int lane) {
    const __half* p0 = A + (rb + (lane >> 2)) * stride + kb + (lane & 3) * 2;
    uint4 a;
    a.x = *reinterpret_cast<const uint32_t*>(p0);
    a.y = *reinterpret_cast<const uint32_t*>(p0 + 8 * stride);
    a.z = *reinterpret_cast<const uint32_t*>(p0 + 8);
    a.w = *reinterpret_cast<const uint32_t*>(p0 + 8 * stride + 8);
    return a;
}

// ===================== prep: zero + permutes + qproj =====================
#define NZB 2048
__global__ void __launch_bounds__(256)
prep_kernel(float* __restrict__ out, size_t n,
            const float* __restrict__ W1,
            const float* __restrict__ q,
            const float* __restrict__ We1,
            const float* __restrict__ We2) {
    int blk = blockIdx.x, tid = threadIdx.x;
    if (blk < NZB) {
        size_t n4 = n >> 2;
        float4* o4 = reinterpret_cast<float4*>(out);
        size_t i = (size_t)blk * 256 + tid;
        size_t stride = (size_t)NZB * 256;
        float4 z = make_float4(0.f, 0.f, 0.f, 0.f);
        for (; i < n4; i += stride) o4[i] = z;
        if (blk == 0 && tid == 0)
            for (size_t t = n4 << 2; t < n; t++) out[t] = 0.f;
        return;
    }
    blk -= NZB;
    if (blk < 256) {   // W1 -> permuted fp16 fragments for logits
        int idx = blk * 256 + tid;
        int k = idx >> 8, n2 = idx & 255;
        float x = W1[(size_t)k * HID + n2];
        int c = k >> 5, kp = k & 31;
        int ntile = n2 >> 3, g = n2 & 7;
        int ktile = kp >> 4;
        int lane = g * 4 + ((kp & 7) >> 1);
        int pos = (kp & 1) + 2 * ((kp & 15) >> 3);
        size_t off = (size_t)c * 8192 +
                     (size_t)(((ntile * 2 + ktile) * 32 + lane) * 4 + pos);
        reinterpret_cast<__half*>(g_Bp)[off] = __float2half_rn(x);
        return;
    }
    blk -= 256;
    if (blk < 96) {    // qproj: 3 per batch
        int sub = blk % 3, b = blk / 3;
        __shared__ float qs[DQ];
        qs[tid] = q[b * DQ + tid];
        __syncthreads();
        float s = 0.f;
        if (sub == 0) {
            #pragma unroll 8
            for (int d = 0; d < DQ; d++) s += qs[d] * W1[(size_t)(DC + d) * HID + tid];
            g_qW1[b * HID + tid] = s;
        } else {
            int c0 = (sub - 1) * 256 + tid;
            #pragma unroll 8
            for (int d = 0; d < DQ; d++) s += qs[d] * We1[(size_t)(DC + d) * EH + c0];
            g_qWe1[b * EH + c0] = s;
        }
        return;
    }
    blk -= 96;
    if (blk < 512) {   // We1^T (first 256 rows) -> permuted fp16
        int idx = blk * 256 + tid;        // [0, 131072)
        int k = idx >> 9, n2 = idx & 511;
        float x = We1[(size_t)k * EH + n2];
        int c = k >> 5, kp = k & 31;
        int ntile = n2 >> 3, g = n2 & 7;
        int ktile = kp >> 4;
        int lane = g * 4 + ((kp & 7) >> 1);
        int pos = (kp & 1) + 2 * ((kp & 15) >> 3);
        g_We1p[(((c * 64 + ntile) * 2 + ktile) * 32 + lane) * 4 + pos] = __float2half_rn(x);
        return;
    }
    blk -= 512;        // We2^T col-interleaved -> permuted fp16 (2048 blocks)
    {
        int idx = blk * 256 + tid;        // [0, 524288)
        int k = idx >> 10, n2 = idx & 1023;
        float x = We2[(size_t)k * (2 * IB) + n2];
        int pcol = (n2 < 512) ? (2 * n2) : (2 * (n2 - 512) + 1);
        int c = k >> 5, kp = k & 31;
        int ntile = pcol >> 3, g = pcol & 7;
        int ktile = kp >> 4;
        int lane = g * 4 + ((kp & 7) >> 1);
        int pos = (kp & 1) + 2 * ((kp & 15) >> 3);
        g_We2p[(((c * 128 + ntile) * 2 + ktile) * 32 + lane) * 4 + pos] = __float2half_rn(x);
    }
}

// ===================== scorer logits: fp16 2-pass, cp.async B =====================
#define SAH 0
#define SAL 8192
#define SB  16384
#define STAGE_B 49152
#define SM_DYN (2 * STAGE_B)

struct PrefA { float4 a[4]; };

__device__ __forceinline__ void load_prefA(PrefA& p, const float* __restrict__ cand,
                                           int b, int k0, int c, int tid) {
    #pragma unroll
    for (int t = 0; t < 4; t++) {
        int idx = tid + t * 256;
        int m = idx >> 4, k4 = idx & 15;
        p.a[t] = *reinterpret_cast<const float4*>(
            &cand[((size_t)b * KK + k0 + m) * DC + c * 64 + k4 * 4]);
    }
}

__device__ __forceinline__ void cp_asyncB(uint32_t stb, int c, int tid) {
    #pragma unroll
    for (int t = 0; t < 8; t++) {
        int idx = tid + t * 256;
        int sub = idx >> 10, j = idx & 1023;
        cp16(stb + SB + sub * 16384 + j * 16, &g_Bp[(c * 2 + sub) * 1024 + j]);
    }
}

__device__ __forceinline__ void store_stageA(char* __restrict__ st, const PrefA& p, int tid) {
    #pragma unroll
    for (int t = 0; t < 4; t++) {
        int idx = tid + t * 256;
        int m = idx >> 4, k4 = idx & 15;
        int sub = k4 >> 3, k4in = k4 & 7;
        float4 v = p.a[t];
        __half hx = __float2half_rn(v.x), hy = __float2half_rn(v.y);
        __half hz = __float2half_rn(v.z), hw = __float2half_rn(v.w);
        uint32_t h01 = h2u(__halves2half2(hx, hy));
        uint32_t h23 = h2u(__halves2half2(hz, hw));
        uint32_t l01 = h2u(__halves2half2(__float2half_rn(v.x - __half2float(hx)),
                                          __float2half_rn(v.y - __half2float(hy))));
        uint32_t l23 = h2u(__halves2half2(__float2half_rn(v.z - __half2float(hz)),
                                          __float2half_rn(v.w - __half2float(hw))));
        int mtile = m >> 4, r = m & 15;
        int ktile = k4in >> 2;
        int lane0 = (r & 7) * 4 + (k4in & 1) * 2;
        int boff = 2 * ((r >> 3) & 1) + 4 * ((k4in >> 1) & 1);
        int base = sub * 4096 + ((mtile * 2 + ktile) * 32) * 16 + boff * 2;
        *reinterpret_cast<uint32_t*>(st + SAH + base + lane0 * 16)       = h01;
        *reinterpret_cast<uint32_t*>(st + SAH + base + (lane0 + 1) * 16) = h23;
        *reinterpret_cast<uint32_t*>(st + SAL + base + lane0 * 16)       = l01;
        *reinterpret_cast<uint32_t*>(st + SAL + base + (lane0 + 1) * 16) = l23;
    }
}

__device__ __forceinline__ void compute_stage(const char* __restrict__ st,
                                              float acc[2][8][4],
                                              int wm, int wn, int lane) {
    #pragma unroll
    for (int sub = 0; sub < 2; sub++) {
        #pragma unroll
        for (int kt = 0; kt < 2; kt++) {
            uint4 ah[2], al[2];
            #pragma unroll
            for (int mt = 0; mt < 2; mt++) {
                int off = sub * 4096 + (((wm * 2 + mt) * 2 + kt) * 32 + lane) * 16;
                ah[mt] = *reinterpret_cast<const uint4*>(st + SAH + off);
                al[mt] = *reinterpret_cast<const uint4*>(st + SAL + off);
            }
            #pragma unroll
            for (int nt = 0; nt < 8; nt++) {
                int ntile = wn * 8 + nt;
                int boff = sub * 16384 + ((ntile * 2 + kt) * 32 + lane) * 8;
                uint2 bb = *reinterpret_cast<const uint2*>(st + SB + boff);
                #pragma unroll
                for (int mt = 0; mt < 2; mt++) {
                    mma16(acc[mt][nt], ah[mt], bb.x, bb.y);
                    mma16(acc[mt][nt], al[mt], bb.x, bb.y);
                }
            }
        }
    }
}

__global__ void __launch_bounds__(256, 2)
logits_mma_kernel(const float* __restrict__ cand,
                  const float* __restrict__ b1,
                  const float* __restrict__ W2,
                  const float* __restrict__ b2,
                  const float* __restrict__ gum) {
    extern __shared__ char dsm[];
    __shared__ float qb_s[HID];
    __shared__ float w2_s[HID];
    __shared__ float part[64][4];

    const int tid = threadIdx.x;
    const int b = blockIdx.y;
    const int k0 = blockIdx.x * 64;
    const int w = tid >> 5, lane = tid & 31;
    const int wm = w & 1, wn = w >> 1;
    const uint32_t sb = smem_u32(dsm);

    qb_s[tid] = g_qW1[b * HID + tid] + b1[tid];
    w2_s[tid] = W2[tid];

    float acc[2][8][4];
    #pragma unroll
    for (int mt = 0; mt < 2; mt++)
        #pragma unroll
        for (int nt = 0; nt < 8; nt++)
            #pragma unroll
            for (int r = 0; r < 4; r++) acc[mt][nt][r] = 0.f;

    PrefA p;
    load_prefA(p, cand, b, k0, 0, tid);
    cp_asyncB(sb, 0, tid);
    CP_COMMIT();
    store_stageA(dsm, p, tid);
    CP_WAIT0();
    __syncthreads();

    #pragma unroll
    for (int c = 0; c < 4; c++) {
        if (c < 3) {
            load_prefA(p, cand, b, k0, c + 1, tid);
            cp_asyncB(sb + ((c + 1) & 1) * STAGE_B, c + 1, tid);
            CP_COMMIT();
        }
        compute_stage(dsm + (c & 1) * STAGE_B, acc, wm, wn, lane);
        if (c < 3) store_stageA(dsm + ((c + 1) & 1) * STAGE_B, p, tid);
        CP_WAIT0();
        __syncthreads();
    }

    float rs[2][2] = {{0.f, 0.f}, {0.f, 0.f}};
    #pragma unroll
    for (int mt = 0; mt < 2; mt++)
        #pragma unroll
        for (int nt = 0; nt < 8; nt++)
            #pragma unroll
            for (int ci = 0; ci < 4; ci++) {
                int col = wn * 64 + nt * 8 + (lane & 3) * 2 + (ci & 1);
                float v = acc[mt][nt][ci] + qb_s[col];
                rs[mt][ci >> 1] += fmaxf(v, 0.f) * w2_s[col];
            }
    #pragma unroll
    for (int mt = 0; mt < 2; mt++)
        #pragma unroll
        for (int rh = 0; rh < 2; rh++) {
            float s = rs[mt][rh];
            s += __shfl_xor_sync(0xffffffffu, s, 1);
            s += __shfl_xor_sync(0xffffffffu, s, 2);
            if ((lane & 3) == 0)
                part[wm * 32 + mt * 16 + rh * 8 + (lane >> 2)][wn] = s;
        }
    __syncthreads();
    if (tid < 64) {
        float lg = part[tid][0] + part[tid][1] + part[tid][2] + part[tid][3] + b2[0];
        size_t gi = (size_t)b * KK + k0 + tid;
        g_logits[gi] = lg;
        g_sel[gi] = lg + gum[gi];
    }
}

// ===================== top-k via 4-level radix select =====================
__global__ void __launch_bounds__(1024)
topk_kernel(const float* __restrict__ cand_score, float* __restrict__ out) {
    const int b = blockIdx.x;
    const int tid = threadIdx.x;
    const int base = tid * 8;

    __shared__ uint32_t hist8[8][256];
    __shared__ uint32_t shist[256];
    __shared__ uint32_t s_prefix, s_above;
    __shared__ uint32_t cntG, cntE;
    __shared__ uint32_t gk[64];
    __shared__ int      gi[64];
    __shared__ int      ei[256];

    uint32_t k[8];
    #pragma unroll
    for (int r = 0; r < 8; r++) {
        uint32_t u = __float_as_uint(g_sel[(size_t)b * KK + base + r]);
        k[r] = (u & 0x80000000u) ? ~u : (u | 0x80000000u);
    }
    if (tid == 0) { s_prefix = 0; s_above = 0; cntG = 0; cntE = 0; }

    #pragma unroll
    for (int round = 0; round < 4; round++) {
        const int shift = 24 - round * 8;
        if (round == 0) {
            #pragma unroll
            for (int t = 0; t < 2; t++) hist8[(tid + t * 1024) >> 8][(tid + t * 1024) & 255] = 0;
        } else if (tid < 256) shist[tid] = 0;
        __syncthreads();
        uint32_t pfx = s_prefix;
        if (round == 0) {
            uint32_t* hh = hist8[(tid >> 5) & 7];
            #pragma unroll
            for (int r = 0; r < 8; r++) atomicAdd(&hh[k[r] >> 24], 1u);
        } else {
            const int ps = shift + 8;
            #pragma unroll
            for (int r = 0; r < 8; r++)
                if ((k[r] >> ps) == (pfx >> ps))
                    atomicAdd(&shist[(k[r] >> shift) & 255u], 1u);
        }
        __syncthreads();
        if (round == 0 && tid < 256) {
            uint32_t s = 0;
            #pragma unroll
            for (int g = 0; g < 8; g++) s += hist8[g][tid];
            shist[tid] = s;
        }
        if (round == 0) __syncthreads();
        if (tid < 32) {
            uint32_t loc[8], tot = 0;
            #pragma unroll
            for (int j = 0; j < 8; j++) { loc[j] = shist[tid * 8 + j]; tot += loc[j]; }
            uint32_t suf = tot;
            #pragma unroll
            for (int off = 1; off < 32; off <<= 1) {
                uint32_t v = __shfl_down_sync(0xffffffffu, suf, off);
                if (tid + off < 32) suf += v;
            }
            uint32_t exclHi = suf - tot;
            uint32_t target = 50u - s_above;
            bool has = (exclHi < target) && (exclHi + tot >= target);
            if (has) {
                uint32_t c = exclHi;
                #pragma unroll
                for (int j = 7; j >= 0; j--) {
                    uint32_t nc = c + loc[j];
                    if (nc >= target) {
                        s_prefix = pfx | ((uint32_t)(tid * 8 + j) << shift);
                        s_above += c;
                        break;
                    }
                    c = nc;
                }
            }
        }
        __syncthreads();
    }

    const uint32_t T50 = s_prefix;
    const uint32_t C1 = s_above;
    const int E = 50 - (int)C1;

    #pragma unroll
    for (int r = 0; r < 8; r++) {
        if (k[r] > T50) {
            uint32_t pos = atomicAdd(&cntG, 1u);
            gk[pos] = k[r]; gi[pos] = base + r;
        } else if (k[r] == T50) {
            uint32_t pos = atomicAdd(&cntE, 1u);
            if (pos < 256) ei[pos] = base + r;
        }
    }
    __syncthreads();

    if (tid < (int)C1) {
        uint32_t mk = gk[tid]; int mi = gi[tid];
        int rank = 0;
        for (int j = 0; j < (int)C1; j++)
            if (gk[j] > mk || (gk[j] == mk && gi[j] < mi)) rank++;
        int row = b * SK + rank;
        g_topk[row] = mi;
        out[OFF_SSC + row] = g_logits[(size_t)b * KK + mi];
        out[OFF_SRS + row] = cand_score[(size_t)b * KK + mi];
        out[OFF_SEL + (size_t)row * KK + mi] = 1.0f;
        out[OFF_HARD + (size_t)row * KK + mi] = 1.0f;
    }
    int nE = (int)cntE; if (nE > 256) nE = 256;
    if (tid < nE) {
        int mi = ei[tid];
        int rank = 0;
        for (int j = 0; j < nE; j++) if (ei[j] < mi) rank++;
        if (rank < E) {
            int row = b * SK + (int)C1 + rank;
            g_topk[row] = mi;
            out[OFF_SSC + row] = g_logits[(size_t)b * KK + mi];
            out[OFF_SRS + row] = cand_score[(size_t)b * KK + mi];
            out[OFF_SEL + (size_t)row * KK + mi] = 1.0f;
            out[OFF_HARD + (size_t)row * KK + mi] = 1.0f;
        }
    }
}

// ===================== encoder: fused fp16 tensor-core, one block/batch =====================
#define EST 264            // A1 row stride (halves)
#define HST 520            // heA row stride (halves)
#define O_A1 0
#define O_HE 33792
#define O_QB 100352
#define O_BE2 102400
#define O_BUF 106496
#define ENC_SMEM 139264

__device__ __forceinline__ void cp_slice(uint32_t dst, const char* src, int tid) {
    #pragma unroll
    for (int t = 0; t < 4; t++) {
        int i = (tid + t * 256) * 16;
        cp16(dst + i, src + i);
    }
}

__global__ void __launch_bounds__(256, 1)
encoder_kernel(const float* __restrict__ cand,
               const float* __restrict__ be1,
               const float* __restrict__ be2,
               const float* __restrict__ eps,
               float* __restrict__ out) {
    extern __shared__ char esm[];
    __half* A1  = reinterpret_cast<__half*>(esm + O_A1);
    __half* HE  = reinterpret_cast<__half*>(esm + O_HE);
    float* qb1  = reinterpret_cast<float*>(esm + O_QB);
    float* be2s = reinterpret_cast<float*>(esm + O_BE2);
    char* BUF = esm + O_BUF;
    const uint32_t bufu = smem_u32(BUF);
    __shared__ int idxs[64];
    __shared__ float redp[8];

    const int tid = threadIdx.x, b = blockIdx.x;
    const int w = tid >> 5, lane = tid & 31;
    const int wm = w & 1, wn = w >> 1;

    if (tid < 64) idxs[tid] = (tid < 50) ? g_topk[b * SK + tid] : 0;
    qb1[tid]       = g_qWe1[b * EH + tid] + be1[tid];
    qb1[tid + 256] = g_qWe1[b * EH + tid + 256] + be1[tid + 256];
    #pragma unroll
    for (int t = 0; t < 4; t++) be2s[tid + t * 256] = be2[tid + t * 256];
    __syncthreads();

    // gather selected rows -> A1 fp16 (rows 50..63 zero)
    #pragma unroll
    for (int t = 0; t < 16; t++) {
        int idx = tid + t * 256;
        int r = idx >> 6, k4 = idx & 63;
        uint2 u; u.x = 0u; u.y = 0u;
        if (r < 50) {
            float4 v = *reinterpret_cast<const float4*>(
                &cand[((size_t)b * KK + idxs[r]) * DC + k4 * 4]);
            u.x = h2u(__halves2half2(__float2half_rn(v.x), __float2half_rn(v.y)));
            u.y = h2u(__halves2half2(__float2half_rn(v.z), __float2half_rn(v.w)));
        }
        *reinterpret_cast<uint2*>(&A1[r * EST + k4 * 4]) = u;
    }
    __syncthreads();

    // ---- GEMM1: he = relu(A1 @ We1a + qb1), N in 2 passes of 256 ----
    const char* we1p = reinterpret_cast<const char*>(g_We1p);
    for (int np = 0; np < 2; np++) {
        float acc[2][8][4];
        #pragma unroll
        for (int mt = 0; mt < 2; mt++)
            #pragma unroll
            for (int nt = 0; nt < 8; nt++)
                #pragma unroll
                for (int r = 0; r < 4; r++) acc[mt][nt][r] = 0.f;

        cp_slice(bufu, we1p + np * 16384, tid);
        CP_COMMIT();
        for (int c = 0; c < 8; c++) {
            if (c < 7) {
                cp_slice(bufu + ((c + 1) & 1) * 16384,
                         we1p + (size_t)(c + 1) * 32768 + np * 16384, tid);
                CP_COMMIT();
                CP_WAIT1();
            } else CP_WAIT0();
            __syncthreads();
            const char* bs = BUF + (c & 1) * 16384;
            #pragma unroll
            for (int kt = 0; kt < 2; kt++) {
                uint4 a[2];
                #pragma unroll
                for (int mt = 0; mt < 2; mt++)
                    a[mt] = ldsA(A1, EST, wm * 32 + mt * 16, c * 32 + kt * 16, lane);
                #pragma unroll
                for (int nt = 0; nt < 8; nt++) {
                    int ntl = wn * 8 + nt;
                    uint2 bb = *reinterpret_cast<const uint2*>(bs + ((ntl * 2 + kt) * 32 + lane) * 8);
                    #pragma unroll
                    for (int mt = 0; mt < 2; mt++)
                        mma16(acc[mt][nt], a[mt], bb.x, bb.y);
                }
            }
            __syncthreads();
        }
        // epilogue -> HE fp16
        #pragma unroll
        for (int mt = 0; mt < 2; mt++)
            #pragma unroll
            for (int nt = 0; nt < 8; nt++)
                #pragma unroll
                for (int pp = 0; pp < 2; pp++) {
                    int col = np * 256 + wn * 64 + nt * 8 + (lane & 3) * 2;
                    int row = wm * 32 + mt * 16 + (lane >> 2) + 8 * pp;
                    float v0 = fmaxf(acc[mt][nt][2 * pp]     + qb1[col],     0.f);
                    float v1 = fmaxf(acc[mt][nt][2 * pp + 1] + qb1[col + 1], 0.f);
                    *reinterpret_cast<uint32_t*>(&HE[row * HST + col]) =
                        h2u(__halves2half2(__float2half_rn(v0), __float2half_rn(v1)));
                }
        __syncthreads();
    }

    // ---- GEMM2: params = HE @ We2 (col-interleaved mu/ls), N in 4 passes ----
    const char* we2p = reinterpret_cast<const char*>(g_We2p);
    float kl = 0.f;
    for (int np = 0; np < 4; np++) {
        float acc[2][8][4];
        #pragma unroll
        for (int mt = 0; mt < 2; mt++)
            #pragma unroll
            for (int nt = 0; nt < 8; nt++)
                #pragma unroll
                for (int r = 0; r < 4; r++) acc[mt][nt][r] = 0.f;

        cp_slice(bufu, we2p + np * 16384, tid);
        CP_COMMIT();
        for (int c = 0; c < 16; c++) {
            if (c < 15) {
                cp_slice(bufu + ((c + 1) & 1) * 16384,
                         we2p + (size_t)(c + 1) * 65536 + np * 16384, tid);
                CP_COMMIT();
                CP_WAIT1();
            } else CP_WAIT0();
            __syncthreads();
            const char* bs = BUF + (c & 1) * 16384;
            #pragma unroll
            for (int kt = 0; kt < 2; kt++) {
                uint4 a[2];
                #pragma unroll
                for (int mt = 0; mt < 2; mt++)
                    a[mt] = ldsA(HE, HST, wm * 32 + mt * 16, c * 32 + kt * 16, lane);
                #pragma unroll
                for (int nt = 0; nt < 8; nt++) {
                    int ntl = wn * 8 + nt;
                    uint2 bb = *reinterpret_cast<const uint2*>(bs + ((ntl * 2 + kt) * 32 + lane) * 8);
                    #pragma unroll
                    for (int mt = 0; mt < 2; mt++)
                        mma16(acc[mt][nt], a[mt], bb.x, bb.y);
                }
            }
            __syncthreads();
        }
        // epilogue: (mu, ls) pairs -> z, kl
        #pragma unroll
        for (int mt = 0; mt < 2; mt++)
            #pragma unroll
            for (int nt = 0; nt < 8; nt++)
                #pragma unroll
                for (int pp = 0; pp < 2; pp++) {
                    int j = np * 128 + wn * 32 + nt * 4 + (lane & 3);
                    int row = wm * 32 + mt * 16 + (lane >> 2) + 8 * pp;
                    if (row < 50) {
                        float mu  = acc[mt][nt][2 * pp]     + be2s[j];
                        float lsr = acc[mt][nt][2 * pp + 1] + be2s[512 + j];
                        float lsc = fminf(fmaxf(lsr, -10.f), 10.f);
                        float sd = expf(lsc);
                        size_t grow = (size_t)b * SK + row;
                        out[OFF_Z + grow * IB + j] = mu + sd * eps[grow * IB + j];
                        kl += mu * mu + sd * sd - 1.0f - 2.0f * lsr;
                    }
                }
    }
    #pragma unroll
    for (int off = 16; off; off >>= 1) kl += __shfl_down_sync(0xffffffffu, kl, off);
    if (lane == 0) redp[w] = kl;
    __syncthreads();
    if (tid == 0) {
        float s = 0.f;
        #pragma unroll
        for (int ww = 0; ww < 8; ww++) s += redp[ww];
        g_klblk[b] = 0.5f * s;
    }
}

// ===================== kl finalize =====================
__global__ void klfinal_kernel(float* __restrict__ out) {
    float s = g_klblk[threadIdx.x];   // 32 threads
    #pragma unroll
    for (int off = 16; off; off >>= 1) s += __shfl_down_sync(0xffffffffu, s, off);
    if (threadIdx.x == 0)
        out[OFF_KL] = (s / (float)(BB * SK)) * 0.001f;
}

// ===================== launch =====================
extern "C" void kernel_launch(void* const* d_in, const int* in_sizes, int n_in,
                              void* d_out, int out_size) {
    const float* query = (const float*)d_in[0];
    const float* cand  = (const float*)d_in[1];
    const float* score = (const float*)d_in[2];
    const float* gum   = (const float*)d_in[3];
    const float* eps   = (const float*)d_in[4];
    const float* W1    = (const float*)d_in[5];
    const float* b1    = (const float*)d_in[6];
    const float* W2    = (const float*)d_in[7];
    const float* b2    = (const float*)d_in[8];
    const float* We1   = (const float*)d_in[9];
    const float* be1   = (const float*)d_in[10];
    const float* We2   = (const float*)d_in[11];
    const float* be2   = (const float*)d_in[12];
    float* out = (float*)d_out;

    static int attr_set = 0;
    if (!attr_set) {
        cudaFuncSetAttribute(logits_mma_kernel,
                             cudaFuncAttributeMaxDynamicSharedMemorySize, SM_DYN);
        cudaFuncSetAttribute(encoder_kernel,
                             cudaFuncAttributeMaxDynamicSharedMemorySize, ENC_SMEM);
        attr_set = 1;
    }

    prep_kernel<<<NZB + 256 + 96 + 512 + 2048, 256>>>(out, (size_t)out_size,
                                                      W1, query, We1, We2);
    logits_mma_kernel<<<dim3(KK / 64, BB), 256, SM_DYN>>>(cand, b1, W2, b2, gum);
    topk_kernel<<<BB, 1024>>>(score, out);
    encoder_kernel<<<BB, 256, ENC_SMEM>>>(cand, be1, be2, eps, out);
    klfinal_kernel<<<1, 32>>>(out);
}

// round 8
// speedup vs baseline: 6.3245x; 1.1480x over previous
#include <cuda_runtime.h>
#include <cuda_fp16.h>
#include <math.h>
#include <stdint.h>

#define BB 32
#define KK 8192
#define DC 256
#define DQ 256
#define HID 256
#define SK 50
#define IB 512
#define EH 512

// ---- output layout (f32, tuple concatenated) ----
#define OFF_Z    0ull
#define OFF_SEL  819200ull
#define OFF_KL   13926400ull
#define OFF_HARD 13926401ull
#define OFF_SSC  27033601ull
#define OFF_SRS  27035201ull

// ---- scratch ----
__device__ float g_logits[BB * KK];
__device__ float g_sel[BB * KK];
__device__ float g_qW1[BB * HID];
__device__ float g_qWe1[BB * EH];
__device__ int   g_topk[BB * SK];
__device__ float g_klblk[BB * 4];
// W1^T fp16 fragment-permuted (for logits): 8 chunks(32k) x 1024 uint4
__device__ __align__(16) uint4 g_Bp[8 * 1024];
// We1^T fp16 fragment-permuted: 8 k-chunks x 64 ntiles x 2 x 32 x 4 halves
__device__ __align__(16) __half g_We1p[131072];
// We2^T fp16 fragment-permuted + mu/ls column interleave: 16 k-chunks x 128 ntiles
__device__ __align__(16) __half g_We2p[524288];

// ===================== helpers =====================
__device__ __forceinline__ uint32_t h2u(__half2 h) {
    return *reinterpret_cast<uint32_t*>(&h);
}
__device__ __forceinline__ uint32_t smem_u32(const void* p) {
    uint32_t a;
    asm("{ .reg .u64 t; cvta.to.shared.u64 t, %1; cvt.u32.u64 %0, t; }" : "=r"(a) : "l"(p));
    return a;
}
__device__ __forceinline__ void mma16(float* c, const uint4& a, uint32_t b0, uint32_t b1) {
    asm volatile(
        "mma.sync.aligned.m16n8k16.row.col.f32.f16.f16.f32 "
        "{%0,%1,%2,%3},{%4,%5,%6,%7},{%8,%9},{%0,%1,%2,%3};"
        : "+f"(c[0]), "+f"(c[1]), "+f"(c[2]), "+f"(c[3])
        : "r"(a.x), "r"(a.y), "r"(a.z), "r"(a.w), "r"(b0), "r"(b1));
}
__device__ __forceinline__ void cp16(uint32_t dst, const void* src) {
    asm volatile("cp.async.cg.shared.global [%0], [%1], 16;" :: "r"(dst), "l"(src));
}
#define CP_COMMIT() asm volatile("cp.async.commit_group;" ::: "memory")
#define CP_WAIT0()  asm volatile("cp.async.wait_group 0;" ::: "memory")

// A-fragment load from row-major fp16 smem (stride in halves)
__device__ __forceinline__ uint4 ldsA(const __half* A, int stride, int rb, int kb, int lane) {
    const __half* p0 = A + (rb + (lane >> 2)) * stride + kb + (lane & 3) * 2;
    uint4 a;
    a.x = *reinterpret_cast<const uint32_t*>(p0);
    a.y = *reinterpret_cast<const uint32_t*>(p0 + 8 * stride);
    a.z = *reinterpret_cast<const uint32_t*>(p0 + 8);
    a.w = *reinterpret_cast<const uint32_t*>(p0 + 8 * stride + 8);
    return a;
}

// ===================== prep: zero + permutes + qproj =====================
#define NZB 2048
__global__ void __launch_bounds__(256)
prep_kernel(float* __restrict__ out, size_t n,
            const float* __restrict__ W1,
            const float* __restrict__ q,
            const float* __restrict__ We1,
            const float* __restrict__ We2) {
    int blk = blockIdx.x, tid = threadIdx.x;
    if (blk < NZB) {
        size_t n4 = n >> 2;
        float4* o4 = reinterpret_cast<float4*>(out);
        size_t i = (size_t)blk * 256 + tid;
        size_t stride = (size_t)NZB * 256;
        float4 z = make_float4(0.f, 0.f, 0.f, 0.f);
        for (; i < n4; i += stride) o4[i] = z;
        if (blk == 0 && tid == 0)
            for (size_t t = n4 << 2; t < n; t++) out[t] = 0.f;
        return;
    }
    blk -= NZB;
    if (blk < 256) {   // W1 -> permuted fp16 fragments for logits
        int idx = blk * 256 + tid;
        int k = idx >> 8, n2 = idx & 255;
        float x = W1[(size_t)k * HID + n2];
        int c = k >> 5, kp = k & 31;
        int ntile = n2 >> 3, g = n2 & 7;
        int ktile = kp >> 4;
        int lane = g * 4 + ((kp & 7) >> 1);
        int pos = (kp & 1) + 2 * ((kp & 15) >> 3);
        size_t off = (size_t)c * 8192 +
                     (size_t)(((ntile * 2 + ktile) * 32 + lane) * 4 + pos);
        reinterpret_cast<__half*>(g_Bp)[off] = __float2half_rn(x);
        return;
    }
    blk -= 256;
    if (blk < 96) {    // qproj: 3 per batch
        int sub = blk % 3, b = blk / 3;
        __shared__ float qs[DQ];
        qs[tid] = q[b * DQ + tid];
        __syncthreads();
        float s = 0.f;
        if (sub == 0) {
            #pragma unroll 8
            for (int d = 0; d < DQ; d++) s += qs[d] * W1[(size_t)(DC + d) * HID + tid];
            g_qW1[b * HID + tid] = s;
        } else {
            int c0 = (sub - 1) * 256 + tid;
            #pragma unroll 8
            for (int d = 0; d < DQ; d++) s += qs[d] * We1[(size_t)(DC + d) * EH + c0];
            g_qWe1[b * EH + c0] = s;
        }
        return;
    }
    blk -= 96;
    if (blk < 512) {   // We1^T (first 256 rows) -> permuted fp16
        int idx = blk * 256 + tid;        // [0, 131072)
        int k = idx >> 9, n2 = idx & 511;
        float x = We1[(size_t)k * EH + n2];
        int c = k >> 5, kp = k & 31;
        int ntile = n2 >> 3, g = n2 & 7;
        int ktile = kp >> 4;
        int lane = g * 4 + ((kp & 7) >> 1);
        int pos = (kp & 1) + 2 * ((kp & 15) >> 3);
        g_We1p[(((c * 64 + ntile) * 2 + ktile) * 32 + lane) * 4 + pos] = __float2half_rn(x);
        return;
    }
    blk -= 512;        // We2^T col-interleaved -> permuted fp16 (2048 blocks)
    {
        int idx = blk * 256 + tid;        // [0, 524288)
        int k = idx >> 10, n2 = idx & 1023;
        float x = We2[(size_t)k * (2 * IB) + n2];
        int pcol = (n2 < 512) ? (2 * n2) : (2 * (n2 - 512) + 1);
        int c = k >> 5, kp = k & 31;
        int ntile = pcol >> 3, g = pcol & 7;
        int ktile = kp >> 4;
        int lane = g * 4 + ((kp & 7) >> 1);
        int pos = (kp & 1) + 2 * ((kp & 15) >> 3);
        g_We2p[(((c * 128 + ntile) * 2 + ktile) * 32 + lane) * 4 + pos] = __float2half_rn(x);
    }
}

// ===================== scorer logits: fp16 2-pass, cp.async B =====================
#define SAH 0
#define SAL 8192
#define SB  16384
#define STAGE_B 49152
#define SM_DYN (2 * STAGE_B)

struct PrefA { float4 a[4]; };

__device__ __forceinline__ void load_prefA(PrefA& p, const float* __restrict__ cand,
                                           int b, int k0, int c, int tid) {
    #pragma unroll
    for (int t = 0; t < 4; t++) {
        int idx = tid + t * 256;
        int m = idx >> 4, k4 = idx & 15;
        p.a[t] = *reinterpret_cast<const float4*>(
            &cand[((size_t)b * KK + k0 + m) * DC + c * 64 + k4 * 4]);
    }
}

__device__ __forceinline__ void cp_asyncB(uint32_t stb, int c, int tid) {
    #pragma unroll
    for (int t = 0; t < 8; t++) {
        int idx = tid + t * 256;
        int sub = idx >> 10, j = idx & 1023;
        cp16(stb + SB + sub * 16384 + j * 16, &g_Bp[(c * 2 + sub) * 1024 + j]);
    }
}

__device__ __forceinline__ void store_stageA(char* __restrict__ st, const PrefA& p, int tid) {
    #pragma unroll
    for (int t = 0; t < 4; t++) {
        int idx = tid + t * 256;
        int m = idx >> 4, k4 = idx & 15;
        int sub = k4 >> 3, k4in = k4 & 7;
        float4 v = p.a[t];
        __half hx = __float2half_rn(v.x), hy = __float2half_rn(v.y);
        __half hz = __float2half_rn(v.z), hw = __float2half_rn(v.w);
        uint32_t h01 = h2u(__halves2half2(hx, hy));
        uint32_t h23 = h2u(__halves2half2(hz, hw));
        uint32_t l01 = h2u(__halves2half2(__float2half_rn(v.x - __half2float(hx)),
                                          __float2half_rn(v.y - __half2float(hy))));
        uint32_t l23 = h2u(__halves2half2(__float2half_rn(v.z - __half2float(hz)),
                                          __float2half_rn(v.w - __half2float(hw))));
        int mtile = m >> 4, r = m & 15;
        int ktile = k4in >> 2;
        int lane0 = (r & 7) * 4 + (k4in & 1) * 2;
        int boff = 2 * ((r >> 3) & 1) + 4 * ((k4in >> 1) & 1);
        int base = sub * 4096 + ((mtile * 2 + ktile) * 32) * 16 + boff * 2;
        *reinterpret_cast<uint32_t*>(st + SAH + base + lane0 * 16)       = h01;
        *reinterpret_cast<uint32_t*>(st + SAH + base + (lane0 + 1) * 16) = h23;
        *reinterpret_cast<uint32_t*>(st + SAL + base + lane0 * 16)       = l01;
        *reinterpret_cast<uint32_t*>(st + SAL + base + (lane0 + 1) * 16) = l23;
    }
}

__device__ __forceinline__ void compute_sub(const char* __restrict__ st, int sub,
                                            float acc[2][8][4],
                                            int wm, int wn, int lane) {
    #pragma unroll
    for (int kt = 0; kt < 2; kt++) {
        uint4 ah[2], al[2];
        #pragma unroll
        for (int mt = 0; mt < 2; mt++) {
            int off = sub * 4096 + (((wm * 2 + mt) * 2 + kt) * 32 + lane) * 16;
            ah[mt] = *reinterpret_cast<const uint4*>(st + SAH + off);
            al[mt] = *reinterpret_cast<const uint4*>(st + SAL + off);
        }
        #pragma unroll
        for (int nt = 0; nt < 8; nt++) {
            int ntile = wn * 8 + nt;
            int boff = sub * 16384 + ((ntile * 2 + kt) * 32 + lane) * 8;
            uint2 bb = *reinterpret_cast<const uint2*>(st + SB + boff);
            #pragma unroll
            for (int mt = 0; mt < 2; mt++) {
                mma16(acc[mt][nt], ah[mt], bb.x, bb.y);
                mma16(acc[mt][nt], al[mt], bb.x, bb.y);
            }
        }
    }
}

__global__ void __launch_bounds__(256, 2)
logits_mma_kernel(const float* __restrict__ cand,
                  const float* __restrict__ b1,
                  const float* __restrict__ W2,
                  const float* __restrict__ b2,
                  const float* __restrict__ gum) {
    extern __shared__ char dsm[];
    __shared__ float qb_s[HID];
    __shared__ float w2_s[HID];
    __shared__ float part[64][4];

    const int tid = threadIdx.x;
    const int b = blockIdx.y;
    const int k0 = blockIdx.x * 64;
    const int w = tid >> 5, lane = tid & 31;
    const int wm = w & 1, wn = w >> 1;
    const uint32_t sb = smem_u32(dsm);

    qb_s[tid] = g_qW1[b * HID + tid] + b1[tid];
    w2_s[tid] = W2[tid];

    float acc[2][8][4];
    #pragma unroll
    for (int mt = 0; mt < 2; mt++)
        #pragma unroll
        for (int nt = 0; nt < 8; nt++)
            #pragma unroll
            for (int r = 0; r < 4; r++) acc[mt][nt][r] = 0.f;

    PrefA p;
    load_prefA(p, cand, b, k0, 0, tid);
    cp_asyncB(sb, 0, tid);
    CP_COMMIT();
    store_stageA(dsm, p, tid);
    CP_WAIT0();
    __syncthreads();

    #pragma unroll
    for (int c = 0; c < 4; c++) {
        if (c < 3) {
            load_prefA(p, cand, b, k0, c + 1, tid);
            cp_asyncB(sb + ((c + 1) & 1) * STAGE_B, c + 1, tid);
            CP_COMMIT();
        }
        compute_sub(dsm + (c & 1) * STAGE_B, 0, acc, wm, wn, lane);
        if (c < 3) store_stageA(dsm + ((c + 1) & 1) * STAGE_B, p, tid);
        compute_sub(dsm + (c & 1) * STAGE_B, 1, acc, wm, wn, lane);
        CP_WAIT0();
        __syncthreads();
    }

    float rs[2][2] = {{0.f, 0.f}, {0.f, 0.f}};
    #pragma unroll
    for (int mt = 0; mt < 2; mt++)
        #pragma unroll
        for (int nt = 0; nt < 8; nt++)
            #pragma unroll
            for (int ci = 0; ci < 4; ci++) {
                int col = wn * 64 + nt * 8 + (lane & 3) * 2 + (ci & 1);
                float v = acc[mt][nt][ci] + qb_s[col];
                rs[mt][ci >> 1] += fmaxf(v, 0.f) * w2_s[col];
            }
    #pragma unroll
    for (int mt = 0; mt < 2; mt++)
        #pragma unroll
        for (int rh = 0; rh < 2; rh++) {
            float s = rs[mt][rh];
            s += __shfl_xor_sync(0xffffffffu, s, 1);
            s += __shfl_xor_sync(0xffffffffu, s, 2);
            if ((lane & 3) == 0)
                part[wm * 32 + mt * 16 + rh * 8 + (lane >> 2)][wn] = s;
        }
    __syncthreads();
    if (tid < 64) {
        float lg = part[tid][0] + part[tid][1] + part[tid][2] + part[tid][3] + b2[0];
        size_t gi = (size_t)b * KK + k0 + tid;
        g_logits[gi] = lg;
        g_sel[gi] = lg + gum[gi];
    }
}

// ===================== top-k via 4-level radix select =====================
__global__ void __launch_bounds__(1024)
topk_kernel(const float* __restrict__ cand_score, float* __restrict__ out) {
    const int b = blockIdx.x;
    const int tid = threadIdx.x;
    const int base = tid * 8;

    __shared__ uint32_t hist8[8][256];
    __shared__ uint32_t shist[256];
    __shared__ uint32_t s_prefix, s_above;
    __shared__ uint32_t cntG, cntE;
    __shared__ uint32_t gk[64];
    __shared__ int      gi[64];
    __shared__ int      ei[256];

    uint32_t k[8];
    #pragma unroll
    for (int r = 0; r < 8; r++) {
        uint32_t u = __float_as_uint(g_sel[(size_t)b * KK + base + r]);
        k[r] = (u & 0x80000000u) ? ~u : (u | 0x80000000u);
    }
    if (tid == 0) { s_prefix = 0; s_above = 0; cntG = 0; cntE = 0; }

    #pragma unroll
    for (int round = 0; round < 4; round++) {
        const int shift = 24 - round * 8;
        if (round == 0) {
            #pragma unroll
            for (int t = 0; t < 2; t++) hist8[(tid + t * 1024) >> 8][(tid + t * 1024) & 255] = 0;
        } else if (tid < 256) shist[tid] = 0;
        __syncthreads();
        uint32_t pfx = s_prefix;
        if (round == 0) {
            uint32_t* hh = hist8[(tid >> 5) & 7];
            #pragma unroll
            for (int r = 0; r < 8; r++) atomicAdd(&hh[k[r] >> 24], 1u);
        } else {
            const int ps = shift + 8;
            #pragma unroll
            for (int r = 0; r < 8; r++)
                if ((k[r] >> ps) == (pfx >> ps))
                    atomicAdd(&shist[(k[r] >> shift) & 255u], 1u);
        }
        __syncthreads();
        if (round == 0 && tid < 256) {
            uint32_t s = 0;
            #pragma unroll
            for (int g = 0; g < 8; g++) s += hist8[g][tid];
            shist[tid] = s;
        }
        if (round == 0) __syncthreads();
        if (tid < 32) {
            uint32_t loc[8], tot = 0;
            #pragma unroll
            for (int j = 0; j < 8; j++) { loc[j] = shist[tid * 8 + j]; tot += loc[j]; }
            uint32_t suf = tot;
            #pragma unroll
            for (int off = 1; off < 32; off <<= 1) {
                uint32_t v = __shfl_down_sync(0xffffffffu, suf, off);
                if (tid + off < 32) suf += v;
            }
            uint32_t exclHi = suf - tot;
            uint32_t target = 50u - s_above;
            bool has = (exclHi < target) && (exclHi + tot >= target);
            if (has) {
                uint32_t c = exclHi;
                #pragma unroll
                for (int j = 7; j >= 0; j--) {
                    uint32_t nc = c + loc[j];
                    if (nc >= target) {
                        s_prefix = pfx | ((uint32_t)(tid * 8 + j) << shift);
                        s_above += c;
                        break;
                    }
                    c = nc;
                }
            }
        }
        __syncthreads();
    }

    const uint32_t T50 = s_prefix;
    const uint32_t C1 = s_above;
    const int E = 50 - (int)C1;

    #pragma unroll
    for (int r = 0; r < 8; r++) {
        if (k[r] > T50) {
            uint32_t pos = atomicAdd(&cntG, 1u);
            gk[pos] = k[r]; gi[pos] = base + r;
        } else if (k[r] == T50) {
            uint32_t pos = atomicAdd(&cntE, 1u);
            if (pos < 256) ei[pos] = base + r;
        }
    }
    __syncthreads();

    if (tid < (int)C1) {
        uint32_t mk = gk[tid]; int mi = gi[tid];
        int rank = 0;
        for (int j = 0; j < (int)C1; j++)
            if (gk[j] > mk || (gk[j] == mk && gi[j] < mi)) rank++;
        int row = b * SK + rank;
        g_topk[row] = mi;
        out[OFF_SSC + row] = g_logits[(size_t)b * KK + mi];
        out[OFF_SRS + row] = cand_score[(size_t)b * KK + mi];
        out[OFF_SEL + (size_t)row * KK + mi] = 1.0f;
        out[OFF_HARD + (size_t)row * KK + mi] = 1.0f;
    }
    int nE = (int)cntE; if (nE > 256) nE = 256;
    if (tid < nE) {
        int mi = ei[tid];
        int rank = 0;
        for (int j = 0; j < nE; j++) if (ei[j] < mi) rank++;
        if (rank < E) {
            int row = b * SK + (int)C1 + rank;
            g_topk[row] = mi;
            out[OFF_SSC + row] = g_logits[(size_t)b * KK + mi];
            out[OFF_SRS + row] = cand_score[(size_t)b * KK + mi];
            out[OFF_SEL + (size_t)row * KK + mi] = 1.0f;
            out[OFF_HARD + (size_t)row * KK + mi] = 1.0f;
        }
    }
}

// ===================== encoder: fused fp16 TC, grid (4, BB) N-split =====================
#define EST 264            // A1 row stride (halves)
#define HST 520            // heA row stride (halves)
#define O_A1 0
#define O_HE 33792
#define O_QB 100352
#define O_BE2 102400
#define O_BUF 106496
#define ENC_SMEM 139264

__device__ __forceinline__ void cp_slice(uint32_t dst, const char* src, int tid) {
    #pragma unroll
    for (int t = 0; t < 4; t++) {
        int i = (tid + t * 256) * 16;
        cp16(dst + i, src + i);
    }
}

__global__ void __launch_bounds__(256, 1)
encoder_kernel(const float* __restrict__ cand,
               const float* __restrict__ be1,
               const float* __restrict__ be2,
               const float* __restrict__ eps,
               float* __restrict__ out) {
    extern __shared__ char esm[];
    __half* A1  = reinterpret_cast<__half*>(esm + O_A1);
    __half* HE  = reinterpret_cast<__half*>(esm + O_HE);
    float* qb1  = reinterpret_cast<float*>(esm + O_QB);
    float* be2s = reinterpret_cast<float*>(esm + O_BE2);
    char* BUF = esm + O_BUF;
    const uint32_t bufu = smem_u32(BUF);
    __shared__ int idxs[64];
    __shared__ float redp[8];

    const int tid = threadIdx.x;
    const int b = blockIdx.y;
    const int bx = blockIdx.x;              // N-quarter of GEMM2
    const int w = tid >> 5, lane = tid & 31;
    const int wm = w & 1, wn = w >> 1;

    if (tid < 64) idxs[tid] = (tid < 50) ? g_topk[b * SK + tid] : 0;
    qb1[tid]       = g_qWe1[b * EH + tid] + be1[tid];
    qb1[tid + 256] = g_qWe1[b * EH + tid + 256] + be1[tid + 256];
    #pragma unroll
    for (int t = 0; t < 4; t++) be2s[tid + t * 256] = be2[tid + t * 256];
    __syncthreads();

    // gather selected rows -> A1 fp16 (rows 50..63 zero)
    #pragma unroll
    for (int t = 0; t < 16; t++) {
        int idx = tid + t * 256;
        int r = idx >> 6, k4 = idx & 63;
        uint2 u; u.x = 0u; u.y = 0u;
        if (r < 50) {
            float4 v = *reinterpret_cast<const float4*>(
                &cand[((size_t)b * KK + idxs[r]) * DC + k4 * 4]);
            u.x = h2u(__halves2half2(__float2half_rn(v.x), __float2half_rn(v.y)));
            u.y = h2u(__halves2half2(__float2half_rn(v.z), __float2half_rn(v.w)));
        }
        *reinterpret_cast<uint2*>(&A1[r * EST + k4 * 4]) = u;
    }
    __syncthreads();

    // ---- GEMM1 (full, redundant across bx): he = relu(A1 @ We1a + qb1) ----
    const char* we1p = reinterpret_cast<const char*>(g_We1p);
    for (int np = 0; np < 2; np++) {
        float acc[2][8][4];
        #pragma unroll
        for (int mt = 0; mt < 2; mt++)
            #pragma unroll
            for (int nt = 0; nt < 8; nt++)
                #pragma unroll
                for (int r = 0; r < 4; r++) acc[mt][nt][r] = 0.f;

        cp_slice(bufu, we1p + np * 16384, tid);
        CP_COMMIT();
        for (int c = 0; c < 8; c++) {
            CP_WAIT0();
            __syncthreads();
            if (c < 7) {
                cp_slice(bufu + ((c + 1) & 1) * 16384,
                         we1p + (size_t)(c + 1) * 32768 + np * 16384, tid);
                CP_COMMIT();
            }
            const char* bs = BUF + (c & 1) * 16384;
            #pragma unroll
            for (int kt = 0; kt < 2; kt++) {
                uint4 a[2];
                #pragma unroll
                for (int mt = 0; mt < 2; mt++)
                    a[mt] = ldsA(A1, EST, wm * 32 + mt * 16, c * 32 + kt * 16, lane);
                #pragma unroll
                for (int nt = 0; nt < 8; nt++) {
                    int ntl = wn * 8 + nt;
                    uint2 bb = *reinterpret_cast<const uint2*>(bs + ((ntl * 2 + kt) * 32 + lane) * 8);
                    #pragma unroll
                    for (int mt = 0; mt < 2; mt++)
                        mma16(acc[mt][nt], a[mt], bb.x, bb.y);
                }
            }
        }
        __syncthreads();
        // epilogue -> HE fp16
        #pragma unroll
        for (int mt = 0; mt < 2; mt++)
            #pragma unroll
            for (int nt = 0; nt < 8; nt++)
                #pragma unroll
                for (int pp = 0; pp < 2; pp++) {
                    int col = np * 256 + wn * 64 + nt * 8 + (lane & 3) * 2;
                    int row = wm * 32 + mt * 16 + (lane >> 2) + 8 * pp;
                    float v0 = fmaxf(acc[mt][nt][2 * pp]     + qb1[col],     0.f);
                    float v1 = fmaxf(acc[mt][nt][2 * pp + 1] + qb1[col + 1], 0.f);
                    *reinterpret_cast<uint32_t*>(&HE[row * HST + col]) =
                        h2u(__halves2half2(__float2half_rn(v0), __float2half_rn(v1)));
                }
        __syncthreads();
    }

    // ---- GEMM2: one N-quarter (bx) of params = HE @ We2 (col-interleaved) ----
    const char* we2p = reinterpret_cast<const char*>(g_We2p);
    float kl = 0.f;
    {
        float acc[2][8][4];
        #pragma unroll
        for (int mt = 0; mt < 2; mt++)
            #pragma unroll
            for (int nt = 0; nt < 8; nt++)
                #pragma unroll
                for (int r = 0; r < 4; r++) acc[mt][nt][r] = 0.f;

        cp_slice(bufu, we2p + bx * 16384, tid);
        CP_COMMIT();
        for (int c = 0; c < 16; c++) {
            CP_WAIT0();
            __syncthreads();
            if (c < 15) {
                cp_slice(bufu + ((c + 1) & 1) * 16384,
                         we2p + (size_t)(c + 1) * 65536 + bx * 16384, tid);
                CP_COMMIT();
            }
            const char* bs = BUF + (c & 1) * 16384;
            #pragma unroll
            for (int kt = 0; kt < 2; kt++) {
                uint4 a[2];
                #pragma unroll
                for (int mt = 0; mt < 2; mt++)
                    a[mt] = ldsA(HE, HST, wm * 32 + mt * 16, c * 32 + kt * 16, lane);
                #pragma unroll
                for (int nt = 0; nt < 8; nt++) {
                    int ntl = wn * 8 + nt;
                    uint2 bb = *reinterpret_cast<const uint2*>(bs + ((ntl * 2 + kt) * 32 + lane) * 8);
                    #pragma unroll
                    for (int mt = 0; mt < 2; mt++)
                        mma16(acc[mt][nt], a[mt], bb.x, bb.y);
                }
            }
        }
        // epilogue: (mu, ls) pairs -> z, kl
        #pragma unroll
        for (int mt = 0; mt < 2; mt++)
            #pragma unroll
            for (int nt = 0; nt < 8; nt++)
                #pragma unroll
                for (int pp = 0; pp < 2; pp++) {
                    int j = bx * 128 + wn * 32 + nt * 4 + (lane & 3);
                    int row = wm * 32 + mt * 16 + (lane >> 2) + 8 * pp;
                    if (row < 50) {
                        float mu  = acc[mt][nt][2 * pp]     + be2s[j];
                        float lsr = acc[mt][nt][2 * pp + 1] + be2s[512 + j];
                        float lsc = fminf(fmaxf(lsr, -10.f), 10.f);
                        float sd = expf(lsc);
                        size_t grow = (size_t)b * SK + row;
                        out[OFF_Z + grow * IB + j] = mu + sd * eps[grow * IB + j];
                        kl += mu * mu + sd * sd - 1.0f - 2.0f * lsr;
                    }
                }
    }
    #pragma unroll
    for (int off = 16; off; off >>= 1) kl += __shfl_down_sync(0xffffffffu, kl, off);
    if (lane == 0) redp[w] = kl;
    __syncthreads();
    if (tid == 0) {
        float s = 0.f;
        #pragma unroll
        for (int ww = 0; ww < 8; ww++) s += redp[ww];
        g_klblk[b * 4 + bx] = 0.5f * s;
    }
}

// ===================== kl finalize =====================
__global__ void klfinal_kernel(float* __restrict__ out) {
    const int tid = threadIdx.x;   // 128
    __shared__ float redp[4];
    float s = g_klblk[tid];
    #pragma unroll
    for (int off = 16; off; off >>= 1) s += __shfl_down_sync(0xffffffffu, s, off);
    if ((tid & 31) == 0) redp[tid >> 5] = s;
    __syncthreads();
    if (tid == 0)
        out[OFF_KL] = ((redp[0] + redp[1] + redp[2] + redp[3]) / (float)(BB * SK)) * 0.001f;
}

// ===================== launch =====================
extern "C" void kernel_launch(void* const* d_in, const int* in_sizes, int n_in,
                              void* d_out, int out_size) {
    const float* query = (const float*)d_in[0];
    const float* cand  = (const float*)d_in[1];
    const float* score = (const float*)d_in[2];
    const float* gum   = (const float*)d_in[3];
    const float* eps   = (const float*)d_in[4];
    const float* W1    = (const float*)d_in[5];
    const float* b1    = (const float*)d_in[6];
    const float* W2    = (const float*)d_in[7];
    const float* b2    = (const float*)d_in[8];
    const float* We1   = (const float*)d_in[9];
    const float* be1   = (const float*)d_in[10];
    const float* We2   = (const float*)d_in[11];
    const float* be2   = (const float*)d_in[12];
    float* out = (float*)d_out;

    static int attr_set = 0;
    if (!attr_set) {
        cudaFuncSetAttribute(logits_mma_kernel,
                             cudaFuncAttributeMaxDynamicSharedMemorySize, SM_DYN);
        cudaFuncSetAttribute(encoder_kernel,
                             cudaFuncAttributeMaxDynamicSharedMemorySize, ENC_SMEM);
        attr_set = 1;
    }

    prep_kernel<<<NZB + 256 + 96 + 512 + 2048, 256>>>(out, (size_t)out_size,
                                                      W1, query, We1, We2);
    logits_mma_kernel<<<dim3(KK / 64, BB), 256, SM_DYN>>>(cand, b1, W2, b2, gum);
    topk_kernel<<<BB, 1024>>>(score, out);
    encoder_kernel<<<dim3(4, BB), 256, ENC_SMEM>>>(cand, be1, be2, eps, out);
    klfinal_kernel<<<1, 128>>>(out);
}

// round 9
// speedup vs baseline: 6.5256x; 1.0318x over previous
#include <cuda_runtime.h>
#include <cuda_fp16.h>
#include <math.h>
#include <stdint.h>

#define BB 32
#define KK 8192
#define DC 256
#define DQ 256
#define HID 256
#define SK 50
#define IB 512
#define EH 512

// ---- output layout (f32, tuple concatenated) ----
#define OFF_Z    0ull
#define OFF_SEL  819200ull
#define OFF_KL   13926400ull
#define OFF_HARD 13926401ull
#define OFF_SSC  27033601ull
#define OFF_SRS  27035201ull

// ---- scratch ----
__device__ float g_logits[BB * KK];
__device__ float g_sel[BB * KK];
__device__ float g_qW1[BB * HID];
__device__ float g_qWe1[BB * EH];
__device__ int   g_topk[BB * SK];
// W1^T fp16 fragment-permuted (for logits): 8 chunks(32k) x 1024 uint4
__device__ __align__(16) uint4 g_Bp[8 * 1024];
// We1^T fp16 fragment-permuted: 8 k-chunks x 64 ntiles x 2 x 32 x 4 halves
__device__ __align__(16) __half g_We1p[131072];
// We2^T fp16 fragment-permuted + mu/ls column interleave: 16 k-chunks x 128 ntiles
__device__ __align__(16) __half g_We2p[524288];

// ===================== helpers =====================
__device__ __forceinline__ uint32_t h2u(__half2 h) {
    return *reinterpret_cast<uint32_t*>(&h);
}
__device__ __forceinline__ uint32_t smem_u32(const void* p) {
    uint32_t a;
    asm("{ .reg .u64 t; cvta.to.shared.u64 t, %1; cvt.u32.u64 %0, t; }" : "=r"(a) : "l"(p));
    return a;
}
__device__ __forceinline__ void mma16(float* c, const uint4& a, uint32_t b0, uint32_t b1) {
    asm volatile(
        "mma.sync.aligned.m16n8k16.row.col.f32.f16.f16.f32 "
        "{%0,%1,%2,%3},{%4,%5,%6,%7},{%8,%9},{%0,%1,%2,%3};"
        : "+f"(c[0]), "+f"(c[1]), "+f"(c[2]), "+f"(c[3])
        : "r"(a.x), "r"(a.y), "r"(a.z), "r"(a.w), "r"(b0), "r"(b1));
}
__device__ __forceinline__ void cp16(uint32_t dst, const void* src) {
    asm volatile("cp.async.cg.shared.global [%0], [%1], 16;" :: "r"(dst), "l"(src));
}
#define CP_COMMIT() asm volatile("cp.async.commit_group;" ::: "memory")
#define CP_WAIT0()  asm volatile("cp.async.wait_group 0;" ::: "memory")
#define CP_WAIT2()  asm volatile("cp.async.wait_group 2;" ::: "memory")

// A-fragment load from row-major fp16 smem (stride in halves)
__device__ __forceinline__ uint4 ldsA(const __half* A, int stride, int rb, int kb, int lane) {
    const __half* p0 = A + (rb + (lane >> 2)) * stride + kb + (lane & 3) * 2;
    uint4 a;
    a.x = *reinterpret_cast<const uint32_t*>(p0);
    a.y = *reinterpret_cast<const uint32_t*>(p0 + 8 * stride);
    a.z = *reinterpret_cast<const uint32_t*>(p0 + 8);
    a.w = *reinterpret_cast<const uint32_t*>(p0 + 8 * stride + 8);
    return a;
}

// ===================== prep: permutes + qproj (no zeroing here) =====================
__global__ void __launch_bounds__(256)
prep_kernel(const float* __restrict__ W1,
            const float* __restrict__ q,
            const float* __restrict__ We1,
            const float* __restrict__ We2) {
    int blk = blockIdx.x, tid = threadIdx.x;
    if (blk < 256) {   // W1 -> permuted fp16 fragments for logits
        int idx = blk * 256 + tid;
        int k = idx >> 8, n2 = idx & 255;
        float x = W1[(size_t)k * HID + n2];
        int c = k >> 5, kp = k & 31;
        int ntile = n2 >> 3, g = n2 & 7;
        int ktile = kp >> 4;
        int lane = g * 4 + ((kp & 7) >> 1);
        int pos = (kp & 1) + 2 * ((kp & 15) >> 3);
        size_t off = (size_t)c * 8192 +
                     (size_t)(((ntile * 2 + ktile) * 32 + lane) * 4 + pos);
        reinterpret_cast<__half*>(g_Bp)[off] = __float2half_rn(x);
        return;
    }
    blk -= 256;
    if (blk < 96) {    // qproj: 3 per batch
        int sub = blk % 3, b = blk / 3;
        __shared__ float qs[DQ];
        qs[tid] = q[b * DQ + tid];
        __syncthreads();
        float s = 0.f;
        if (sub == 0) {
            #pragma unroll 8
            for (int d = 0; d < DQ; d++) s += qs[d] * W1[(size_t)(DC + d) * HID + tid];
            g_qW1[b * HID + tid] = s;
        } else {
            int c0 = (sub - 1) * 256 + tid;
            #pragma unroll 8
            for (int d = 0; d < DQ; d++) s += qs[d] * We1[(size_t)(DC + d) * EH + c0];
            g_qWe1[b * EH + c0] = s;
        }
        return;
    }
    blk -= 96;
    if (blk < 512) {   // We1^T (first 256 rows) -> permuted fp16
        int idx = blk * 256 + tid;        // [0, 131072)
        int k = idx >> 9, n2 = idx & 511;
        float x = We1[(size_t)k * EH + n2];
        int c = k >> 5, kp = k & 31;
        int ntile = n2 >> 3, g = n2 & 7;
        int ktile = kp >> 4;
        int lane = g * 4 + ((kp & 7) >> 1);
        int pos = (kp & 1) + 2 * ((kp & 15) >> 3);
        g_We1p[(((c * 64 + ntile) * 2 + ktile) * 32 + lane) * 4 + pos] = __float2half_rn(x);
        return;
    }
    blk -= 512;        // We2^T col-interleaved -> permuted fp16 (2048 blocks)
    {
        int idx = blk * 256 + tid;        // [0, 524288)
        int k = idx >> 10, n2 = idx & 1023;
        float x = We2[(size_t)k * (2 * IB) + n2];
        int pcol = (n2 < 512) ? (2 * n2) : (2 * (n2 - 512) + 1);
        int c = k >> 5, kp = k & 31;
        int ntile = pcol >> 3, g = pcol & 7;
        int ktile = kp >> 4;
        int lane = g * 4 + ((kp & 7) >> 1);
        int pos = (kp & 1) + 2 * ((kp & 15) >> 3);
        g_We2p[(((c * 128 + ntile) * 2 + ktile) * 32 + lane) * 4 + pos] = __float2half_rn(x);
    }
}

// ===================== scorer logits: fp16 2-pass + fused output zeroing =====================
#define SAH 0
#define SAL 8192
#define SB  16384
#define STAGE_B 49152
#define SM_DYN (2 * STAGE_B)

struct PrefA { float4 a[4]; };

__device__ __forceinline__ void load_prefA(PrefA& p, const float* __restrict__ cand,
                                           int b, int k0, int c, int tid) {
    #pragma unroll
    for (int t = 0; t < 4; t++) {
        int idx = tid + t * 256;
        int m = idx >> 4, k4 = idx & 15;
        p.a[t] = *reinterpret_cast<const float4*>(
            &cand[((size_t)b * KK + k0 + m) * DC + c * 64 + k4 * 4]);
    }
}

__device__ __forceinline__ void cp_asyncB(uint32_t stb, int c, int tid) {
    #pragma unroll
    for (int t = 0; t < 8; t++) {
        int idx = tid + t * 256;
        int sub = idx >> 10, j = idx & 1023;
        cp16(stb + SB + sub * 16384 + j * 16, &g_Bp[(c * 2 + sub) * 1024 + j]);
    }
}

__device__ __forceinline__ void store_stageA(char* __restrict__ st, const PrefA& p, int tid) {
    #pragma unroll
    for (int t = 0; t < 4; t++) {
        int idx = tid + t * 256;
        int m = idx >> 4, k4 = idx & 15;
        int sub = k4 >> 3, k4in = k4 & 7;
        float4 v = p.a[t];
        __half hx = __float2half_rn(v.x), hy = __float2half_rn(v.y);
        __half hz = __float2half_rn(v.z), hw = __float2half_rn(v.w);
        uint32_t h01 = h2u(__halves2half2(hx, hy));
        uint32_t h23 = h2u(__halves2half2(hz, hw));
        uint32_t l01 = h2u(__halves2half2(__float2half_rn(v.x - __half2float(hx)),
                                          __float2half_rn(v.y - __half2float(hy))));
        uint32_t l23 = h2u(__halves2half2(__float2half_rn(v.z - __half2float(hz)),
                                          __float2half_rn(v.w - __half2float(hw))));
        int mtile = m >> 4, r = m & 15;
        int ktile = k4in >> 2;
        int lane0 = (r & 7) * 4 + (k4in & 1) * 2;
        int boff = 2 * ((r >> 3) & 1) + 4 * ((k4in >> 1) & 1);
        int base = sub * 4096 + ((mtile * 2 + ktile) * 32) * 16 + boff * 2;
        *reinterpret_cast<uint32_t*>(st + SAH + base + lane0 * 16)       = h01;
        *reinterpret_cast<uint32_t*>(st + SAH + base + (lane0 + 1) * 16) = h23;
        *reinterpret_cast<uint32_t*>(st + SAL + base + lane0 * 16)       = l01;
        *reinterpret_cast<uint32_t*>(st + SAL + base + (lane0 + 1) * 16) = l23;
    }
}

__device__ __forceinline__ void compute_sub(const char* __restrict__ st, int sub,
                                            float acc[2][8][4],
                                            int wm, int wn, int lane) {
    #pragma unroll
    for (int kt = 0; kt < 2; kt++) {
        uint4 ah[2], al[2];
        #pragma unroll
        for (int mt = 0; mt < 2; mt++) {
            int off = sub * 4096 + (((wm * 2 + mt) * 2 + kt) * 32 + lane) * 16;
            ah[mt] = *reinterpret_cast<const uint4*>(st + SAH + off);
            al[mt] = *reinterpret_cast<const uint4*>(st + SAL + off);
        }
        #pragma unroll
        for (int nt = 0; nt < 8; nt++) {
            int ntile = wn * 8 + nt;
            int boff = sub * 16384 + ((ntile * 2 + kt) * 32 + lane) * 8;
            uint2 bb = *reinterpret_cast<const uint2*>(st + SB + boff);
            #pragma unroll
            for (int mt = 0; mt < 2; mt++) {
                mma16(acc[mt][nt], ah[mt], bb.x, bb.y);
                mma16(acc[mt][nt], al[mt], bb.x, bb.y);
            }
        }
    }
}

__global__ void __launch_bounds__(256, 2)
logits_mma_kernel(const float* __restrict__ cand,
                  const float* __restrict__ b1,
                  const float* __restrict__ W2,
                  const float* __restrict__ b2,
                  const float* __restrict__ gum,
                  float* __restrict__ out) {
    extern __shared__ char dsm[];
    __shared__ float qb_s[HID];
    __shared__ float w2_s[HID];
    __shared__ float part[64][4];

    const int tid = threadIdx.x;
    const int b = blockIdx.y;
    const int k0 = blockIdx.x * 64;
    const int w = tid >> 5, lane = tid & 31;
    const int wm = w & 1, wn = w >> 1;
    const uint32_t sb = smem_u32(dsm);

    // ---- fused zeroing of SEL + KL + HARD (26214401 floats from 819200) ----
    {
        int bid = blockIdx.y * gridDim.x + blockIdx.x;      // 0..4095
        float4* oz = reinterpret_cast<float4*>(out) + 204800 + (size_t)bid * 1600;
        float4 z4 = make_float4(0.f, 0.f, 0.f, 0.f);
        #pragma unroll
        for (int t = tid; t < 1600; t += 256) oz[t] = z4;
        if (bid == 0 && tid == 0) out[27033600] = 0.f;      // scalar tail
    }

    qb_s[tid] = g_qW1[b * HID + tid] + b1[tid];
    w2_s[tid] = W2[tid];

    float acc[2][8][4];
    #pragma unroll
    for (int mt = 0; mt < 2; mt++)
        #pragma unroll
        for (int nt = 0; nt < 8; nt++)
            #pragma unroll
            for (int r = 0; r < 4; r++) acc[mt][nt][r] = 0.f;

    PrefA p;
    load_prefA(p, cand, b, k0, 0, tid);
    cp_asyncB(sb, 0, tid);
    CP_COMMIT();
    store_stageA(dsm, p, tid);
    CP_WAIT0();
    __syncthreads();

    #pragma unroll
    for (int c = 0; c < 4; c++) {
        if (c < 3) {
            load_prefA(p, cand, b, k0, c + 1, tid);
            cp_asyncB(sb + ((c + 1) & 1) * STAGE_B, c + 1, tid);
            CP_COMMIT();
        }
        compute_sub(dsm + (c & 1) * STAGE_B, 0, acc, wm, wn, lane);
        if (c < 3) store_stageA(dsm + ((c + 1) & 1) * STAGE_B, p, tid);
        compute_sub(dsm + (c & 1) * STAGE_B, 1, acc, wm, wn, lane);
        CP_WAIT0();
        __syncthreads();
    }

    float rs[2][2] = {{0.f, 0.f}, {0.f, 0.f}};
    #pragma unroll
    for (int mt = 0; mt < 2; mt++)
        #pragma unroll
        for (int nt = 0; nt < 8; nt++)
            #pragma unroll
            for (int ci = 0; ci < 4; ci++) {
                int col = wn * 64 + nt * 8 + (lane & 3) * 2 + (ci & 1);
                float v = acc[mt][nt][ci] + qb_s[col];
                rs[mt][ci >> 1] += fmaxf(v, 0.f) * w2_s[col];
            }
    #pragma unroll
    for (int mt = 0; mt < 2; mt++)
        #pragma unroll
        for (int rh = 0; rh < 2; rh++) {
            float s = rs[mt][rh];
            s += __shfl_xor_sync(0xffffffffu, s, 1);
            s += __shfl_xor_sync(0xffffffffu, s, 2);
            if ((lane & 3) == 0)
                part[wm * 32 + mt * 16 + rh * 8 + (lane >> 2)][wn] = s;
        }
    __syncthreads();
    if (tid < 64) {
        float lg = part[tid][0] + part[tid][1] + part[tid][2] + part[tid][3] + b2[0];
        size_t gi = (size_t)b * KK + k0 + tid;
        g_logits[gi] = lg;
        g_sel[gi] = lg + gum[gi];
    }
}

// ===================== top-k via 4-level radix select =====================
__global__ void __launch_bounds__(1024)
topk_kernel(const float* __restrict__ cand_score, float* __restrict__ out) {
    const int b = blockIdx.x;
    const int tid = threadIdx.x;
    const int base = tid * 8;

    __shared__ uint32_t hist8[8][256];
    __shared__ uint32_t shist[256];
    __shared__ uint32_t s_prefix, s_above;
    __shared__ uint32_t cntG, cntE;
    __shared__ uint32_t gk[64];
    __shared__ int      gi[64];
    __shared__ int      ei[256];

    uint32_t k[8];
    #pragma unroll
    for (int r = 0; r < 8; r++) {
        uint32_t u = __float_as_uint(g_sel[(size_t)b * KK + base + r]);
        k[r] = (u & 0x80000000u) ? ~u : (u | 0x80000000u);
    }
    if (tid == 0) { s_prefix = 0; s_above = 0; cntG = 0; cntE = 0; }

    #pragma unroll
    for (int round = 0; round < 4; round++) {
        const int shift = 24 - round * 8;
        if (round == 0) {
            #pragma unroll
            for (int t = 0; t < 2; t++) hist8[(tid + t * 1024) >> 8][(tid + t * 1024) & 255] = 0;
        } else if (tid < 256) shist[tid] = 0;
        __syncthreads();
        uint32_t pfx = s_prefix;
        if (round == 0) {
            uint32_t* hh = hist8[(tid >> 5) & 7];
            #pragma unroll
            for (int r = 0; r < 8; r++) atomicAdd(&hh[k[r] >> 24], 1u);
        } else {
            const int ps = shift + 8;
            #pragma unroll
            for (int r = 0; r < 8; r++)
                if ((k[r] >> ps) == (pfx >> ps))
                    atomicAdd(&shist[(k[r] >> shift) & 255u], 1u);
        }
        __syncthreads();
        if (round == 0 && tid < 256) {
            uint32_t s = 0;
            #pragma unroll
            for (int g = 0; g < 8; g++) s += hist8[g][tid];
            shist[tid] = s;
        }
        if (round == 0) __syncthreads();
        if (tid < 32) {
            uint32_t loc[8], tot = 0;
            #pragma unroll
            for (int j = 0; j < 8; j++) { loc[j] = shist[tid * 8 + j]; tot += loc[j]; }
            uint32_t suf = tot;
            #pragma unroll
            for (int off = 1; off < 32; off <<= 1) {
                uint32_t v = __shfl_down_sync(0xffffffffu, suf, off);
                if (tid + off < 32) suf += v;
            }
            uint32_t exclHi = suf - tot;
            uint32_t target = 50u - s_above;
            bool has = (exclHi < target) && (exclHi + tot >= target);
            if (has) {
                uint32_t c = exclHi;
                #pragma unroll
                for (int j = 7; j >= 0; j--) {
                    uint32_t nc = c + loc[j];
                    if (nc >= target) {
                        s_prefix = pfx | ((uint32_t)(tid * 8 + j) << shift);
                        s_above += c;
                        break;
                    }
                    c = nc;
                }
            }
        }
        __syncthreads();
    }

    const uint32_t T50 = s_prefix;
    const uint32_t C1 = s_above;
    const int E = 50 - (int)C1;

    #pragma unroll
    for (int r = 0; r < 8; r++) {
        if (k[r] > T50) {
            uint32_t pos = atomicAdd(&cntG, 1u);
            gk[pos] = k[r]; gi[pos] = base + r;
        } else if (k[r] == T50) {
            uint32_t pos = atomicAdd(&cntE, 1u);
            if (pos < 256) ei[pos] = base + r;
        }
    }
    __syncthreads();

    if (tid < (int)C1) {
        uint32_t mk = gk[tid]; int mi = gi[tid];
        int rank = 0;
        for (int j = 0; j < (int)C1; j++)
            if (gk[j] > mk || (gk[j] == mk && gi[j] < mi)) rank++;
        int row = b * SK + rank;
        g_topk[row] = mi;
        out[OFF_SSC + row] = g_logits[(size_t)b * KK + mi];
        out[OFF_SRS + row] = cand_score[(size_t)b * KK + mi];
        out[OFF_SEL + (size_t)row * KK + mi] = 1.0f;
        out[OFF_HARD + (size_t)row * KK + mi] = 1.0f;
    }
    int nE = (int)cntE; if (nE > 256) nE = 256;
    if (tid < nE) {
        int mi = ei[tid];
        int rank = 0;
        for (int j = 0; j < nE; j++) if (ei[j] < mi) rank++;
        if (rank < E) {
            int row = b * SK + (int)C1 + rank;
            g_topk[row] = mi;
            out[OFF_SSC + row] = g_logits[(size_t)b * KK + mi];
            out[OFF_SRS + row] = cand_score[(size_t)b * KK + mi];
            out[OFF_SEL + (size_t)row * KK + mi] = 1.0f;
            out[OFF_HARD + (size_t)row * KK + mi] = 1.0f;
        }
    }
}

// ===================== encoder: fused fp16 TC, 4-slot cp.async ring =====================
#define EST 264            // A1 row stride (halves)
#define HST 520            // HE row stride (halves)
#define O_A1 0
#define O_HE 33792
#define O_QB 100352
#define O_BE2 102400
#define O_BUF 106496
#define ENC_SMEM (O_BUF + 4 * 16384)   // 172032

__device__ __forceinline__ void cp_slice(uint32_t dst, const char* src, int tid) {
    #pragma unroll
    for (int t = 0; t < 4; t++) {
        int i = (tid + t * 256) * 16;
        cp16(dst + i, src + i);
    }
}

__global__ void __launch_bounds__(256, 1)
encoder_kernel(const float* __restrict__ cand,
               const float* __restrict__ be1,
               const float* __restrict__ be2,
               const float* __restrict__ eps,
               float* __restrict__ out) {
    extern __shared__ char esm[];
    __half* A1  = reinterpret_cast<__half*>(esm + O_A1);
    __half* HE  = reinterpret_cast<__half*>(esm + O_HE);
    float* qb1  = reinterpret_cast<float*>(esm + O_QB);
    float* be2s = reinterpret_cast<float*>(esm + O_BE2);
    char* BUF = esm + O_BUF;
    const uint32_t bufu = smem_u32(BUF);
    __shared__ int idxs[64];
    __shared__ float redp[8];

    const int tid = threadIdx.x;
    const int b = blockIdx.y;
    const int bx = blockIdx.x;              // N-quarter of GEMM2
    const int w = tid >> 5, lane = tid & 31;
    const int wm = w & 1, wn = w >> 1;

    if (tid < 64) idxs[tid] = (tid < 50) ? g_topk[b * SK + tid] : 0;
    qb1[tid]       = g_qWe1[b * EH + tid] + be1[tid];
    qb1[tid + 256] = g_qWe1[b * EH + tid + 256] + be1[tid + 256];
    #pragma unroll
    for (int t = 0; t < 4; t++) be2s[tid + t * 256] = be2[tid + t * 256];
    __syncthreads();

    // gather selected rows -> A1 fp16 (rows 50..63 zero)
    #pragma unroll
    for (int t = 0; t < 16; t++) {
        int idx = tid + t * 256;
        int r = idx >> 6, k4 = idx & 63;
        uint2 u; u.x = 0u; u.y = 0u;
        if (r < 50) {
            float4 v = *reinterpret_cast<const float4*>(
                &cand[((size_t)b * KK + idxs[r]) * DC + k4 * 4]);
            u.x = h2u(__halves2half2(__float2half_rn(v.x), __float2half_rn(v.y)));
            u.y = h2u(__halves2half2(__float2half_rn(v.z), __float2half_rn(v.w)));
        }
        *reinterpret_cast<uint2*>(&A1[r * EST + k4 * 4]) = u;
    }
    __syncthreads();

    const char* we1p = reinterpret_cast<const char*>(g_We1p);
    const char* we2p = reinterpret_cast<const char*>(g_We2p);
    // chunk i source: i<16 -> GEMM1 (np=i>>3, kc=i&7); i>=16 -> GEMM2 chunk i-16
    #define ENC_SRC(i) ((i) < 16 \
        ? we1p + (size_t)((i) & 7) * 32768 + ((i) >> 3) * 16384 \
        : we2p + (size_t)((i) - 16) * 65536 + bx * 16384)

    // prologue: 3-deep lookahead
    cp_slice(bufu + 0 * 16384, ENC_SRC(0), tid); CP_COMMIT();
    cp_slice(bufu + 1 * 16384, ENC_SRC(1), tid); CP_COMMIT();
    cp_slice(bufu + 2 * 16384, ENC_SRC(2), tid); CP_COMMIT();

    float acc[2][8][4];
    float kl = 0.f;

    for (int i = 0; i < 32; i++) {
        if (i == 0 || i == 8 || i == 16) {
            #pragma unroll
            for (int mt = 0; mt < 2; mt++)
                #pragma unroll
                for (int nt = 0; nt < 8; nt++)
                    #pragma unroll
                    for (int r = 0; r < 4; r++) acc[mt][nt][r] = 0.f;
        }
        CP_WAIT2();            // chunk i landed (pending kept at 3 via empty commits)
        __syncthreads();
        if (i + 3 < 32) cp_slice(bufu + ((i + 3) & 3) * 16384, ENC_SRC(i + 3), tid);
        CP_COMMIT();           // empty group at tail keeps the count uniform

        const char* bs = BUF + (i & 3) * 16384;
        const __half* Ap = (i < 16) ? A1 : HE;
        const int stride = (i < 16) ? EST : HST;
        const int kb = (i < 16) ? (i & 7) * 32 : (i - 16) * 32;
        #pragma unroll
        for (int kt = 0; kt < 2; kt++) {
            uint4 a[2];
            #pragma unroll
            for (int mt = 0; mt < 2; mt++)
                a[mt] = ldsA(Ap, stride, wm * 32 + mt * 16, kb + kt * 16, lane);
            #pragma unroll
            for (int nt = 0; nt < 8; nt++) {
                int ntl = wn * 8 + nt;
                uint2 bb = *reinterpret_cast<const uint2*>(bs + ((ntl * 2 + kt) * 32 + lane) * 8);
                #pragma unroll
                for (int mt = 0; mt < 2; mt++)
                    mma16(acc[mt][nt], a[mt], bb.x, bb.y);
            }
        }

        if (i == 7 || i == 15) {           // GEMM1 epilogue for pass np=i>>3
            int np = i >> 3;
            #pragma unroll
            for (int mt = 0; mt < 2; mt++)
                #pragma unroll
                for (int nt = 0; nt < 8; nt++)
                    #pragma unroll
                    for (int pp = 0; pp < 2; pp++) {
                        int col = np * 256 + wn * 64 + nt * 8 + (lane & 3) * 2;
                        int row = wm * 32 + mt * 16 + (lane >> 2) + 8 * pp;
                        float v0 = fmaxf(acc[mt][nt][2 * pp]     + qb1[col],     0.f);
                        float v1 = fmaxf(acc[mt][nt][2 * pp + 1] + qb1[col + 1], 0.f);
                        *reinterpret_cast<uint32_t*>(&HE[row * HST + col]) =
                            h2u(__halves2half2(__float2half_rn(v0), __float2half_rn(v1)));
                    }
        }
    }
    // GEMM2 epilogue: (mu, ls) pairs -> z, kl
    #pragma unroll
    for (int mt = 0; mt < 2; mt++)
        #pragma unroll
        for (int nt = 0; nt < 8; nt++)
            #pragma unroll
            for (int pp = 0; pp < 2; pp++) {
                int j = bx * 128 + wn * 32 + nt * 4 + (lane & 3);
                int row = wm * 32 + mt * 16 + (lane >> 2) + 8 * pp;
                if (row < 50) {
                    float mu  = acc[mt][nt][2 * pp]     + be2s[j];
                    float lsr = acc[mt][nt][2 * pp + 1] + be2s[512 + j];
                    float lsc = fminf(fmaxf(lsr, -10.f), 10.f);
                    float sd = expf(lsc);
                    size_t grow = (size_t)b * SK + row;
                    out[OFF_Z + grow * IB + j] = mu + sd * eps[grow * IB + j];
                    kl += mu * mu + sd * sd - 1.0f - 2.0f * lsr;
                }
            }
    #pragma unroll
    for (int off = 16; off; off >>= 1) kl += __shfl_down_sync(0xffffffffu, kl, off);
    if (lane == 0) redp[w] = kl;
    __syncthreads();
    if (tid == 0) {
        float s = 0.f;
        #pragma unroll
        for (int ww = 0; ww < 8; ww++) s += redp[ww];
        atomicAdd(&out[OFF_KL], 0.5f * s * (0.001f / (float)(BB * SK)));
    }
}

// ===================== launch =====================
extern "C" void kernel_launch(void* const* d_in, const int* in_sizes, int n_in,
                              void* d_out, int out_size) {
    const float* query = (const float*)d_in[0];
    const float* cand  = (const float*)d_in[1];
    const float* score = (const float*)d_in[2];
    const float* gum   = (const float*)d_in[3];
    const float* eps   = (const float*)d_in[4];
    const float* W1    = (const float*)d_in[5];
    const float* b1    = (const float*)d_in[6];
    const float* W2    = (const float*)d_in[7];
    const float* b2    = (const float*)d_in[8];
    const float* We1   = (const float*)d_in[9];
    const float* be1   = (const float*)d_in[10];
    const float* We2   = (const float*)d_in[11];
    const float* be2   = (const float*)d_in[12];
    float* out = (float*)d_out;

    static int attr_set = 0;
    if (!attr_set) {
        cudaFuncSetAttribute(logits_mma_kernel,
                             cudaFuncAttributeMaxDynamicSharedMemorySize, SM_DYN);
        cudaFuncSetAttribute(encoder_kernel,
                             cudaFuncAttributeMaxDynamicSharedMemorySize, ENC_SMEM);
        attr_set = 1;
    }

    prep_kernel<<<256 + 96 + 512 + 2048, 256>>>(W1, query, We1, We2);
    logits_mma_kernel<<<dim3(KK / 64, BB), 256, SM_DYN>>>(cand, b1, W2, b2, gum, out);
    topk_kernel<<<BB, 1024>>>(score, out);
    encoder_kernel<<<dim3(4, BB), 256, ENC_SMEM>>>(cand, be1, be2, eps, out);
}

// round 10
// speedup vs baseline: 6.6522x; 1.0194x over previous
#include <cuda_runtime.h>
#include <cuda_fp16.h>
#include <math.h>
#include <stdint.h>

#define BB 32
#define KK 8192
#define DC 256
#define DQ 256
#define HID 256
#define SK 50
#define IB 512
#define EH 512

// ---- output layout (f32, tuple concatenated) ----
#define OFF_Z    0ull
#define OFF_SEL  819200ull
#define OFF_KL   13926400ull
#define OFF_HARD 13926401ull
#define OFF_SSC  27033601ull
#define OFF_SRS  27035201ull

// ---- scratch ----
__device__ float g_logits[BB * KK];
__device__ float g_sel[BB * KK];
__device__ float g_qW1[BB * HID];
__device__ float g_qWe1[BB * EH];
__device__ int   g_topk[BB * SK];
// W1^T fp16 fragment-permuted (for logits): 8 chunks(32k) x 1024 uint4
__device__ __align__(16) uint4 g_Bp[8 * 1024];
// We1^T fp16 fragment-permuted: 131072 halves
__device__ __align__(16) __half g_We1p[131072];
// We2^T fp16 fragment-permuted + mu/ls column interleave: 524288 halves
__device__ __align__(16) __half g_We2p[524288];

// ===================== helpers =====================
__device__ __forceinline__ uint32_t h2u(__half2 h) {
    return *reinterpret_cast<uint32_t*>(&h);
}
__device__ __forceinline__ uint32_t smem_u32(const void* p) {
    uint32_t a;
    asm("{ .reg .u64 t; cvta.to.shared.u64 t, %1; cvt.u32.u64 %0, t; }" : "=r"(a) : "l"(p));
    return a;
}
__device__ __forceinline__ void mma16(float* c, const uint4& a, uint32_t b0, uint32_t b1) {
    asm volatile(
        "mma.sync.aligned.m16n8k16.row.col.f32.f16.f16.f32 "
        "{%0,%1,%2,%3},{%4,%5,%6,%7},{%8,%9},{%0,%1,%2,%3};"
        : "+f"(c[0]), "+f"(c[1]), "+f"(c[2]), "+f"(c[3])
        : "r"(a.x), "r"(a.y), "r"(a.z), "r"(a.w), "r"(b0), "r"(b1));
}
__device__ __forceinline__ void cp16(uint32_t dst, const void* src) {
    asm volatile("cp.async.cg.shared.global [%0], [%1], 16;" :: "r"(dst), "l"(src));
}
#define CP_COMMIT() asm volatile("cp.async.commit_group;" ::: "memory")
#define CP_WAIT0()  asm volatile("cp.async.wait_group 0;" ::: "memory")

// A-fragment load from row-major fp16 smem (stride in halves)
__device__ __forceinline__ uint4 ldsA(const __half* A, int stride, int rb, int kb, int lane) {
    const __half* p0 = A + (rb + (lane >> 2)) * stride + kb + (lane & 3) * 2;
    uint4 a;
    a.x = *reinterpret_cast<const uint32_t*>(p0);
    a.y = *reinterpret_cast<const uint32_t*>(p0 + 8 * stride);
    a.z = *reinterpret_cast<const uint32_t*>(p0 + 8);
    a.w = *reinterpret_cast<const uint32_t*>(p0 + 8 * stride + 8);
    return a;
}
// B-fragment direct from permuted gmem: frag = 128 halves, lane owns 4
__device__ __forceinline__ uint2 ldgB(const __half* __restrict__ base,
                                      int fragIdx, int lane) {
    return *reinterpret_cast<const uint2*>(base + (size_t)fragIdx * 128 + lane * 4);
}

// ===================== prep: W1 permute + qproj only =====================
__global__ void __launch_bounds__(256)
prep_kernel(const float* __restrict__ W1,
            const float* __restrict__ q,
            const float* __restrict__ We1) {
    int blk = blockIdx.x, tid = threadIdx.x;
    if (blk < 256) {   // W1 -> permuted fp16 fragments for logits
        int idx = blk * 256 + tid;
        int k = idx >> 8, n2 = idx & 255;
        float x = W1[(size_t)k * HID + n2];
        int c = k >> 5, kp = k & 31;
        int ntile = n2 >> 3, g = n2 & 7;
        int ktile = kp >> 4;
        int lane = g * 4 + ((kp & 7) >> 1);
        int pos = (kp & 1) + 2 * ((kp & 15) >> 3);
        size_t off = (size_t)c * 8192 +
                     (size_t)(((ntile * 2 + ktile) * 32 + lane) * 4 + pos);
        reinterpret_cast<__half*>(g_Bp)[off] = __float2half_rn(x);
        return;
    }
    blk -= 256;        // qproj: 3 per batch (96 blocks)
    int sub = blk % 3, b = blk / 3;
    __shared__ float qs[DQ];
    qs[tid] = q[b * DQ + tid];
    __syncthreads();
    float s = 0.f;
    if (sub == 0) {
        #pragma unroll 8
        for (int d = 0; d < DQ; d++) s += qs[d] * W1[(size_t)(DC + d) * HID + tid];
        g_qW1[b * HID + tid] = s;
    } else {
        int c0 = (sub - 1) * 256 + tid;
        #pragma unroll 8
        for (int d = 0; d < DQ; d++) s += qs[d] * We1[(size_t)(DC + d) * EH + c0];
        g_qWe1[b * EH + c0] = s;
    }
}

// ===================== scorer logits: fp16 2-pass + fused zero + We permutes =====================
#define SAH 0
#define SAL 8192
#define SB  16384
#define STAGE_B 49152
#define SM_DYN (2 * STAGE_B)

struct PrefA { float4 a[4]; };

__device__ __forceinline__ void load_prefA(PrefA& p, const float* __restrict__ cand,
                                           int b, int k0, int c, int tid) {
    #pragma unroll
    for (int t = 0; t < 4; t++) {
        int idx = tid + t * 256;
        int m = idx >> 4, k4 = idx & 15;
        p.a[t] = *reinterpret_cast<const float4*>(
            &cand[((size_t)b * KK + k0 + m) * DC + c * 64 + k4 * 4]);
    }
}

__device__ __forceinline__ void cp_asyncB(uint32_t stb, int c, int tid) {
    #pragma unroll
    for (int t = 0; t < 8; t++) {
        int idx = tid + t * 256;
        int sub = idx >> 10, j = idx & 1023;
        cp16(stb + SB + sub * 16384 + j * 16, &g_Bp[(c * 2 + sub) * 1024 + j]);
    }
}

__device__ __forceinline__ void store_stageA(char* __restrict__ st, const PrefA& p, int tid) {
    #pragma unroll
    for (int t = 0; t < 4; t++) {
        int idx = tid + t * 256;
        int m = idx >> 4, k4 = idx & 15;
        int sub = k4 >> 3, k4in = k4 & 7;
        float4 v = p.a[t];
        __half hx = __float2half_rn(v.x), hy = __float2half_rn(v.y);
        __half hz = __float2half_rn(v.z), hw = __float2half_rn(v.w);
        uint32_t h01 = h2u(__halves2half2(hx, hy));
        uint32_t h23 = h2u(__halves2half2(hz, hw));
        uint32_t l01 = h2u(__halves2half2(__float2half_rn(v.x - __half2float(hx)),
                                          __float2half_rn(v.y - __half2float(hy))));
        uint32_t l23 = h2u(__halves2half2(__float2half_rn(v.z - __half2float(hz)),
                                          __float2half_rn(v.w - __half2float(hw))));
        int mtile = m >> 4, r = m & 15;
        int ktile = k4in >> 2;
        int lane0 = (r & 7) * 4 + (k4in & 1) * 2;
        int boff = 2 * ((r >> 3) & 1) + 4 * ((k4in >> 1) & 1);
        int base = sub * 4096 + ((mtile * 2 + ktile) * 32) * 16 + boff * 2;
        *reinterpret_cast<uint32_t*>(st + SAH + base + lane0 * 16)       = h01;
        *reinterpret_cast<uint32_t*>(st + SAH + base + (lane0 + 1) * 16) = h23;
        *reinterpret_cast<uint32_t*>(st + SAL + base + lane0 * 16)       = l01;
        *reinterpret_cast<uint32_t*>(st + SAL + base + (lane0 + 1) * 16) = l23;
    }
}

__device__ __forceinline__ void compute_sub(const char* __restrict__ st, int sub,
                                            float acc[2][8][4],
                                            int wm, int wn, int lane) {
    #pragma unroll
    for (int kt = 0; kt < 2; kt++) {
        uint4 ah[2], al[2];
        #pragma unroll
        for (int mt = 0; mt < 2; mt++) {
            int off = sub * 4096 + (((wm * 2 + mt) * 2 + kt) * 32 + lane) * 16;
            ah[mt] = *reinterpret_cast<const uint4*>(st + SAH + off);
            al[mt] = *reinterpret_cast<const uint4*>(st + SAL + off);
        }
        #pragma unroll
        for (int nt = 0; nt < 8; nt++) {
            int ntile = wn * 8 + nt;
            int boff = sub * 16384 + ((ntile * 2 + kt) * 32 + lane) * 8;
            uint2 bb = *reinterpret_cast<const uint2*>(st + SB + boff);
            #pragma unroll
            for (int mt = 0; mt < 2; mt++) {
                mma16(acc[mt][nt], ah[mt], bb.x, bb.y);
                mma16(acc[mt][nt], al[mt], bb.x, bb.y);
            }
        }
    }
}

__global__ void __launch_bounds__(256, 2)
logits_mma_kernel(const float* __restrict__ cand,
                  const float* __restrict__ b1,
                  const float* __restrict__ W2,
                  const float* __restrict__ b2,
                  const float* __restrict__ gum,
                  const float* __restrict__ We1,
                  const float* __restrict__ We2,
                  float* __restrict__ out) {
    extern __shared__ char dsm[];
    __shared__ float qb_s[HID];
    __shared__ float w2_s[HID];
    __shared__ float part[64][4];

    const int tid = threadIdx.x;
    const int b = blockIdx.y;
    const int k0 = blockIdx.x * 64;
    const int w = tid >> 5, lane = tid & 31;
    const int wm = w & 1, wn = w >> 1;
    const uint32_t sb = smem_u32(dsm);
    const int bid = blockIdx.y * gridDim.x + blockIdx.x;    // 0..4095

    // ---- fused: zero SEL+KL+HARD, permute We1/We2 slices (160 elems/block) ----
    {
        float4* oz = reinterpret_cast<float4*>(out) + 204800 + (size_t)bid * 1600;
        float4 z4 = make_float4(0.f, 0.f, 0.f, 0.f);
        #pragma unroll
        for (int t = tid; t < 1600; t += 256) oz[t] = z4;
        if (bid == 0 && tid == 0) out[27033600] = 0.f;
        if (tid < 160) {
            int e = bid * 160 + tid;                        // 0..655359
            if (e < 131072) {
                int k = e >> 9, n2 = e & 511;
                float x = We1[(size_t)k * EH + n2];
                int c = k >> 5, kp = k & 31;
                int ntile = n2 >> 3, g = n2 & 7;
                int ktile = kp >> 4;
                int ln = g * 4 + ((kp & 7) >> 1);
                int pos = (kp & 1) + 2 * ((kp & 15) >> 3);
                g_We1p[(((c * 64 + ntile) * 2 + ktile) * 32 + ln) * 4 + pos] =
                    __float2half_rn(x);
            } else {
                int e2 = e - 131072;
                int k = e2 >> 10, n2 = e2 & 1023;
                float x = We2[(size_t)k * (2 * IB) + n2];
                int pcol = (n2 < 512) ? (2 * n2) : (2 * (n2 - 512) + 1);
                int c = k >> 5, kp = k & 31;
                int ntile = pcol >> 3, g = pcol & 7;
                int ktile = kp >> 4;
                int ln = g * 4 + ((kp & 7) >> 1);
                int pos = (kp & 1) + 2 * ((kp & 15) >> 3);
                g_We2p[(((c * 128 + ntile) * 2 + ktile) * 32 + ln) * 4 + pos] =
                    __float2half_rn(x);
            }
        }
    }

    qb_s[tid] = g_qW1[b * HID + tid] + b1[tid];
    w2_s[tid] = W2[tid];

    float acc[2][8][4];
    #pragma unroll
    for (int mt = 0; mt < 2; mt++)
        #pragma unroll
        for (int nt = 0; nt < 8; nt++)
            #pragma unroll
            for (int r = 0; r < 4; r++) acc[mt][nt][r] = 0.f;

    PrefA p;
    load_prefA(p, cand, b, k0, 0, tid);
    cp_asyncB(sb, 0, tid);
    CP_COMMIT();
    store_stageA(dsm, p, tid);
    CP_WAIT0();
    __syncthreads();

    #pragma unroll
    for (int c = 0; c < 4; c++) {
        if (c < 3) {
            load_prefA(p, cand, b, k0, c + 1, tid);
            cp_asyncB(sb + ((c + 1) & 1) * STAGE_B, c + 1, tid);
            CP_COMMIT();
        }
        compute_sub(dsm + (c & 1) * STAGE_B, 0, acc, wm, wn, lane);
        if (c < 3) store_stageA(dsm + ((c + 1) & 1) * STAGE_B, p, tid);
        compute_sub(dsm + (c & 1) * STAGE_B, 1, acc, wm, wn, lane);
        CP_WAIT0();
        __syncthreads();
    }

    float rs[2][2] = {{0.f, 0.f}, {0.f, 0.f}};
    #pragma unroll
    for (int mt = 0; mt < 2; mt++)
        #pragma unroll
        for (int nt = 0; nt < 8; nt++)
            #pragma unroll
            for (int ci = 0; ci < 4; ci++) {
                int col = wn * 64 + nt * 8 + (lane & 3) * 2 + (ci & 1);
                float v = acc[mt][nt][ci] + qb_s[col];
                rs[mt][ci >> 1] += fmaxf(v, 0.f) * w2_s[col];
            }
    #pragma unroll
    for (int mt = 0; mt < 2; mt++)
        #pragma unroll
        for (int rh = 0; rh < 2; rh++) {
            float s = rs[mt][rh];
            s += __shfl_xor_sync(0xffffffffu, s, 1);
            s += __shfl_xor_sync(0xffffffffu, s, 2);
            if ((lane & 3) == 0)
                part[wm * 32 + mt * 16 + rh * 8 + (lane >> 2)][wn] = s;
        }
    __syncthreads();
    if (tid < 64) {
        float lg = part[tid][0] + part[tid][1] + part[tid][2] + part[tid][3] + b2[0];
        size_t gi = (size_t)b * KK + k0 + tid;
        g_logits[gi] = lg;
        g_sel[gi] = lg + gum[gi];
    }
}

// ===================== top-k via 4-level radix select =====================
__global__ void __launch_bounds__(1024)
topk_kernel(const float* __restrict__ cand_score, float* __restrict__ out) {
    const int b = blockIdx.x;
    const int tid = threadIdx.x;
    const int base = tid * 8;

    __shared__ uint32_t hist8[8][256];
    __shared__ uint32_t shist[256];
    __shared__ uint32_t s_prefix, s_above;
    __shared__ uint32_t cntG, cntE;
    __shared__ uint32_t gk[64];
    __shared__ int      gi[64];
    __shared__ int      ei[256];

    uint32_t k[8];
    #pragma unroll
    for (int r = 0; r < 8; r++) {
        uint32_t u = __float_as_uint(g_sel[(size_t)b * KK + base + r]);
        k[r] = (u & 0x80000000u) ? ~u : (u | 0x80000000u);
    }
    if (tid == 0) { s_prefix = 0; s_above = 0; cntG = 0; cntE = 0; }

    #pragma unroll
    for (int round = 0; round < 4; round++) {
        const int shift = 24 - round * 8;
        if (round == 0) {
            #pragma unroll
            for (int t = 0; t < 2; t++) hist8[(tid + t * 1024) >> 8][(tid + t * 1024) & 255] = 0;
        } else if (tid < 256) shist[tid] = 0;
        __syncthreads();
        uint32_t pfx = s_prefix;
        if (round == 0) {
            uint32_t* hh = hist8[(tid >> 5) & 7];
            #pragma unroll
            for (int r = 0; r < 8; r++) atomicAdd(&hh[k[r] >> 24], 1u);
        } else {
            const int ps = shift + 8;
            #pragma unroll
            for (int r = 0; r < 8; r++)
                if ((k[r] >> ps) == (pfx >> ps))
                    atomicAdd(&shist[(k[r] >> shift) & 255u], 1u);
        }
        __syncthreads();
        if (round == 0 && tid < 256) {
            uint32_t s = 0;
            #pragma unroll
            for (int g = 0; g < 8; g++) s += hist8[g][tid];
            shist[tid] = s;
        }
        if (round == 0) __syncthreads();
        if (tid < 32) {
            uint32_t loc[8], tot = 0;
            #pragma unroll
            for (int j = 0; j < 8; j++) { loc[j] = shist[tid * 8 + j]; tot += loc[j]; }
            uint32_t suf = tot;
            #pragma unroll
            for (int off = 1; off < 32; off <<= 1) {
                uint32_t v = __shfl_down_sync(0xffffffffu, suf, off);
                if (tid + off < 32) suf += v;
            }
            uint32_t exclHi = suf - tot;
            uint32_t target = 50u - s_above;
            bool has = (exclHi < target) && (exclHi + tot >= target);
            if (has) {
                uint32_t c = exclHi;
                #pragma unroll
                for (int j = 7; j >= 0; j--) {
                    uint32_t nc = c + loc[j];
                    if (nc >= target) {
                        s_prefix = pfx | ((uint32_t)(tid * 8 + j) << shift);
                        s_above += c;
                        break;
                    }
                    c = nc;
                }
            }
        }
        __syncthreads();
    }

    const uint32_t T50 = s_prefix;
    const uint32_t C1 = s_above;
    const int E = 50 - (int)C1;

    #pragma unroll
    for (int r = 0; r < 8; r++) {
        if (k[r] > T50) {
            uint32_t pos = atomicAdd(&cntG, 1u);
            gk[pos] = k[r]; gi[pos] = base + r;
        } else if (k[r] == T50) {
            uint32_t pos = atomicAdd(&cntE, 1u);
            if (pos < 256) ei[pos] = base + r;
        }
    }
    __syncthreads();

    if (tid < (int)C1) {
        uint32_t mk = gk[tid]; int mi = gi[tid];
        int rank = 0;
        for (int j = 0; j < (int)C1; j++)
            if (gk[j] > mk || (gk[j] == mk && gi[j] < mi)) rank++;
        int row = b * SK + rank;
        g_topk[row] = mi;
        out[OFF_SSC + row] = g_logits[(size_t)b * KK + mi];
        out[OFF_SRS + row] = cand_score[(size_t)b * KK + mi];
        out[OFF_SEL + (size_t)row * KK + mi] = 1.0f;
        out[OFF_HARD + (size_t)row * KK + mi] = 1.0f;
    }
    int nE = (int)cntE; if (nE > 256) nE = 256;
    if (tid < nE) {
        int mi = ei[tid];
        int rank = 0;
        for (int j = 0; j < nE; j++) if (ei[j] < mi) rank++;
        if (rank < E) {
            int row = b * SK + (int)C1 + rank;
            g_topk[row] = mi;
            out[OFF_SSC + row] = g_logits[(size_t)b * KK + mi];
            out[OFF_SRS + row] = cand_score[(size_t)b * KK + mi];
            out[OFF_SEL + (size_t)row * KK + mi] = 1.0f;
            out[OFF_HARD + (size_t)row * KK + mi] = 1.0f;
        }
    }
}

// ===================== encoder: fp16 TC, B direct from gmem, sync-free mainloops =====================
#define EST 264            // A1 row stride (halves)
#define HST 520            // HE row stride (halves)
#define O_A1 0
#define O_HE 33792
#define O_QB 100352
#define O_BE2 102400
#define ENC_SMEM 106496

__global__ void __launch_bounds__(256, 1)
encoder_kernel(const float* __restrict__ cand,
               const float* __restrict__ be1,
               const float* __restrict__ be2,
               const float* __restrict__ eps,
               float* __restrict__ out) {
    extern __shared__ char esm[];
    __half* A1  = reinterpret_cast<__half*>(esm + O_A1);
    __half* HE  = reinterpret_cast<__half*>(esm + O_HE);
    float* qb1  = reinterpret_cast<float*>(esm + O_QB);
    float* be2s = reinterpret_cast<float*>(esm + O_BE2);
    __shared__ int idxs[64];
    __shared__ float redp[8];

    const int tid = threadIdx.x;
    const int b = blockIdx.y;
    const int bx = blockIdx.x;              // N-quarter of GEMM2
    const int w = tid >> 5, lane = tid & 31;
    const int wm = w & 1, wn = w >> 1;

    if (tid < 64) idxs[tid] = (tid < 50) ? g_topk[b * SK + tid] : 0;
    qb1[tid]       = g_qWe1[b * EH + tid] + be1[tid];
    qb1[tid + 256] = g_qWe1[b * EH + tid + 256] + be1[tid + 256];
    #pragma unroll
    for (int t = 0; t < 4; t++) be2s[tid + t * 256] = be2[tid + t * 256];
    __syncthreads();

    // gather selected rows -> A1 fp16 (rows 50..63 zero)
    #pragma unroll
    for (int t = 0; t < 16; t++) {
        int idx = tid + t * 256;
        int r = idx >> 6, k4 = idx & 63;
        uint2 u; u.x = 0u; u.y = 0u;
        if (r < 50) {
            float4 v = *reinterpret_cast<const float4*>(
                &cand[((size_t)b * KK + idxs[r]) * DC + k4 * 4]);
            u.x = h2u(__halves2half2(__float2half_rn(v.x), __float2half_rn(v.y)));
            u.y = h2u(__halves2half2(__float2half_rn(v.z), __float2half_rn(v.w)));
        }
        *reinterpret_cast<uint2*>(&A1[r * EST + k4 * 4]) = u;
    }
    __syncthreads();

    float acc[2][8][4];

    // ---- GEMM1: he = relu(A1 @ We1a + qb1); B fragments LDG direct ----
    for (int np = 0; np < 2; np++) {
        #pragma unroll
        for (int mt = 0; mt < 2; mt++)
            #pragma unroll
            for (int nt = 0; nt < 8; nt++)
                #pragma unroll
                for (int r = 0; r < 4; r++) acc[mt][nt][r] = 0.f;

        #pragma unroll 4
        for (int kt = 0; kt < 16; kt++) {
            int c = kt >> 1, ktile = kt & 1;
            uint4 a[2];
            #pragma unroll
            for (int mt = 0; mt < 2; mt++)
                a[mt] = ldsA(A1, EST, wm * 32 + mt * 16, kt * 16, lane);
            #pragma unroll
            for (int nt = 0; nt < 8; nt++) {
                int ntl = np * 32 + wn * 8 + nt;
                uint2 bb = ldgB(g_We1p, (c * 64 + ntl) * 2 + ktile, lane);
                #pragma unroll
                for (int mt = 0; mt < 2; mt++)
                    mma16(acc[mt][nt], a[mt], bb.x, bb.y);
            }
        }
        // epilogue -> HE fp16
        #pragma unroll
        for (int mt = 0; mt < 2; mt++)
            #pragma unroll
            for (int nt = 0; nt < 8; nt++)
                #pragma unroll
                for (int pp = 0; pp < 2; pp++) {
                    int col = np * 256 + wn * 64 + nt * 8 + (lane & 3) * 2;
                    int row = wm * 32 + mt * 16 + (lane >> 2) + 8 * pp;
                    float v0 = fmaxf(acc[mt][nt][2 * pp]     + qb1[col],     0.f);
                    float v1 = fmaxf(acc[mt][nt][2 * pp + 1] + qb1[col + 1], 0.f);
                    *reinterpret_cast<uint32_t*>(&HE[row * HST + col]) =
                        h2u(__halves2half2(__float2half_rn(v0), __float2half_rn(v1)));
                }
    }
    __syncthreads();   // HE exchange across wn

    // ---- GEMM2: N-quarter bx of params = HE @ We2 (col-interleaved) ----
    #pragma unroll
    for (int mt = 0; mt < 2; mt++)
        #pragma unroll
        for (int nt = 0; nt < 8; nt++)
            #pragma unroll
            for (int r = 0; r < 4; r++) acc[mt][nt][r] = 0.f;

    #pragma unroll 4
    for (int kt = 0; kt < 32; kt++) {
        int c = kt >> 1, ktile = kt & 1;
        uint4 a[2];
        #pragma unroll
        for (int mt = 0; mt < 2; mt++)
            a[mt] = ldsA(HE, HST, wm * 32 + mt * 16, kt * 16, lane);
        #pragma unroll
        for (int nt = 0; nt < 8; nt++) {
            int ntl = bx * 32 + wn * 8 + nt;
            uint2 bb = ldgB(g_We2p, (c * 128 + ntl) * 2 + ktile, lane);
            #pragma unroll
            for (int mt = 0; mt < 2; mt++)
                mma16(acc[mt][nt], a[mt], bb.x, bb.y);
        }
    }

    // epilogue: (mu, ls) pairs -> z, kl
    float kl = 0.f;
    #pragma unroll
    for (int mt = 0; mt < 2; mt++)
        #pragma unroll
        for (int nt = 0; nt < 8; nt++)
            #pragma unroll
            for (int pp = 0; pp < 2; pp++) {
                int j = bx * 128 + wn * 32 + nt * 4 + (lane & 3);
                int row = wm * 32 + mt * 16 + (lane >> 2) + 8 * pp;
                if (row < 50) {
                    float mu  = acc[mt][nt][2 * pp]     + be2s[j];
                    float lsr = acc[mt][nt][2 * pp + 1] + be2s[512 + j];
                    float lsc = fminf(fmaxf(lsr, -10.f), 10.f);
                    float sd = expf(lsc);
                    size_t grow = (size_t)b * SK + row;
                    out[OFF_Z + grow * IB + j] = mu + sd * eps[grow * IB + j];
                    kl += mu * mu + sd * sd - 1.0f - 2.0f * lsr;
                }
            }
    #pragma unroll
    for (int off = 16; off; off >>= 1) kl += __shfl_down_sync(0xffffffffu, kl, off);
    if (lane == 0) redp[w] = kl;
    __syncthreads();
    if (tid == 0) {
        float s = 0.f;
        #pragma unroll
        for (int ww = 0; ww < 8; ww++) s += redp[ww];
        atomicAdd(&out[OFF_KL], 0.5f * s * (0.001f / (float)(BB * SK)));
    }
}

// ===================== launch =====================
extern "C" void kernel_launch(void* const* d_in, const int* in_sizes, int n_in,
                              void* d_out, int out_size) {
    const float* query = (const float*)d_in[0];
    const float* cand  = (const float*)d_in[1];
    const float* score = (const float*)d_in[2];
    const float* gum   = (const float*)d_in[3];
    const float* eps   = (const float*)d_in[4];
    const float* W1    = (const float*)d_in[5];
    const float* b1    = (const float*)d_in[6];
    const float* W2    = (const float*)d_in[7];
    const float* b2    = (const float*)d_in[8];
    const float* We1   = (const float*)d_in[9];
    const float* be1   = (const float*)d_in[10];
    const float* We2   = (const float*)d_in[11];
    const float* be2   = (const float*)d_in[12];
    float* out = (float*)d_out;

    static int attr_set = 0;
    if (!attr_set) {
        cudaFuncSetAttribute(logits_mma_kernel,
                             cudaFuncAttributeMaxDynamicSharedMemorySize, SM_DYN);
        cudaFuncSetAttribute(encoder_kernel,
                             cudaFuncAttributeMaxDynamicSharedMemorySize, ENC_SMEM);
        attr_set = 1;
    }

    prep_kernel<<<256 + 96, 256>>>(W1, query, We1);
    logits_mma_kernel<<<dim3(KK / 64, BB), 256, SM_DYN>>>(cand, b1, W2, b2, gum,
                                                          We1, We2, out);
    topk_kernel<<<BB, 1024>>>(score, out);
    encoder_kernel<<<dim3(4, BB), 256, ENC_SMEM>>>(cand, be1, be2, eps, out);
}

// round 11
// speedup vs baseline: 9.0703x; 1.3635x over previous
#include <cuda_runtime.h>
#include <cuda_fp16.h>
#include <math.h>
#include <stdint.h>

#define BB 32
#define KK 8192
#define DC 256
#define DQ 256
#define HID 256
#define SK 50
#define IB 512
#define EH 512

// ---- output layout (f32, tuple concatenated) ----
#define OFF_Z    0ull
#define OFF_SEL  819200ull
#define OFF_KL   13926400ull
#define OFF_HARD 13926401ull
#define OFF_SSC  27033601ull
#define OFF_SRS  27035201ull

// ---- scratch ----
__device__ float g_logits[BB * KK];
__device__ float g_sel[BB * KK];
__device__ float g_qW1[BB * HID];
__device__ float g_qWe1[BB * EH];
__device__ int   g_topk[BB * SK];
// W1^T fp16 fragment-permuted (for logits): 8 chunks(32k) x 1024 uint4
__device__ __align__(16) uint4 g_Bp[8 * 1024];
// We1^T fp16 fragment-permuted: 131072 halves
__device__ __align__(16) __half g_We1p[131072];
// We2^T fp16 fragment-permuted + mu/ls column interleave: 524288 halves
__device__ __align__(16) __half g_We2p[524288];

// ===================== helpers =====================
__device__ __forceinline__ uint32_t h2u(__half2 h) {
    return *reinterpret_cast<uint32_t*>(&h);
}
__device__ __forceinline__ uint32_t smem_u32(const void* p) {
    uint32_t a;
    asm("{ .reg .u64 t; cvta.to.shared.u64 t, %1; cvt.u32.u64 %0, t; }" : "=r"(a) : "l"(p));
    return a;
}
__device__ __forceinline__ void mma16(float* c, const uint4& a, uint32_t b0, uint32_t b1) {
    asm volatile(
        "mma.sync.aligned.m16n8k16.row.col.f32.f16.f16.f32 "
        "{%0,%1,%2,%3},{%4,%5,%6,%7},{%8,%9},{%0,%1,%2,%3};"
        : "+f"(c[0]), "+f"(c[1]), "+f"(c[2]), "+f"(c[3])
        : "r"(a.x), "r"(a.y), "r"(a.z), "r"(a.w), "r"(b0), "r"(b1));
}
__device__ __forceinline__ void cp16(uint32_t dst, const void* src) {
    asm volatile("cp.async.cg.shared.global [%0], [%1], 16;" :: "r"(dst), "l"(src));
}
#define CP_COMMIT() asm volatile("cp.async.commit_group;" ::: "memory")
#define CP_WAIT0()  asm volatile("cp.async.wait_group 0;" ::: "memory")

// A-fragment load from row-major fp16 smem (stride in halves)
__device__ __forceinline__ uint4 ldsA(const __half* A, int stride, int rb, int kb, int lane) {
    const __half* p0 = A + (rb + (lane >> 2)) * stride + kb + (lane & 3) * 2;
    uint4 a;
    a.x = *reinterpret_cast<const uint32_t*>(p0);
    a.y = *reinterpret_cast<const uint32_t*>(p0 + 8 * stride);
    a.z = *reinterpret_cast<const uint32_t*>(p0 + 8);
    a.w = *reinterpret_cast<const uint32_t*>(p0 + 8 * stride + 8);
    return a;
}
// B-fragment direct from permuted gmem: frag = 128 halves, lane owns 4
__device__ __forceinline__ uint2 ldgB(const __half* __restrict__ base,
                                      int fragIdx, int lane) {
    return *reinterpret_cast<const uint2*>(base + (size_t)fragIdx * 128 + lane * 4);
}

// ===================== prep: W1 permute + qproj only =====================
__global__ void __launch_bounds__(256)
prep_kernel(const float* __restrict__ W1,
            const float* __restrict__ q,
            const float* __restrict__ We1) {
    int blk = blockIdx.x, tid = threadIdx.x;
    if (blk < 256) {   // W1 -> permuted fp16 fragments for logits
        int idx = blk * 256 + tid;
        int k = idx >> 8, n2 = idx & 255;
        float x = W1[(size_t)k * HID + n2];
        int c = k >> 5, kp = k & 31;
        int ntile = n2 >> 3, g = n2 & 7;
        int ktile = kp >> 4;
        int lane = g * 4 + ((kp & 7) >> 1);
        int pos = (kp & 1) + 2 * ((kp & 15) >> 3);
        size_t off = (size_t)c * 8192 +
                     (size_t)(((ntile * 2 + ktile) * 32 + lane) * 4 + pos);
        reinterpret_cast<__half*>(g_Bp)[off] = __float2half_rn(x);
        return;
    }
    blk -= 256;        // qproj: 3 per batch (96 blocks)
    int sub = blk % 3, b = blk / 3;
    __shared__ float qs[DQ];
    qs[tid] = q[b * DQ + tid];
    __syncthreads();
    float s = 0.f;
    if (sub == 0) {
        #pragma unroll 8
        for (int d = 0; d < DQ; d++) s += qs[d] * W1[(size_t)(DC + d) * HID + tid];
        g_qW1[b * HID + tid] = s;
    } else {
        int c0 = (sub - 1) * 256 + tid;
        #pragma unroll 8
        for (int d = 0; d < DQ; d++) s += qs[d] * We1[(size_t)(DC + d) * EH + c0];
        g_qWe1[b * EH + c0] = s;
    }
}

// ===================== scorer logits: fp16 1-pass + fused zero + We permutes =====================
#define SAH 0
#define SB  8192
#define STAGE_B 40960
#define SM_DYN (2 * STAGE_B)

struct PrefA { float4 a[4]; };

__device__ __forceinline__ void load_prefA(PrefA& p, const float* __restrict__ cand,
                                           int b, int k0, int c, int tid) {
    #pragma unroll
    for (int t = 0; t < 4; t++) {
        int idx = tid + t * 256;
        int m = idx >> 4, k4 = idx & 15;
        p.a[t] = *reinterpret_cast<const float4*>(
            &cand[((size_t)b * KK + k0 + m) * DC + c * 64 + k4 * 4]);
    }
}

__device__ __forceinline__ void cp_asyncB(uint32_t stb, int c, int tid) {
    #pragma unroll
    for (int t = 0; t < 8; t++) {
        int idx = tid + t * 256;
        int sub = idx >> 10, j = idx & 1023;
        cp16(stb + SB + sub * 16384 + j * 16, &g_Bp[(c * 2 + sub) * 1024 + j]);
    }
}

__device__ __forceinline__ void store_stageA(char* __restrict__ st, const PrefA& p, int tid) {
    #pragma unroll
    for (int t = 0; t < 4; t++) {
        int idx = tid + t * 256;
        int m = idx >> 4, k4 = idx & 15;
        int sub = k4 >> 3, k4in = k4 & 7;
        float4 v = p.a[t];
        uint32_t h01 = h2u(__floats2half2_rn(v.x, v.y));
        uint32_t h23 = h2u(__floats2half2_rn(v.z, v.w));
        int mtile = m >> 4, r = m & 15;
        int ktile = k4in >> 2;
        int lane0 = (r & 7) * 4 + (k4in & 1) * 2;
        int boff = 2 * ((r >> 3) & 1) + 4 * ((k4in >> 1) & 1);
        int base = sub * 4096 + ((mtile * 2 + ktile) * 32) * 16 + boff * 2;
        *reinterpret_cast<uint32_t*>(st + SAH + base + lane0 * 16)       = h01;
        *reinterpret_cast<uint32_t*>(st + SAH + base + (lane0 + 1) * 16) = h23;
    }
}

__device__ __forceinline__ void compute_sub(const char* __restrict__ st, int sub,
                                            float acc[2][8][4],
                                            int wm, int wn, int lane) {
    #pragma unroll
    for (int kt = 0; kt < 2; kt++) {
        uint4 ah[2];
        #pragma unroll
        for (int mt = 0; mt < 2; mt++) {
            int off = sub * 4096 + (((wm * 2 + mt) * 2 + kt) * 32 + lane) * 16;
            ah[mt] = *reinterpret_cast<const uint4*>(st + SAH + off);
        }
        #pragma unroll
        for (int nt = 0; nt < 8; nt++) {
            int ntile = wn * 8 + nt;
            int boff = sub * 16384 + ((ntile * 2 + kt) * 32 + lane) * 8;
            uint2 bb = *reinterpret_cast<const uint2*>(st + SB + boff);
            #pragma unroll
            for (int mt = 0; mt < 2; mt++)
                mma16(acc[mt][nt], ah[mt], bb.x, bb.y);
        }
    }
}

__global__ void __launch_bounds__(256, 2)
logits_mma_kernel(const float* __restrict__ cand,
                  const float* __restrict__ b1,
                  const float* __restrict__ W2,
                  const float* __restrict__ b2,
                  const float* __restrict__ gum,
                  const float* __restrict__ We1,
                  const float* __restrict__ We2,
                  float* __restrict__ out) {
    extern __shared__ char dsm[];
    __shared__ float qb_s[HID];
    __shared__ float w2_s[HID];
    __shared__ float part[64][4];

    const int tid = threadIdx.x;
    const int b = blockIdx.y;
    const int k0 = blockIdx.x * 64;
    const int w = tid >> 5, lane = tid & 31;
    const int wm = w & 1, wn = w >> 1;
    const uint32_t sb = smem_u32(dsm);
    const int bid = blockIdx.y * gridDim.x + blockIdx.x;    // 0..4095

    // ---- fused: zero SEL+KL+HARD, permute We1/We2 slices (160 elems/block) ----
    {
        float4* oz = reinterpret_cast<float4*>(out) + 204800 + (size_t)bid * 1600;
        float4 z4 = make_float4(0.f, 0.f, 0.f, 0.f);
        #pragma unroll
        for (int t = tid; t < 1600; t += 256) oz[t] = z4;
        if (bid == 0 && tid == 0) out[27033600] = 0.f;
        if (tid < 160) {
            int e = bid * 160 + tid;                        // 0..655359
            if (e < 131072) {
                int k = e >> 9, n2 = e & 511;
                float x = We1[(size_t)k * EH + n2];
                int c = k >> 5, kp = k & 31;
                int ntile = n2 >> 3, g = n2 & 7;
                int ktile = kp >> 4;
                int ln = g * 4 + ((kp & 7) >> 1);
                int pos = (kp & 1) + 2 * ((kp & 15) >> 3);
                g_We1p[(((c * 64 + ntile) * 2 + ktile) * 32 + ln) * 4 + pos] =
                    __float2half_rn(x);
            } else {
                int e2 = e - 131072;
                int k = e2 >> 10, n2 = e2 & 1023;
                float x = We2[(size_t)k * (2 * IB) + n2];
                int pcol = (n2 < 512) ? (2 * n2) : (2 * (n2 - 512) + 1);
                int c = k >> 5, kp = k & 31;
                int ntile = pcol >> 3, g = pcol & 7;
                int ktile = kp >> 4;
                int ln = g * 4 + ((kp & 7) >> 1);
                int pos = (kp & 1) + 2 * ((kp & 15) >> 3);
                g_We2p[(((c * 128 + ntile) * 2 + ktile) * 32 + ln) * 4 + pos] =
                    __float2half_rn(x);
            }
        }
    }

    qb_s[tid] = g_qW1[b * HID + tid] + b1[tid];
    w2_s[tid] = W2[tid];

    float acc[2][8][4];
    #pragma unroll
    for (int mt = 0; mt < 2; mt++)
        #pragma unroll
        for (int nt = 0; nt < 8; nt++)
            #pragma unroll
            for (int r = 0; r < 4; r++) acc[mt][nt][r] = 0.f;

    PrefA p;
    load_prefA(p, cand, b, k0, 0, tid);
    cp_asyncB(sb, 0, tid);
    CP_COMMIT();
    store_stageA(dsm, p, tid);
    CP_WAIT0();
    __syncthreads();

    #pragma unroll
    for (int c = 0; c < 4; c++) {
        if (c < 3) {
            load_prefA(p, cand, b, k0, c + 1, tid);
            cp_asyncB(sb + ((c + 1) & 1) * STAGE_B, c + 1, tid);
            CP_COMMIT();
        }
        compute_sub(dsm + (c & 1) * STAGE_B, 0, acc, wm, wn, lane);
        if (c < 3) store_stageA(dsm + ((c + 1) & 1) * STAGE_B, p, tid);
        compute_sub(dsm + (c & 1) * STAGE_B, 1, acc, wm, wn, lane);
        CP_WAIT0();
        __syncthreads();
    }

    float rs[2][2] = {{0.f, 0.f}, {0.f, 0.f}};
    #pragma unroll
    for (int mt = 0; mt < 2; mt++)
        #pragma unroll
        for (int nt = 0; nt < 8; nt++)
            #pragma unroll
            for (int ci = 0; ci < 4; ci++) {
                int col = wn * 64 + nt * 8 + (lane & 3) * 2 + (ci & 1);
                float v = acc[mt][nt][ci] + qb_s[col];
                rs[mt][ci >> 1] += fmaxf(v, 0.f) * w2_s[col];
            }
    #pragma unroll
    for (int mt = 0; mt < 2; mt++)
        #pragma unroll
        for (int rh = 0; rh < 2; rh++) {
            float s = rs[mt][rh];
            s += __shfl_xor_sync(0xffffffffu, s, 1);
            s += __shfl_xor_sync(0xffffffffu, s, 2);
            if ((lane & 3) == 0)
                part[wm * 32 + mt * 16 + rh * 8 + (lane >> 2)][wn] = s;
        }
    __syncthreads();
    if (tid < 64) {
        float lg = part[tid][0] + part[tid][1] + part[tid][2] + part[tid][3] + b2[0];
        size_t gi = (size_t)b * KK + k0 + tid;
        g_logits[gi] = lg;
        g_sel[gi] = lg + gum[gi];
    }
}

// ===================== top-k via 4-level radix select =====================
__global__ void __launch_bounds__(1024)
topk_kernel(const float* __restrict__ cand_score, float* __restrict__ out) {
    const int b = blockIdx.x;
    const int tid = threadIdx.x;
    const int base = tid * 8;

    __shared__ uint32_t hist8[8][256];
    __shared__ uint32_t shist[256];
    __shared__ uint32_t s_prefix, s_above;
    __shared__ uint32_t cntG, cntE;
    __shared__ uint32_t gk[64];
    __shared__ int      gi[64];
    __shared__ int      ei[256];

    uint32_t k[8];
    #pragma unroll
    for (int r = 0; r < 8; r++) {
        uint32_t u = __float_as_uint(g_sel[(size_t)b * KK + base + r]);
        k[r] = (u & 0x80000000u) ? ~u : (u | 0x80000000u);
    }
    if (tid == 0) { s_prefix = 0; s_above = 0; cntG = 0; cntE = 0; }

    #pragma unroll
    for (int round = 0; round < 4; round++) {
        const int shift = 24 - round * 8;
        if (round == 0) {
            #pragma unroll
            for (int t = 0; t < 2; t++) hist8[(tid + t * 1024) >> 8][(tid + t * 1024) & 255] = 0;
        } else if (tid < 256) shist[tid] = 0;
        __syncthreads();
        uint32_t pfx = s_prefix;
        if (round == 0) {
            uint32_t* hh = hist8[(tid >> 5) & 7];
            #pragma unroll
            for (int r = 0; r < 8; r++) atomicAdd(&hh[k[r] >> 24], 1u);
        } else {
            const int ps = shift + 8;
            #pragma unroll
            for (int r = 0; r < 8; r++)
                if ((k[r] >> ps) == (pfx >> ps))
                    atomicAdd(&shist[(k[r] >> shift) & 255u], 1u);
        }
        __syncthreads();
        if (round == 0 && tid < 256) {
            uint32_t s = 0;
            #pragma unroll
            for (int g = 0; g < 8; g++) s += hist8[g][tid];
            shist[tid] = s;
        }
        if (round == 0) __syncthreads();
        if (tid < 32) {
            uint32_t loc[8], tot = 0;
            #pragma unroll
            for (int j = 0; j < 8; j++) { loc[j] = shist[tid * 8 + j]; tot += loc[j]; }
            uint32_t suf = tot;
            #pragma unroll
            for (int off = 1; off < 32; off <<= 1) {
                uint32_t v = __shfl_down_sync(0xffffffffu, suf, off);
                if (tid + off < 32) suf += v;
            }
            uint32_t exclHi = suf - tot;
            uint32_t target = 50u - s_above;
            bool has = (exclHi < target) && (exclHi + tot >= target);
            if (has) {
                uint32_t c = exclHi;
                #pragma unroll
                for (int j = 7; j >= 0; j--) {
                    uint32_t nc = c + loc[j];
                    if (nc >= target) {
                        s_prefix = pfx | ((uint32_t)(tid * 8 + j) << shift);
                        s_above += c;
                        break;
                    }
                    c = nc;
                }
            }
        }
        __syncthreads();
    }

    const uint32_t T50 = s_prefix;
    const uint32_t C1 = s_above;
    const int E = 50 - (int)C1;

    #pragma unroll
    for (int r = 0; r < 8; r++) {
        if (k[r] > T50) {
            uint32_t pos = atomicAdd(&cntG, 1u);
            gk[pos] = k[r]; gi[pos] = base + r;
        } else if (k[r] == T50) {
            uint32_t pos = atomicAdd(&cntE, 1u);
            if (pos < 256) ei[pos] = base + r;
        }
    }
    __syncthreads();

    if (tid < (int)C1) {
        uint32_t mk = gk[tid]; int mi = gi[tid];
        int rank = 0;
        for (int j = 0; j < (int)C1; j++)
            if (gk[j] > mk || (gk[j] == mk && gi[j] < mi)) rank++;
        int row = b * SK + rank;
        g_topk[row] = mi;
        out[OFF_SSC + row] = g_logits[(size_t)b * KK + mi];
        out[OFF_SRS + row] = cand_score[(size_t)b * KK + mi];
        out[OFF_SEL + (size_t)row * KK + mi] = 1.0f;
        out[OFF_HARD + (size_t)row * KK + mi] = 1.0f;
    }
    int nE = (int)cntE; if (nE > 256) nE = 256;
    if (tid < nE) {
        int mi = ei[tid];
        int rank = 0;
        for (int j = 0; j < nE; j++) if (ei[j] < mi) rank++;
        if (rank < E) {
            int row = b * SK + (int)C1 + rank;
            g_topk[row] = mi;
            out[OFF_SSC + row] = g_logits[(size_t)b * KK + mi];
            out[OFF_SRS + row] = cand_score[(size_t)b * KK + mi];
            out[OFF_SEL + (size_t)row * KK + mi] = 1.0f;
            out[OFF_HARD + (size_t)row * KK + mi] = 1.0f;
        }
    }
}

// ===================== encoder: fp16 TC, 512 threads, B direct from gmem =====================
#define EST 264            // A1 row stride (halves)
#define HST 520            // HE row stride (halves)
#define O_A1 0
#define O_HE 33792
#define O_QB 100352
#define O_BE2 102400
#define ENC_SMEM 106496

__global__ void __launch_bounds__(512, 1)
encoder_kernel(const float* __restrict__ cand,
               const float* __restrict__ be1,
               const float* __restrict__ be2,
               const float* __restrict__ eps,
               float* __restrict__ out) {
    extern __shared__ char esm[];
    __half* A1  = reinterpret_cast<__half*>(esm + O_A1);
    __half* HE  = reinterpret_cast<__half*>(esm + O_HE);
    float* qb1  = reinterpret_cast<float*>(esm + O_QB);
    float* be2s = reinterpret_cast<float*>(esm + O_BE2);
    __shared__ int idxs[64];
    __shared__ float redp[16];

    const int tid = threadIdx.x;
    const int b = blockIdx.y;
    const int bx = blockIdx.x;              // N-quarter of GEMM2
    const int w = tid >> 5, lane = tid & 31;
    const int wm = w & 1, wn = w >> 1;      // wn 0..7

    if (tid < 64) idxs[tid] = (tid < 50) ? g_topk[b * SK + tid] : 0;
    qb1[tid]  = g_qWe1[b * EH + tid] + be1[tid];
    be2s[tid]       = be2[tid];
    be2s[tid + 512] = be2[tid + 512];
    __syncthreads();

    // gather selected rows -> A1 fp16 (rows 50..63 zero)
    #pragma unroll
    for (int t = 0; t < 8; t++) {
        int idx = tid + t * 512;
        int r = idx >> 6, k4 = idx & 63;
        uint2 u; u.x = 0u; u.y = 0u;
        if (r < 50) {
            float4 v = *reinterpret_cast<const float4*>(
                &cand[((size_t)b * KK + idxs[r]) * DC + k4 * 4]);
            u.x = h2u(__floats2half2_rn(v.x, v.y));
            u.y = h2u(__floats2half2_rn(v.z, v.w));
        }
        *reinterpret_cast<uint2*>(&A1[r * EST + k4 * 4]) = u;
    }
    __syncthreads();

    // ---- GEMM1: full 512 cols in one pass across 8 wn ----
    {
        float acc[2][8][4];
        #pragma unroll
        for (int mt = 0; mt < 2; mt++)
            #pragma unroll
            for (int nt = 0; nt < 8; nt++)
                #pragma unroll
                for (int r = 0; r < 4; r++) acc[mt][nt][r] = 0.f;

        #pragma unroll 4
        for (int kt = 0; kt < 16; kt++) {
            int c = kt >> 1, ktile = kt & 1;
            uint4 a[2];
            #pragma unroll
            for (int mt = 0; mt < 2; mt++)
                a[mt] = ldsA(A1, EST, wm * 32 + mt * 16, kt * 16, lane);
            #pragma unroll
            for (int nt = 0; nt < 8; nt++) {
                int ntl = wn * 8 + nt;
                uint2 bb = ldgB(g_We1p, (c * 64 + ntl) * 2 + ktile, lane);
                #pragma unroll
                for (int mt = 0; mt < 2; mt++)
                    mma16(acc[mt][nt], a[mt], bb.x, bb.y);
            }
        }
        // epilogue -> HE fp16
        #pragma unroll
        for (int mt = 0; mt < 2; mt++)
            #pragma unroll
            for (int nt = 0; nt < 8; nt++)
                #pragma unroll
                for (int pp = 0; pp < 2; pp++) {
                    int col = wn * 64 + nt * 8 + (lane & 3) * 2;
                    int row = wm * 32 + mt * 16 + (lane >> 2) + 8 * pp;
                    float v0 = fmaxf(acc[mt][nt][2 * pp]     + qb1[col],     0.f);
                    float v1 = fmaxf(acc[mt][nt][2 * pp + 1] + qb1[col + 1], 0.f);
                    *reinterpret_cast<uint32_t*>(&HE[row * HST + col]) =
                        h2u(__floats2half2_rn(v0, v1));
                }
    }
    __syncthreads();   // HE exchange

    // ---- GEMM2: N-quarter bx, 32 ntiles over 8 wn (4 each) ----
    float acc2[2][4][4];
    #pragma unroll
    for (int mt = 0; mt < 2; mt++)
        #pragma unroll
        for (int nt = 0; nt < 4; nt++)
            #pragma unroll
            for (int r = 0; r < 4; r++) acc2[mt][nt][r] = 0.f;

    #pragma unroll 4
    for (int kt = 0; kt < 32; kt++) {
        int c = kt >> 1, ktile = kt & 1;
        uint4 a[2];
        #pragma unroll
        for (int mt = 0; mt < 2; mt++)
            a[mt] = ldsA(HE, HST, wm * 32 + mt * 16, kt * 16, lane);
        #pragma unroll
        for (int nt = 0; nt < 4; nt++) {
            int ntl = bx * 32 + wn * 4 + nt;
            uint2 bb = ldgB(g_We2p, (c * 128 + ntl) * 2 + ktile, lane);
            #pragma unroll
            for (int mt = 0; mt < 2; mt++)
                mma16(acc2[mt][nt], a[mt], bb.x, bb.y);
        }
    }

    // epilogue: (mu, ls) pairs -> z, kl
    float kl = 0.f;
    #pragma unroll
    for (int mt = 0; mt < 2; mt++)
        #pragma unroll
        for (int nt = 0; nt < 4; nt++)
            #pragma unroll
            for (int pp = 0; pp < 2; pp++) {
                int j = bx * 128 + wn * 16 + nt * 4 + (lane & 3);
                int row = wm * 32 + mt * 16 + (lane >> 2) + 8 * pp;
                if (row < 50) {
                    float mu  = acc2[mt][nt][2 * pp]     + be2s[j];
                    float lsr = acc2[mt][nt][2 * pp + 1] + be2s[512 + j];
                    float lsc = fminf(fmaxf(lsr, -10.f), 10.f);
                    float sd = expf(lsc);
                    size_t grow = (size_t)b * SK + row;
                    out[OFF_Z + grow * IB + j] = mu + sd * eps[grow * IB + j];
                    kl += mu * mu + sd * sd - 1.0f - 2.0f * lsr;
                }
            }
    #pragma unroll
    for (int off = 16; off; off >>= 1) kl += __shfl_down_sync(0xffffffffu, kl, off);
    if (lane == 0) redp[w] = kl;
    __syncthreads();
    if (tid == 0) {
        float s = 0.f;
        #pragma unroll
        for (int ww = 0; ww < 16; ww++) s += redp[ww];
        atomicAdd(&out[OFF_KL], 0.5f * s * (0.001f / (float)(BB * SK)));
    }
}

// ===================== launch =====================
extern "C" void kernel_launch(void* const* d_in, const int* in_sizes, int n_in,
                              void* d_out, int out_size) {
    const float* query = (const float*)d_in[0];
    const float* cand  = (const float*)d_in[1];
    const float* score = (const float*)d_in[2];
    const float* gum   = (const float*)d_in[3];
    const float* eps   = (const float*)d_in[4];
    const float* W1    = (const float*)d_in[5];
    const float* b1    = (const float*)d_in[6];
    const float* W2    = (const float*)d_in[7];
    const float* b2    = (const float*)d_in[8];
    const float* We1   = (const float*)d_in[9];
    const float* be1   = (const float*)d_in[10];
    const float* We2   = (const float*)d_in[11];
    const float* be2   = (const float*)d_in[12];
    float* out = (float*)d_out;

    static int attr_set = 0;
    if (!attr_set) {
        cudaFuncSetAttribute(logits_mma_kernel,
                             cudaFuncAttributeMaxDynamicSharedMemorySize, SM_DYN);
        cudaFuncSetAttribute(encoder_kernel,
                             cudaFuncAttributeMaxDynamicSharedMemorySize, ENC_SMEM);
        attr_set = 1;
    }

    prep_kernel<<<256 + 96, 256>>>(W1, query, We1);
    logits_mma_kernel<<<dim3(KK / 64, BB), 256, SM_DYN>>>(cand, b1, W2, b2, gum,
                                                          We1, We2, out);
    topk_kernel<<<BB, 1024>>>(score, out);
    encoder_kernel<<<dim3(4, BB), 512, ENC_SMEM>>>(cand, be1, be2, eps, out);
}